// round 2
// baseline (speedup 1.0000x reference)
#include <cuda_runtime.h>
#include <math.h>

// ---------------- problem constants ----------------
#define Bn    32
#define DIMc  384
#define Rr    28
#define Nn    784          // R*R
#define Hh    8
#define KDd   32
#define Dd    128
#define NHKD  256          // H*KD
#define DHd   1024         // H*D
#define TQ    7            // queries per attention block (112 tiles of 7 = 784)

__device__ __constant__ float kSCALE = 0.17677669529663687f; // 1/sqrt(32)

// ---------------- scratch (static device arrays; no allocation) ----------------
__device__ float g_q   [(size_t)Bn * NHKD * Nn];       //  25.7 MB   [B,256,N]
__device__ float g_k   [(size_t)Bn * NHKD * Nn];       //  25.7 MB   [B,256,N]
__device__ float g_vmap[(size_t)Bn * DHd  * Nn];       // 102.8 MB   [B,1024,N]
__device__ float g_vl  [(size_t)Bn * DHd  * Nn];       // 102.8 MB   [B,1024,N]
__device__ float g_attn[(size_t)Bn * Hh * Nn * Nn];    // 629.4 MB   [B,H,N,N] (post mix2)
__device__ float g_o   [(size_t)Bn * DHd  * Nn];       // 102.8 MB   relu(o+vl)

// ==========================================================================
// Generic pointwise-conv GEMM:  Y[b,o,n] = ((sum_k W[o,k]*X[b,k,n]) + bias[o])*s[o] + t[o]
// grid: (ceil(784/64)=13, O/64, B)   block: 256 threads, each 4x4 outputs
// ==========================================================================
__global__ __launch_bounds__(256)
void proj_kernel(const float* __restrict__ X, const float* __restrict__ W,
                 const float* __restrict__ bias, const float* __restrict__ s,
                 const float* __restrict__ t, float* __restrict__ Y,
                 int O, int K)
{
    __shared__ float Ws[16][64];   // [k][o]
    __shared__ float Xs[16][64];   // [k][n]

    const int b  = blockIdx.z;
    const int o0 = blockIdx.y * 64;
    const int n0 = blockIdx.x * 64;
    const int tid = threadIdx.x;

    const float* Xb = X + (size_t)b * K * Nn;

    const int lo = tid >> 2;            // 0..63  (o row for W load)
    const int lk = (tid & 3) * 4;       // 0,4,8,12
    const int xk = tid >> 4;            // 0..15  (k row for X load)
    const int xn = (tid & 15) * 4;      // 0..60

    const int to = tid >> 4;            // 0..15  (compute o group)
    const int tn = tid & 15;            // 0..15  (compute n group)

    float acc[4][4];
#pragma unroll
    for (int i = 0; i < 4; ++i)
#pragma unroll
        for (int j = 0; j < 4; ++j) acc[i][j] = 0.f;

    for (int kk = 0; kk < K; kk += 16) {
        // W tile
        float4 w4 = *(const float4*)&W[(size_t)(o0 + lo) * K + kk + lk];
        Ws[lk + 0][lo] = w4.x; Ws[lk + 1][lo] = w4.y;
        Ws[lk + 2][lo] = w4.z; Ws[lk + 3][lo] = w4.w;
        // X tile (bounds on n; 784 % 4 == 0 so float4 is safe when in range)
        float4 x4 = make_float4(0.f, 0.f, 0.f, 0.f);
        if (n0 + xn < Nn)
            x4 = *(const float4*)&Xb[(size_t)(kk + xk) * Nn + n0 + xn];
        Xs[xk][xn + 0] = x4.x; Xs[xk][xn + 1] = x4.y;
        Xs[xk][xn + 2] = x4.z; Xs[xk][xn + 3] = x4.w;
        __syncthreads();

#pragma unroll
        for (int k = 0; k < 16; ++k) {
            float4 wv = *(const float4*)&Ws[k][to * 4];
            float4 xv = *(const float4*)&Xs[k][tn * 4];
            float wr[4] = {wv.x, wv.y, wv.z, wv.w};
            float xr[4] = {xv.x, xv.y, xv.z, xv.w};
#pragma unroll
            for (int i = 0; i < 4; ++i)
#pragma unroll
                for (int j = 0; j < 4; ++j) acc[i][j] = fmaf(wr[i], xr[j], acc[i][j]);
        }
        __syncthreads();
    }

#pragma unroll
    for (int i = 0; i < 4; ++i) {
        const int o = o0 + to * 4 + i;
        const float bi = bias[o], si = s[o], ti = t[o];
#pragma unroll
        for (int j = 0; j < 4; ++j) {
            const int n = n0 + tn * 4 + j;
            if (n < Nn)
                Y[((size_t)b * O + o) * Nn + n] = (acc[i][j] + bi) * si + ti;
        }
    }
}

// ==========================================================================
// Depthwise 3x3 conv (SAME, zero pad) + bias + affine:  g_vl from g_vmap
// ==========================================================================
__global__ __launch_bounds__(256)
void dwconv_kernel(const float* __restrict__ V, const float* __restrict__ Wc,
                   const float* __restrict__ bias, const float* __restrict__ s,
                   const float* __restrict__ t, float* __restrict__ Out)
{
    const int idx = blockIdx.x * 256 + threadIdx.x;
    if (idx >= Bn * DHd * Nn) return;
    const int pos = idx % Nn;
    const int ch  = (idx / Nn) % DHd;
    const int b   = idx / (Nn * DHd);
    const int y = pos / Rr, x = pos % Rr;

    const float* vb = V + ((size_t)b * DHd + ch) * Nn;
    const float* wc = Wc + ch * 9;
    float acc = 0.f;
#pragma unroll
    for (int dy = 0; dy < 3; ++dy) {
        const int yy = y + dy - 1;
        if (yy < 0 || yy >= Rr) continue;
#pragma unroll
        for (int dx = 0; dx < 3; ++dx) {
            const int xx = x + dx - 1;
            if (xx < 0 || xx >= Rr) continue;
            acc = fmaf(vb[yy * Rr + xx], wc[dy * 3 + dx], acc);
        }
    }
    Out[idx] = (acc + bias[ch]) * s[ch] + t[ch];
}

// ==========================================================================
// Fused attention core: QK^T*scale + rel-bias -> th1 mix -> softmax -> th2 mix
// writes post-mix2 attention to g_attn [B,H,N,N].
// grid: (112, B)   block: 256 (8 warps; warp g owns output head g)
// dyn smem: S[TQ][8][784] + A[8][784] + qs[TQ][256]  = 207,872 B
// ==========================================================================
__global__ __launch_bounds__(256)
void attn_kernel(const float* __restrict__ Q, const float* __restrict__ K,
                 const int*   __restrict__ idxs, const float* __restrict__ ab,
                 const float* __restrict__ th1w, const float* __restrict__ th1b,
                 const float* __restrict__ th2w, const float* __restrict__ th2b,
                 float* __restrict__ Attn)
{
    extern __shared__ float sm[];
    float* S  = sm;                       // TQ*8*784
    float* A  = S + TQ * Hh * Nn;         // 8*784
    float* qs = A + Hh * Nn;              // TQ*256

    const int b   = blockIdx.y;
    const int n0  = blockIdx.x * TQ;
    const int tid = threadIdx.x;
    const int g    = tid >> 5;
    const int lane = tid & 31;

    // load Q rows for the tile: qs[nq][c] = Q[b, c, n0+nq]
    for (int e = tid; e < TQ * NHKD; e += 256) {
        const int nq = e / NHKD, c = e % NHKD;
        qs[nq * NHKD + c] = Q[((size_t)b * NHKD + c) * Nn + (n0 + nq)];
    }
    __syncthreads();

    // Phase 1: scores  S[nq][h][m] = <q,k>*scale + ab[h, idxs[n,m]]
    for (int h = 0; h < Hh; ++h) {
        const float* Kb = K + ((size_t)b * NHKD + h * KDd) * Nn;
        for (int m = tid; m < Nn; m += 256) {
            float kk[KDd];
#pragma unroll
            for (int j = 0; j < KDd; ++j) kk[j] = Kb[j * Nn + m];
#pragma unroll
            for (int nq = 0; nq < TQ; ++nq) {
                const float* qv = &qs[nq * NHKD + h * KDd];
                float acc = 0.f;
#pragma unroll
                for (int j = 0; j < KDd; ++j) acc = fmaf(qv[j], kk[j], acc);
                const int n   = n0 + nq;
                const int idx = idxs[n * Nn + m];
                S[(nq * Hh + h) * Nn + m] = acc * kSCALE + ab[h * Nn + idx];
            }
        }
    }
    __syncthreads();

    // Phase 2: per-query mix1 -> softmax -> mix2 -> global write
    float w1[Hh], w2[Hh];
#pragma unroll
    for (int h = 0; h < Hh; ++h) { w1[h] = th1w[g * Hh + h]; w2[h] = th2w[g * Hh + h]; }
    const float b1 = th1b[g], b2 = th2b[g];

    for (int nq = 0; nq < TQ; ++nq) {
        const float* Sq = S + nq * Hh * Nn;
        float maxv = -1e30f;
        for (int m = lane; m < Nn; m += 32) {
            float a = b1;
#pragma unroll
            for (int h = 0; h < Hh; ++h) a = fmaf(w1[h], Sq[h * Nn + m], a);
            A[g * Nn + m] = a;
            maxv = fmaxf(maxv, a);
        }
#pragma unroll
        for (int off = 16; off; off >>= 1)
            maxv = fmaxf(maxv, __shfl_xor_sync(0xffffffffu, maxv, off));
        float sum = 0.f;
        for (int m = lane; m < Nn; m += 32) {
            const float e = __expf(A[g * Nn + m] - maxv);
            A[g * Nn + m] = e;
            sum += e;
        }
#pragma unroll
        for (int off = 16; off; off >>= 1)
            sum += __shfl_xor_sync(0xffffffffu, sum, off);
        const float inv = 1.f / sum;
        for (int m = lane; m < Nn; m += 32) A[g * Nn + m] *= inv;
        __syncthreads();

        const size_t obase = (((size_t)(b * Hh + g)) * Nn + (n0 + nq)) * Nn;
        for (int m = lane; m < Nn; m += 32) {
            float a = b2;
#pragma unroll
            for (int h = 0; h < Hh; ++h) a = fmaf(w2[h], A[h * Nn + m], a);
            Attn[obase + m] = a;
        }
        __syncthreads();
    }
}

// ==========================================================================
// AV:  o[b,g,n,d] = sum_m attn[b,g,n,m] * vmap[b, g*128+d, m]; then +vl, relu
// grid: (13 n-tiles, 2 d-tiles, B*H)   block 256, 4x4 per thread
// ==========================================================================
__global__ __launch_bounds__(256)
void av_kernel(const float* __restrict__ Attn, const float* __restrict__ V,
               const float* __restrict__ Vl, float* __restrict__ Out)
{
    __shared__ float As[16][64];   // [m][n]
    __shared__ float Vs[16][64];   // [m][d]

    const int bg = blockIdx.z;
    const int b  = bg >> 3;
    const int g  = bg & 7;
    const int n0 = blockIdx.x * 64;
    const int d0 = blockIdx.y * 64;
    const int tid = threadIdx.x;

    const float* Ab = Attn + (size_t)bg * Nn * Nn;               // [n][m]
    const float* Vb = V + ((size_t)b * DHd + g * Dd) * Nn;       // [d][m]

    const int lr = tid >> 2;            // 0..63 row (n or d)
    const int lm = (tid & 3) * 4;       // 0,4,8,12
    const int ti = tid >> 4;            // n group
    const int tj = tid & 15;            // d group

    float acc[4][4];
#pragma unroll
    for (int i = 0; i < 4; ++i)
#pragma unroll
        for (int j = 0; j < 4; ++j) acc[i][j] = 0.f;

    for (int m0 = 0; m0 < Nn; m0 += 16) {
        float4 a4 = make_float4(0.f, 0.f, 0.f, 0.f);
        if (n0 + lr < Nn)
            a4 = *(const float4*)&Ab[(size_t)(n0 + lr) * Nn + m0 + lm];
        As[lm + 0][lr] = a4.x; As[lm + 1][lr] = a4.y;
        As[lm + 2][lr] = a4.z; As[lm + 3][lr] = a4.w;
        float4 v4 = *(const float4*)&Vb[(size_t)(d0 + lr) * Nn + m0 + lm];
        Vs[lm + 0][lr] = v4.x; Vs[lm + 1][lr] = v4.y;
        Vs[lm + 2][lr] = v4.z; Vs[lm + 3][lr] = v4.w;
        __syncthreads();

#pragma unroll
        for (int k = 0; k < 16; ++k) {
            float4 av = *(const float4*)&As[k][ti * 4];
            float4 vv = *(const float4*)&Vs[k][tj * 4];
            float ar[4] = {av.x, av.y, av.z, av.w};
            float vr[4] = {vv.x, vv.y, vv.z, vv.w};
#pragma unroll
            for (int i = 0; i < 4; ++i)
#pragma unroll
                for (int j = 0; j < 4; ++j) acc[i][j] = fmaf(ar[i], vr[j], acc[i][j]);
        }
        __syncthreads();
    }

#pragma unroll
    for (int i = 0; i < 4; ++i) {
        const int n = n0 + ti * 4 + i;
        if (n >= Nn) continue;
#pragma unroll
        for (int j = 0; j < 4; ++j) {
            const int d  = d0 + tj * 4 + j;
            const int ch = g * Dd + d;
            const size_t oi = ((size_t)b * DHd + ch) * Nn + n;
            const float v = acc[i][j] + Vl[oi];
            Out[oi] = v > 0.f ? v : 0.f;
        }
    }
}

// ==========================================================================
// launch
// ==========================================================================
extern "C" void kernel_launch(void* const* d_in, const int* in_sizes, int n_in,
                              void* d_out, int out_size)
{
    const float* x    = (const float*)d_in[0];
    const float* Wq   = (const float*)d_in[1];
    const float* bq   = (const float*)d_in[2];
    const float* sq   = (const float*)d_in[3];
    const float* tq   = (const float*)d_in[4];
    const float* Wk   = (const float*)d_in[5];
    const float* bk   = (const float*)d_in[6];
    const float* sk   = (const float*)d_in[7];
    const float* tk   = (const float*)d_in[8];
    const float* Wv   = (const float*)d_in[9];
    const float* bv   = (const float*)d_in[10];
    const float* sv   = (const float*)d_in[11];
    const float* tv   = (const float*)d_in[12];
    const float* Wvl  = (const float*)d_in[13];
    const float* bvl  = (const float*)d_in[14];
    const float* svl  = (const float*)d_in[15];
    const float* tvl  = (const float*)d_in[16];
    const float* th1w = (const float*)d_in[17];
    const float* th1b = (const float*)d_in[18];
    const float* th2w = (const float*)d_in[19];
    const float* th2b = (const float*)d_in[20];
    const float* ab   = (const float*)d_in[21];
    const float* Wp   = (const float*)d_in[22];
    const float* bp   = (const float*)d_in[23];
    const float* sp   = (const float*)d_in[24];
    const float* tp   = (const float*)d_in[25];
    const int*   idxs = (const int*)d_in[26];
    float* out = (float*)d_out;

    void *pq, *pk, *pv, *pvl, *pattn, *po;
    cudaGetSymbolAddress(&pq, g_q);
    cudaGetSymbolAddress(&pk, g_k);
    cudaGetSymbolAddress(&pv, g_vmap);
    cudaGetSymbolAddress(&pvl, g_vl);
    cudaGetSymbolAddress(&pattn, g_attn);
    cudaGetSymbolAddress(&po, g_o);
    float* q    = (float*)pq;
    float* k    = (float*)pk;
    float* vmap = (float*)pv;
    float* vl   = (float*)pvl;
    float* attn = (float*)pattn;
    float* o    = (float*)po;

    const dim3 blk(256);

    // projections
    proj_kernel<<<dim3(13, NHKD / 64, Bn), blk>>>(x, Wq, bq, sq, tq, q, NHKD, DIMc);
    proj_kernel<<<dim3(13, NHKD / 64, Bn), blk>>>(x, Wk, bk, sk, tk, k, NHKD, DIMc);
    proj_kernel<<<dim3(13, DHd  / 64, Bn), blk>>>(x, Wv, bv, sv, tv, vmap, DHd, DIMc);

    // depthwise conv branch
    {
        const int total = Bn * DHd * Nn;
        dwconv_kernel<<<(total + 255) / 256, blk>>>(vmap, Wvl, bvl, svl, tvl, vl);
    }

    // fused attention (QK + bias -> mix1 -> softmax -> mix2)
    {
        const int smem = (TQ * Hh * Nn + Hh * Nn + TQ * NHKD) * (int)sizeof(float);
        cudaFuncSetAttribute(attn_kernel, cudaFuncAttributeMaxDynamicSharedMemorySize, smem);
        attn_kernel<<<dim3(Nn / TQ, Bn), blk, smem>>>(q, k, idxs, ab, th1w, th1b,
                                                      th2w, th2b, attn);
    }

    // AV + vl + relu
    av_kernel<<<dim3(13, 2, Bn * Hh), blk>>>(attn, vmap, vl, o);

    // final projection
    proj_kernel<<<dim3(13, DIMc / 64, Bn), blk>>>(o, Wp, bp, sp, tp, out, DIMc, DHd);
}

// round 3
// speedup vs baseline: 1.6124x; 1.6124x over previous
#include <cuda_runtime.h>
#include <math.h>

// ---------------- problem constants ----------------
#define Bn    32
#define DIMc  384
#define Rr    28
#define Nn    784          // R*R
#define Hh    8
#define KDd   32
#define Dd    128
#define NHKD  256          // H*KD
#define DHd   1024         // H*D
#define TQ    7            // queries per attention block

__device__ __constant__ float kSCALE = 0.17677669529663687f; // 1/sqrt(32)

// ---------------- scratch ----------------
__device__ float g_q   [(size_t)Bn * NHKD * Nn];
__device__ float g_k   [(size_t)Bn * NHKD * Nn];
__device__ float g_vmap[(size_t)Bn * DHd  * Nn];
__device__ float g_vl  [(size_t)Bn * DHd  * Nn];
__device__ float g_attn[(size_t)Bn * Hh * Nn * Nn];
__device__ float g_o   [(size_t)Bn * DHd  * Nn];

// ---------------- tf32 MMA helpers ----------------
__device__ __forceinline__ unsigned f2tf(float x) {
    unsigned r;
    asm("cvt.rna.tf32.f32 %0, %1;" : "=r"(r) : "f"(x));
    return r;
}

__device__ __forceinline__ void mma_tf32(float c[4],
                                         unsigned a0, unsigned a1, unsigned a2, unsigned a3,
                                         unsigned b0, unsigned b1)
{
    asm volatile("mma.sync.aligned.m16n8k8.row.col.f32.tf32.tf32.f32 "
                 "{%0,%1,%2,%3}, {%4,%5,%6,%7}, {%8,%9}, {%0,%1,%2,%3};"
                 : "+f"(c[0]), "+f"(c[1]), "+f"(c[2]), "+f"(c[3])
                 : "r"(a0), "r"(a1), "r"(a2), "r"(a3), "r"(b0), "r"(b1));
}

#define WS_STR 36   // [64 rows][32 k] stride -> frag LDS conflict-free
#define XS_STR 72   // [32 k][64 n] stride -> frag LDS conflict-free

// ==========================================================================
// tf32 pointwise-conv GEMM: Y[b,o,n] = ((sum_k W[o,k]*X[b,k,n])+bias[o])*s[o]+t[o]
// grid: (13, O/64, B)  block 256 (8 warps, warp tile 16m x 32n)
// ==========================================================================
__global__ __launch_bounds__(256)
void proj_mma(const float* __restrict__ X, const float* __restrict__ W,
              const float* __restrict__ bias, const float* __restrict__ s,
              const float* __restrict__ t, float* __restrict__ Y,
              int O, int K)
{
    __shared__ unsigned Ws[64 * WS_STR];   // [o][k]
    __shared__ unsigned Xs[32 * XS_STR];   // [k][n]

    const int b  = blockIdx.z;
    const int o0 = blockIdx.y * 64;
    const int n0 = blockIdx.x * 64;
    const int tid  = threadIdx.x;
    const int lane = tid & 31, wid = tid >> 5;
    const int wm = wid & 3, wn = wid >> 2;       // 4 warps along m, 2 along n
    const int gr = lane >> 2, tg = lane & 3;

    const float* Xb = X + (size_t)b * K * Nn;

    const int wrow = tid >> 3;          // 0..31 (W o-row, +32)
    const int wcol = (tid & 7) * 4;     // 0..28 (W k-col)
    const int xk   = tid >> 4;          // 0..15 (X k-row, +16)
    const int xn   = (tid & 15) * 4;    // 0..60 (X n-col)

    float acc[4][4];
#pragma unroll
    for (int j = 0; j < 4; ++j)
#pragma unroll
        for (int e = 0; e < 4; ++e) acc[j][e] = 0.f;

    for (int kk = 0; kk < K; kk += 32) {
#pragma unroll
        for (int h = 0; h < 2; ++h) {
            const int r = wrow + h * 32;
            float4 w4 = *(const float4*)&W[(size_t)(o0 + r) * K + kk + wcol];
            unsigned* p = &Ws[r * WS_STR + wcol];
            p[0] = f2tf(w4.x); p[1] = f2tf(w4.y); p[2] = f2tf(w4.z); p[3] = f2tf(w4.w);
        }
#pragma unroll
        for (int h = 0; h < 2; ++h) {
            const int r = xk + h * 16;
            float4 x4 = make_float4(0.f, 0.f, 0.f, 0.f);
            if (n0 + xn < Nn)
                x4 = *(const float4*)&Xb[(size_t)(kk + r) * Nn + n0 + xn];
            unsigned* p = &Xs[r * XS_STR + xn];
            p[0] = f2tf(x4.x); p[1] = f2tf(x4.y); p[2] = f2tf(x4.z); p[3] = f2tf(x4.w);
        }
        __syncthreads();

#pragma unroll
        for (int ks = 0; ks < 32; ks += 8) {
            const unsigned a0 = Ws[(wm * 16 + gr)     * WS_STR + ks + tg];
            const unsigned a1 = Ws[(wm * 16 + gr + 8) * WS_STR + ks + tg];
            const unsigned a2 = Ws[(wm * 16 + gr)     * WS_STR + ks + tg + 4];
            const unsigned a3 = Ws[(wm * 16 + gr + 8) * WS_STR + ks + tg + 4];
#pragma unroll
            for (int j = 0; j < 4; ++j) {
                const int n = wn * 32 + j * 8 + gr;
                const unsigned b0 = Xs[(ks + tg)     * XS_STR + n];
                const unsigned b1 = Xs[(ks + tg + 4) * XS_STR + n];
                mma_tf32(acc[j], a0, a1, a2, a3, b0, b1);
            }
        }
        __syncthreads();
    }

#pragma unroll
    for (int j = 0; j < 4; ++j) {
#pragma unroll
        for (int e = 0; e < 4; ++e) {
            const int row = wm * 16 + gr + ((e >> 1) ? 8 : 0);
            const int col = wn * 32 + j * 8 + tg * 2 + (e & 1);
            const int o = o0 + row, n = n0 + col;
            if (n < Nn)
                Y[((size_t)b * O + o) * Nn + n] = (acc[j][e] + bias[o]) * s[o] + t[o];
        }
    }
}

// ==========================================================================
// tf32 AV GEMM: O[n,d] = sum_m P[n][m] * V[d][m]; epilogue +Vl, relu.
// A = P row-major [M=n][K=m]; B = V[d][m] (= col-major [m][d]).
// grid: (13 n-tiles, 2 d-tiles, B*H)  block 256
// ==========================================================================
__global__ __launch_bounds__(256)
void av_mma(const float* __restrict__ Attn, const float* __restrict__ V,
            const float* __restrict__ Vl, float* __restrict__ Out)
{
    __shared__ unsigned As[64 * WS_STR];   // P tile [n][m]
    __shared__ unsigned Vs[64 * WS_STR];   // V tile [d][m]

    const int bg = blockIdx.z;
    const int b  = bg >> 3;
    const int g  = bg & 7;
    const int n0 = blockIdx.x * 64;
    const int d0 = blockIdx.y * 64;
    const int tid  = threadIdx.x;
    const int lane = tid & 31, wid = tid >> 5;
    const int wm = wid & 3, wn = wid >> 2;    // wm along n, wn along d
    const int gr = lane >> 2, tg = lane & 3;

    const float* Ab = Attn + (size_t)bg * Nn * Nn;            // [n][m]
    const float* Vb = V + ((size_t)b * DHd + g * Dd) * Nn;    // [d][m]

    const int lrow = tid >> 3;          // 0..31 (+32)
    const int lcol = (tid & 7) * 4;     // m 0..28

    float acc[4][4];
#pragma unroll
    for (int j = 0; j < 4; ++j)
#pragma unroll
        for (int e = 0; e < 4; ++e) acc[j][e] = 0.f;

    for (int m0 = 0; m0 < Nn; m0 += 32) {   // 25 iters; last partial (m 768..783)
        const bool mok = (m0 + lcol) < Nn;
#pragma unroll
        for (int h = 0; h < 2; ++h) {
            const int r = lrow + h * 32;
            float4 a4 = make_float4(0.f, 0.f, 0.f, 0.f);
            if (mok && (n0 + r) < Nn)
                a4 = *(const float4*)&Ab[(size_t)(n0 + r) * Nn + m0 + lcol];
            unsigned* p = &As[r * WS_STR + lcol];
            p[0] = f2tf(a4.x); p[1] = f2tf(a4.y); p[2] = f2tf(a4.z); p[3] = f2tf(a4.w);

            float4 v4 = make_float4(0.f, 0.f, 0.f, 0.f);
            if (mok)
                v4 = *(const float4*)&Vb[(size_t)(d0 + r) * Nn + m0 + lcol];
            unsigned* q = &Vs[r * WS_STR + lcol];
            q[0] = f2tf(v4.x); q[1] = f2tf(v4.y); q[2] = f2tf(v4.z); q[3] = f2tf(v4.w);
        }
        __syncthreads();

#pragma unroll
        for (int ks = 0; ks < 32; ks += 8) {
            const unsigned a0 = As[(wm * 16 + gr)     * WS_STR + ks + tg];
            const unsigned a1 = As[(wm * 16 + gr + 8) * WS_STR + ks + tg];
            const unsigned a2 = As[(wm * 16 + gr)     * WS_STR + ks + tg + 4];
            const unsigned a3 = As[(wm * 16 + gr + 8) * WS_STR + ks + tg + 4];
#pragma unroll
            for (int j = 0; j < 4; ++j) {
                const int d = wn * 32 + j * 8 + gr;
                const unsigned b0 = Vs[d * WS_STR + ks + tg];
                const unsigned b1 = Vs[d * WS_STR + ks + tg + 4];
                mma_tf32(acc[j], a0, a1, a2, a3, b0, b1);
            }
        }
        __syncthreads();
    }

#pragma unroll
    for (int j = 0; j < 4; ++j) {
#pragma unroll
        for (int e = 0; e < 4; ++e) {
            const int n = n0 + wm * 16 + gr + ((e >> 1) ? 8 : 0);
            const int d = d0 + wn * 32 + j * 8 + tg * 2 + (e & 1);
            if (n < Nn) {
                const size_t oi = ((size_t)b * DHd + g * Dd + d) * Nn + n;
                const float v = acc[j][e] + Vl[oi];
                Out[oi] = v > 0.f ? v : 0.f;
            }
        }
    }
}

// ==========================================================================
// Depthwise 3x3 conv (SAME) + bias + affine
// ==========================================================================
__global__ __launch_bounds__(256)
void dwconv_kernel(const float* __restrict__ V, const float* __restrict__ Wc,
                   const float* __restrict__ bias, const float* __restrict__ s,
                   const float* __restrict__ t, float* __restrict__ Out)
{
    const int idx = blockIdx.x * 256 + threadIdx.x;
    if (idx >= Bn * DHd * Nn) return;
    const int pos = idx % Nn;
    const int ch  = (idx / Nn) % DHd;
    const int b   = idx / (Nn * DHd);
    const int y = pos / Rr, x = pos % Rr;

    const float* vb = V + ((size_t)b * DHd + ch) * Nn;
    const float* wc = Wc + ch * 9;
    float acc = 0.f;
#pragma unroll
    for (int dy = 0; dy < 3; ++dy) {
        const int yy = y + dy - 1;
        if (yy < 0 || yy >= Rr) continue;
#pragma unroll
        for (int dx = 0; dx < 3; ++dx) {
            const int xx = x + dx - 1;
            if (xx < 0 || xx >= Rr) continue;
            acc = fmaf(vb[yy * Rr + xx], wc[dy * 3 + dx], acc);
        }
    }
    Out[idx] = (acc + bias[ch]) * s[ch] + t[ch];
}

// ==========================================================================
// Fused attention core (fp32): QK*scale + bias -> mix1 -> softmax -> mix2
// ==========================================================================
__global__ __launch_bounds__(256)
void attn_kernel(const float* __restrict__ Q, const float* __restrict__ K,
                 const int*   __restrict__ idxs, const float* __restrict__ ab,
                 const float* __restrict__ th1w, const float* __restrict__ th1b,
                 const float* __restrict__ th2w, const float* __restrict__ th2b,
                 float* __restrict__ Attn)
{
    extern __shared__ float sm[];
    float* S  = sm;                       // TQ*8*784
    float* A  = S + TQ * Hh * Nn;         // 8*784
    float* qs = A + Hh * Nn;              // TQ*256

    const int b   = blockIdx.y;
    const int n0  = blockIdx.x * TQ;
    const int tid = threadIdx.x;
    const int g    = tid >> 5;
    const int lane = tid & 31;

    for (int e = tid; e < TQ * NHKD; e += 256) {
        const int nq = e / NHKD, c = e % NHKD;
        qs[nq * NHKD + c] = Q[((size_t)b * NHKD + c) * Nn + (n0 + nq)];
    }
    __syncthreads();

    for (int h = 0; h < Hh; ++h) {
        const float* Kb = K + ((size_t)b * NHKD + h * KDd) * Nn;
        for (int m = tid; m < Nn; m += 256) {
            float kk[KDd];
#pragma unroll
            for (int j = 0; j < KDd; ++j) kk[j] = Kb[j * Nn + m];
#pragma unroll
            for (int nq = 0; nq < TQ; ++nq) {
                const float* qv = &qs[nq * NHKD + h * KDd];
                float acc = 0.f;
#pragma unroll
                for (int j = 0; j < KDd; ++j) acc = fmaf(qv[j], kk[j], acc);
                const int n   = n0 + nq;
                const int idx = idxs[n * Nn + m];
                S[(nq * Hh + h) * Nn + m] = acc * kSCALE + ab[h * Nn + idx];
            }
        }
    }
    __syncthreads();

    float w1[Hh], w2[Hh];
#pragma unroll
    for (int h = 0; h < Hh; ++h) { w1[h] = th1w[g * Hh + h]; w2[h] = th2w[g * Hh + h]; }
    const float b1 = th1b[g], b2 = th2b[g];

    for (int nq = 0; nq < TQ; ++nq) {
        const float* Sq = S + nq * Hh * Nn;
        float maxv = -1e30f;
        for (int m = lane; m < Nn; m += 32) {
            float a = b1;
#pragma unroll
            for (int h = 0; h < Hh; ++h) a = fmaf(w1[h], Sq[h * Nn + m], a);
            A[g * Nn + m] = a;
            maxv = fmaxf(maxv, a);
        }
#pragma unroll
        for (int off = 16; off; off >>= 1)
            maxv = fmaxf(maxv, __shfl_xor_sync(0xffffffffu, maxv, off));
        float sum = 0.f;
        for (int m = lane; m < Nn; m += 32) {
            const float e = __expf(A[g * Nn + m] - maxv);
            A[g * Nn + m] = e;
            sum += e;
        }
#pragma unroll
        for (int off = 16; off; off >>= 1)
            sum += __shfl_xor_sync(0xffffffffu, sum, off);
        const float inv = 1.f / sum;
        for (int m = lane; m < Nn; m += 32) A[g * Nn + m] *= inv;
        __syncthreads();

        const size_t obase = (((size_t)(b * Hh + g)) * Nn + (n0 + nq)) * Nn;
        for (int m = lane; m < Nn; m += 32) {
            float a = b2;
#pragma unroll
            for (int h = 0; h < Hh; ++h) a = fmaf(w2[h], A[h * Nn + m], a);
            Attn[obase + m] = a;
        }
        __syncthreads();
    }
}

// ==========================================================================
// launch
// ==========================================================================
extern "C" void kernel_launch(void* const* d_in, const int* in_sizes, int n_in,
                              void* d_out, int out_size)
{
    const float* x    = (const float*)d_in[0];
    const float* Wq   = (const float*)d_in[1];
    const float* bq   = (const float*)d_in[2];
    const float* sq   = (const float*)d_in[3];
    const float* tq   = (const float*)d_in[4];
    const float* Wk   = (const float*)d_in[5];
    const float* bk   = (const float*)d_in[6];
    const float* sk   = (const float*)d_in[7];
    const float* tk   = (const float*)d_in[8];
    const float* Wv   = (const float*)d_in[9];
    const float* bv   = (const float*)d_in[10];
    const float* sv   = (const float*)d_in[11];
    const float* tv   = (const float*)d_in[12];
    const float* Wvl  = (const float*)d_in[13];
    const float* bvl  = (const float*)d_in[14];
    const float* svl  = (const float*)d_in[15];
    const float* tvl  = (const float*)d_in[16];
    const float* th1w = (const float*)d_in[17];
    const float* th1b = (const float*)d_in[18];
    const float* th2w = (const float*)d_in[19];
    const float* th2b = (const float*)d_in[20];
    const float* ab   = (const float*)d_in[21];
    const float* Wp   = (const float*)d_in[22];
    const float* bp   = (const float*)d_in[23];
    const float* sp   = (const float*)d_in[24];
    const float* tp   = (const float*)d_in[25];
    const int*   idxs = (const int*)d_in[26];
    float* out = (float*)d_out;

    void *pq, *pk, *pv, *pvl, *pattn, *po;
    cudaGetSymbolAddress(&pq, g_q);
    cudaGetSymbolAddress(&pk, g_k);
    cudaGetSymbolAddress(&pv, g_vmap);
    cudaGetSymbolAddress(&pvl, g_vl);
    cudaGetSymbolAddress(&pattn, g_attn);
    cudaGetSymbolAddress(&po, g_o);
    float* q    = (float*)pq;
    float* k    = (float*)pk;
    float* vmap = (float*)pv;
    float* vl   = (float*)pvl;
    float* attn = (float*)pattn;
    float* o    = (float*)po;

    const dim3 blk(256);

    // projections (tf32 tensor cores)
    proj_mma<<<dim3(13, NHKD / 64, Bn), blk>>>(x, Wq, bq, sq, tq, q, NHKD, DIMc);
    proj_mma<<<dim3(13, NHKD / 64, Bn), blk>>>(x, Wk, bk, sk, tk, k, NHKD, DIMc);
    proj_mma<<<dim3(13, DHd  / 64, Bn), blk>>>(x, Wv, bv, sv, tv, vmap, DHd, DIMc);

    // depthwise conv branch
    {
        const int total = Bn * DHd * Nn;
        dwconv_kernel<<<(total + 255) / 256, blk>>>(vmap, Wvl, bvl, svl, tvl, vl);
    }

    // fused attention (fp32)
    {
        const int smem = (TQ * Hh * Nn + Hh * Nn + TQ * NHKD) * (int)sizeof(float);
        cudaFuncSetAttribute(attn_kernel, cudaFuncAttributeMaxDynamicSharedMemorySize, smem);
        attn_kernel<<<dim3(Nn / TQ, Bn), blk, smem>>>(q, k, idxs, ab, th1w, th1b,
                                                      th2w, th2b, attn);
    }

    // AV + vl + relu (tf32 tensor cores)
    av_mma<<<dim3(13, 2, Bn * Hh), blk>>>(attn, vmap, vl, o);

    // final projection (tf32 tensor cores)
    proj_mma<<<dim3(13, DIMc / 64, Bn), blk>>>(o, Wp, bp, sp, tp, out, DIMc, DHd);
}

// round 5
// speedup vs baseline: 1.6269x; 1.0090x over previous
#include <cuda_runtime.h>
#include <math.h>

// ---------------- problem constants ----------------
#define Bn    32
#define DIMc  384
#define Rr    28
#define Nn    784          // R*R
#define Hh    8
#define KDd   32
#define Dd    128
#define NHKD  256          // H*KD
#define DHd   1024         // H*D
#define TQ    7            // queries per attention block

__device__ __constant__ float kSCALE = 0.17677669529663687f; // 1/sqrt(32)

// ---------------- scratch ----------------
__device__ float g_q   [(size_t)Bn * NHKD * Nn];
__device__ float g_k   [(size_t)Bn * NHKD * Nn];
__device__ float g_vmap[(size_t)Bn * DHd  * Nn];
__device__ float g_vl  [(size_t)Bn * DHd  * Nn];
__device__ float g_attn[(size_t)Bn * Hh * Nn * Nn];
__device__ float g_o   [(size_t)Bn * DHd  * Nn];

// ---------------- tf32 MMA helpers ----------------
__device__ __forceinline__ unsigned f2tf(float x) {
    unsigned r;
    asm("cvt.rna.tf32.f32 %0, %1;" : "=r"(r) : "f"(x));
    return r;
}

__device__ __forceinline__ void mma_tf32(float c[4],
                                         unsigned a0, unsigned a1, unsigned a2, unsigned a3,
                                         unsigned b0, unsigned b1)
{
    asm volatile("mma.sync.aligned.m16n8k8.row.col.f32.tf32.tf32.f32 "
                 "{%0,%1,%2,%3}, {%4,%5,%6,%7}, {%8,%9}, {%0,%1,%2,%3};"
                 : "+f"(c[0]), "+f"(c[1]), "+f"(c[2]), "+f"(c[3])
                 : "r"(a0), "r"(a1), "r"(a2), "r"(a3), "r"(b0), "r"(b1));
}

#define WS_STR 36
#define XS_STR 72

// ==========================================================================
// tf32 pointwise-conv GEMM
// ==========================================================================
__global__ __launch_bounds__(256)
void proj_mma(const float* __restrict__ X, const float* __restrict__ W,
              const float* __restrict__ bias, const float* __restrict__ s,
              const float* __restrict__ t, float* __restrict__ Y,
              int O, int K)
{
    __shared__ unsigned Ws[64 * WS_STR];   // [o][k]
    __shared__ unsigned Xs[32 * XS_STR];   // [k][n]

    const int b  = blockIdx.z;
    const int o0 = blockIdx.y * 64;
    const int n0 = blockIdx.x * 64;
    const int tid  = threadIdx.x;
    const int lane = tid & 31, wid = tid >> 5;
    const int wm = wid & 3, wn = wid >> 2;
    const int gr = lane >> 2, tg = lane & 3;

    const float* Xb = X + (size_t)b * K * Nn;

    const int wrow = tid >> 3;
    const int wcol = (tid & 7) * 4;
    const int xk   = tid >> 4;
    const int xn   = (tid & 15) * 4;

    float acc[4][4];
#pragma unroll
    for (int j = 0; j < 4; ++j)
#pragma unroll
        for (int e = 0; e < 4; ++e) acc[j][e] = 0.f;

    for (int kk = 0; kk < K; kk += 32) {
#pragma unroll
        for (int h = 0; h < 2; ++h) {
            const int r = wrow + h * 32;
            float4 w4 = *(const float4*)&W[(size_t)(o0 + r) * K + kk + wcol];
            unsigned* p = &Ws[r * WS_STR + wcol];
            p[0] = f2tf(w4.x); p[1] = f2tf(w4.y); p[2] = f2tf(w4.z); p[3] = f2tf(w4.w);
        }
#pragma unroll
        for (int h = 0; h < 2; ++h) {
            const int r = xk + h * 16;
            float4 x4 = make_float4(0.f, 0.f, 0.f, 0.f);
            if (n0 + xn < Nn)
                x4 = *(const float4*)&Xb[(size_t)(kk + r) * Nn + n0 + xn];
            unsigned* p = &Xs[r * XS_STR + xn];
            p[0] = f2tf(x4.x); p[1] = f2tf(x4.y); p[2] = f2tf(x4.z); p[3] = f2tf(x4.w);
        }
        __syncthreads();

#pragma unroll
        for (int ks = 0; ks < 32; ks += 8) {
            const unsigned a0 = Ws[(wm * 16 + gr)     * WS_STR + ks + tg];
            const unsigned a1 = Ws[(wm * 16 + gr + 8) * WS_STR + ks + tg];
            const unsigned a2 = Ws[(wm * 16 + gr)     * WS_STR + ks + tg + 4];
            const unsigned a3 = Ws[(wm * 16 + gr + 8) * WS_STR + ks + tg + 4];
#pragma unroll
            for (int j = 0; j < 4; ++j) {
                const int n = wn * 32 + j * 8 + gr;
                const unsigned b0 = Xs[(ks + tg)     * XS_STR + n];
                const unsigned b1 = Xs[(ks + tg + 4) * XS_STR + n];
                mma_tf32(acc[j], a0, a1, a2, a3, b0, b1);
            }
        }
        __syncthreads();
    }

#pragma unroll
    for (int j = 0; j < 4; ++j) {
#pragma unroll
        for (int e = 0; e < 4; ++e) {
            const int row = wm * 16 + gr + ((e >> 1) ? 8 : 0);
            const int col = wn * 32 + j * 8 + tg * 2 + (e & 1);
            const int o = o0 + row, n = n0 + col;
            if (n < Nn)
                Y[((size_t)b * O + o) * Nn + n] = (acc[j][e] + bias[o]) * s[o] + t[o];
        }
    }
}

// ==========================================================================
// tf32 AV GEMM + vl + relu
// ==========================================================================
__global__ __launch_bounds__(256)
void av_mma(const float* __restrict__ Attn, const float* __restrict__ V,
            const float* __restrict__ Vl, float* __restrict__ Out)
{
    __shared__ unsigned As[64 * WS_STR];
    __shared__ unsigned Vs[64 * WS_STR];

    const int bg = blockIdx.z;
    const int b  = bg >> 3;
    const int g  = bg & 7;
    const int n0 = blockIdx.x * 64;
    const int d0 = blockIdx.y * 64;
    const int tid  = threadIdx.x;
    const int lane = tid & 31, wid = tid >> 5;
    const int wm = wid & 3, wn = wid >> 2;
    const int gr = lane >> 2, tg = lane & 3;

    const float* Ab = Attn + (size_t)bg * Nn * Nn;
    const float* Vb = V + ((size_t)b * DHd + g * Dd) * Nn;

    const int lrow = tid >> 3;
    const int lcol = (tid & 7) * 4;

    float acc[4][4];
#pragma unroll
    for (int j = 0; j < 4; ++j)
#pragma unroll
        for (int e = 0; e < 4; ++e) acc[j][e] = 0.f;

    for (int m0 = 0; m0 < Nn; m0 += 32) {
        const bool mok = (m0 + lcol) < Nn;
#pragma unroll
        for (int h = 0; h < 2; ++h) {
            const int r = lrow + h * 32;
            float4 a4 = make_float4(0.f, 0.f, 0.f, 0.f);
            if (mok && (n0 + r) < Nn)
                a4 = *(const float4*)&Ab[(size_t)(n0 + r) * Nn + m0 + lcol];
            unsigned* p = &As[r * WS_STR + lcol];
            p[0] = f2tf(a4.x); p[1] = f2tf(a4.y); p[2] = f2tf(a4.z); p[3] = f2tf(a4.w);

            float4 v4 = make_float4(0.f, 0.f, 0.f, 0.f);
            if (mok)
                v4 = *(const float4*)&Vb[(size_t)(d0 + r) * Nn + m0 + lcol];
            unsigned* q = &Vs[r * WS_STR + lcol];
            q[0] = f2tf(v4.x); q[1] = f2tf(v4.y); q[2] = f2tf(v4.z); q[3] = f2tf(v4.w);
        }
        __syncthreads();

#pragma unroll
        for (int ks = 0; ks < 32; ks += 8) {
            const unsigned a0 = As[(wm * 16 + gr)     * WS_STR + ks + tg];
            const unsigned a1 = As[(wm * 16 + gr + 8) * WS_STR + ks + tg];
            const unsigned a2 = As[(wm * 16 + gr)     * WS_STR + ks + tg + 4];
            const unsigned a3 = As[(wm * 16 + gr + 8) * WS_STR + ks + tg + 4];
#pragma unroll
            for (int j = 0; j < 4; ++j) {
                const int d = wn * 32 + j * 8 + gr;
                const unsigned b0 = Vs[d * WS_STR + ks + tg];
                const unsigned b1 = Vs[d * WS_STR + ks + tg + 4];
                mma_tf32(acc[j], a0, a1, a2, a3, b0, b1);
            }
        }
        __syncthreads();
    }

#pragma unroll
    for (int j = 0; j < 4; ++j) {
#pragma unroll
        for (int e = 0; e < 4; ++e) {
            const int n = n0 + wm * 16 + gr + ((e >> 1) ? 8 : 0);
            const int d = d0 + wn * 32 + j * 8 + tg * 2 + (e & 1);
            if (n < Nn) {
                const size_t oi = ((size_t)b * DHd + g * Dd + d) * Nn + n;
                const float v = acc[j][e] + Vl[oi];
                Out[oi] = v > 0.f ? v : 0.f;
            }
        }
    }
}

// ==========================================================================
// Depthwise 3x3 conv v2: one block per (b,channel); plane staged in smem
// ==========================================================================
__global__ __launch_bounds__(256)
void dwconv_kernel(const float* __restrict__ V, const float* __restrict__ Wc,
                   const float* __restrict__ bias, const float* __restrict__ s,
                   const float* __restrict__ t, float* __restrict__ Out)
{
    __shared__ float p[Nn];
    const int bc  = blockIdx.x;          // b*DHd + ch
    const int ch  = bc & (DHd - 1);
    const int tid = threadIdx.x;

    const float* vb = V + (size_t)bc * Nn;
    for (int i = tid; i < Nn; i += 256) p[i] = vb[i];

    float w[9];
#pragma unroll
    for (int j = 0; j < 9; ++j) w[j] = __ldg(&Wc[ch * 9 + j]);
    const float bi = bias[ch], si = s[ch], ti = t[ch];
    __syncthreads();

    for (int i = tid; i < Nn; i += 256) {
        const int y = i / Rr, x = i % Rr;
        float acc = 0.f;
#pragma unroll
        for (int dy = 0; dy < 3; ++dy) {
            const int yy = y + dy - 1;
            if (yy < 0 || yy >= Rr) continue;
#pragma unroll
            for (int dx = 0; dx < 3; ++dx) {
                const int xx = x + dx - 1;
                if (xx < 0 || xx >= Rr) continue;
                acc = fmaf(p[yy * Rr + xx], w[dy * 3 + dx], acc);
            }
        }
        Out[(size_t)bc * Nn + i] = (acc + bi) * si + ti;
    }
}

// ==========================================================================
// Fused attention core v2:
//   phase 1: QK^T via tf32 MMA (+ scale + arithmetic rel-pos bias from smem)
//   phase 2: mix1 -> softmax -> mix2 -> write
// grid: (112, B)  block 256 (8 warps; warp g = head g)
// smem: S[7][8][784] | ab[8][784] (aliased w/ A[8][784] in phase 2) | qs[7][256]
// ==========================================================================
__global__ __launch_bounds__(256)
void attn_kernel(const float* __restrict__ Q, const float* __restrict__ K,
                 const float* __restrict__ ab,
                 const float* __restrict__ th1w, const float* __restrict__ th1b,
                 const float* __restrict__ th2w, const float* __restrict__ th2b,
                 float* __restrict__ Attn)
{
    extern __shared__ float sm[];
    float* S    = sm;                          // 43904 floats
    float* ab_s = S + TQ * Hh * Nn;            // 6272 floats (phase 1)
    float* A    = ab_s;                        // alias     (phase 2)
    float* qs   = ab_s + Hh * Nn;              // 1792 floats (phase 1)

    const int b   = blockIdx.y;
    const int n0  = blockIdx.x * TQ;
    const int tid = threadIdx.x;
    const int g    = tid >> 5;
    const int lane = tid & 31;
    const int gr = lane >> 2, tg = lane & 3;

    // stage ab + Q rows
    for (int e = tid; e < Hh * Nn; e += 256) ab_s[e] = ab[e];
    for (int e = tid; e < TQ * NHKD; e += 256) {
        const int nq = e >> 8, c = e & 255;
        qs[nq * NHKD + c] = Q[((size_t)b * NHKD + c) * Nn + (n0 + nq)];
    }
    __syncthreads();

    // ---------------- phase 1: MMA scores ----------------
    {
        // A fragments: 16 query rows (7 valid, rest zero), K=32 in 4 chunks of 8
        unsigned af[4][4];
#pragma unroll
        for (int ks = 0; ks < 4; ++ks) {
            float q0 = 0.f, q2 = 0.f;
            if (gr < TQ) {
                q0 = qs[gr * NHKD + g * KDd + ks * 8 + tg];
                q2 = qs[gr * NHKD + g * KDd + ks * 8 + tg + 4];
            }
            af[ks][0] = f2tf(q0); af[ks][1] = 0u;
            af[ks][2] = f2tf(q2); af[ks][3] = 0u;
        }

        const float* Kb = K + ((size_t)b * NHKD + g * KDd) * Nn;
        const float* abg = ab_s + g * Nn;
        const int n = n0 + gr;                  // query index (valid if gr<7)
        const int yn = n / Rr, xn = n % Rr;
        float* Sg = S + g * Nn;                 // S[(gr*8+g)*784 + m] base uses gr below

#pragma unroll 2
        for (int m0 = 0; m0 < Nn; m0 += 8) {
            unsigned bf[4][2];
#pragma unroll
            for (int ks = 0; ks < 4; ++ks) {
                bf[ks][0] = f2tf(Kb[(size_t)(ks * 8 + tg)     * Nn + m0 + gr]);
                bf[ks][1] = f2tf(Kb[(size_t)(ks * 8 + tg + 4) * Nn + m0 + gr]);
            }
            float c[4] = {0.f, 0.f, 0.f, 0.f};
#pragma unroll
            for (int ks = 0; ks < 4; ++ks)
                mma_tf32(c, af[ks][0], af[ks][1], af[ks][2], af[ks][3],
                         bf[ks][0], bf[ks][1]);
            if (gr < TQ) {
#pragma unroll
                for (int e = 0; e < 2; ++e) {
                    const int m  = m0 + tg * 2 + e;
                    const int ym = m / Rr, xm = m % Rr;
                    const int dy = yn > ym ? yn - ym : ym - yn;
                    const int dx = xn > xm ? xn - xm : xm - xn;
                    Sg[(size_t)gr * Hh * Nn + m] = c[e] * kSCALE + abg[dy * Rr + dx];
                }
            }
        }
    }
    __syncthreads();

    // ---------------- phase 2: mix1 -> softmax -> mix2 ----------------
    float w1[Hh], w2[Hh];
#pragma unroll
    for (int h = 0; h < Hh; ++h) { w1[h] = th1w[g * Hh + h]; w2[h] = th2w[g * Hh + h]; }
    const float b1 = th1b[g], b2 = th2b[g];

    for (int nq = 0; nq < TQ; ++nq) {
        const float* Sq = S + (size_t)nq * Hh * Nn;
        float maxv = -1e30f;
        for (int m = lane; m < Nn; m += 32) {
            float a = b1;
#pragma unroll
            for (int h = 0; h < Hh; ++h) a = fmaf(w1[h], Sq[h * Nn + m], a);
            A[g * Nn + m] = a;
            maxv = fmaxf(maxv, a);
        }
#pragma unroll
        for (int off = 16; off; off >>= 1)
            maxv = fmaxf(maxv, __shfl_xor_sync(0xffffffffu, maxv, off));
        float sum = 0.f;
        for (int m = lane; m < Nn; m += 32) {
            const float e = __expf(A[g * Nn + m] - maxv);
            A[g * Nn + m] = e;
            sum += e;
        }
#pragma unroll
        for (int off = 16; off; off >>= 1)
            sum += __shfl_xor_sync(0xffffffffu, sum, off);
        const float inv = 1.f / sum;
        for (int m = lane; m < Nn; m += 32) A[g * Nn + m] *= inv;
        __syncthreads();

        const size_t obase = (((size_t)(b * Hh + g)) * Nn + (n0 + nq)) * Nn;
        for (int m = lane; m < Nn; m += 32) {
            float a = b2;
#pragma unroll
            for (int h = 0; h < Hh; ++h) a = fmaf(w2[h], A[h * Nn + m], a);
            Attn[obase + m] = a;
        }
        __syncthreads();
    }
}

// ==========================================================================
// launch
// ==========================================================================
extern "C" void kernel_launch(void* const* d_in, const int* in_sizes, int n_in,
                              void* d_out, int out_size)
{
    const float* x    = (const float*)d_in[0];
    const float* Wq   = (const float*)d_in[1];
    const float* bq   = (const float*)d_in[2];
    const float* sq   = (const float*)d_in[3];
    const float* tq   = (const float*)d_in[4];
    const float* Wk   = (const float*)d_in[5];
    const float* bk   = (const float*)d_in[6];
    const float* sk   = (const float*)d_in[7];
    const float* tk   = (const float*)d_in[8];
    const float* Wv   = (const float*)d_in[9];
    const float* bv   = (const float*)d_in[10];
    const float* sv   = (const float*)d_in[11];
    const float* tv   = (const float*)d_in[12];
    const float* Wvl  = (const float*)d_in[13];
    const float* bvl  = (const float*)d_in[14];
    const float* svl  = (const float*)d_in[15];
    const float* tvl  = (const float*)d_in[16];
    const float* th1w = (const float*)d_in[17];
    const float* th1b = (const float*)d_in[18];
    const float* th2w = (const float*)d_in[19];
    const float* th2b = (const float*)d_in[20];
    const float* ab   = (const float*)d_in[21];
    const float* Wp   = (const float*)d_in[22];
    const float* bp   = (const float*)d_in[23];
    const float* sp   = (const float*)d_in[24];
    const float* tp   = (const float*)d_in[25];
    float* out = (float*)d_out;

    void *pq, *pk, *pv, *pvl, *pattn, *po;
    cudaGetSymbolAddress(&pq, g_q);
    cudaGetSymbolAddress(&pk, g_k);
    cudaGetSymbolAddress(&pv, g_vmap);
    cudaGetSymbolAddress(&pvl, g_vl);
    cudaGetSymbolAddress(&pattn, g_attn);
    cudaGetSymbolAddress(&po, g_o);
    float* q    = (float*)pq;
    float* k    = (float*)pk;
    float* vmap = (float*)pv;
    float* vl   = (float*)pvl;
    float* attn = (float*)pattn;
    float* o    = (float*)po;

    const dim3 blk(256);

    // projections (tf32 tensor cores)
    proj_mma<<<dim3(13, NHKD / 64, Bn), blk>>>(x, Wq, bq, sq, tq, q, NHKD, DIMc);
    proj_mma<<<dim3(13, NHKD / 64, Bn), blk>>>(x, Wk, bk, sk, tk, k, NHKD, DIMc);
    proj_mma<<<dim3(13, DHd  / 64, Bn), blk>>>(x, Wv, bv, sv, tv, vmap, DHd, DIMc);

    // depthwise conv branch
    dwconv_kernel<<<Bn * DHd, blk>>>(vmap, Wvl, bvl, svl, tvl, vl);

    // fused attention (MMA QK + mix + softmax)
    {
        const int smem = (TQ * Hh * Nn + Hh * Nn + TQ * NHKD) * (int)sizeof(float);
        cudaFuncSetAttribute(attn_kernel, cudaFuncAttributeMaxDynamicSharedMemorySize, smem);
        attn_kernel<<<dim3(Nn / TQ, Bn), blk, smem>>>(q, k, ab, th1w, th1b,
                                                      th2w, th2b, attn);
    }

    // AV + vl + relu (tf32 tensor cores)
    av_mma<<<dim3(13, 2, Bn * Hh), blk>>>(attn, vmap, vl, o);

    // final projection (tf32 tensor cores)
    proj_mma<<<dim3(13, DIMc / 64, Bn), blk>>>(o, Wp, bp, sp, tp, out, DIMc, DHd);
}

// round 7
// speedup vs baseline: 1.7520x; 1.0769x over previous
#include <cuda_runtime.h>
#include <math.h>

// ---------------- problem constants ----------------
#define Bn    32
#define DIMc  384
#define Rr    28
#define Nn    784          // R*R
#define Hh    8
#define KDd   32
#define Dd    128
#define NHKD  256          // H*KD
#define DHd   1024         // H*D
#define TQ    7            // queries per attention block

__device__ __constant__ float kSCALE = 0.17677669529663687f; // 1/sqrt(32)

// ---------------- scratch ----------------
__device__ float g_q   [(size_t)Bn * NHKD * Nn];
__device__ float g_k   [(size_t)Bn * NHKD * Nn];
__device__ float g_vmap[(size_t)Bn * DHd  * Nn];
__device__ float g_vl  [(size_t)Bn * DHd  * Nn];
__device__ float g_attn[(size_t)Bn * Hh * Nn * Nn];
__device__ float g_o   [(size_t)Bn * DHd  * Nn];

// ---------------- tf32 MMA helpers ----------------
__device__ __forceinline__ unsigned f2tf(float x) {
    unsigned r;
    asm("cvt.rna.tf32.f32 %0, %1;" : "=r"(r) : "f"(x));
    return r;
}

__device__ __forceinline__ void mma_tf32(float c[4],
                                         unsigned a0, unsigned a1, unsigned a2, unsigned a3,
                                         unsigned b0, unsigned b1)
{
    asm volatile("mma.sync.aligned.m16n8k8.row.col.f32.tf32.tf32.f32 "
                 "{%0,%1,%2,%3}, {%4,%5,%6,%7}, {%8,%9}, {%0,%1,%2,%3};"
                 : "+f"(c[0]), "+f"(c[1]), "+f"(c[2]), "+f"(c[3])
                 : "r"(a0), "r"(a1), "r"(a2), "r"(a3), "r"(b0), "r"(b1));
}

#define WS_STR 36
#define XS_STR 72

// ==========================================================================
// tf32 pointwise-conv GEMM
// ==========================================================================
__global__ __launch_bounds__(256)
void proj_mma(const float* __restrict__ X, const float* __restrict__ W,
              const float* __restrict__ bias, const float* __restrict__ s,
              const float* __restrict__ t, float* __restrict__ Y,
              int O, int K)
{
    __shared__ unsigned Ws[64 * WS_STR];   // [o][k]
    __shared__ unsigned Xs[32 * XS_STR];   // [k][n]

    const int b  = blockIdx.z;
    const int o0 = blockIdx.y * 64;
    const int n0 = blockIdx.x * 64;
    const int tid  = threadIdx.x;
    const int lane = tid & 31, wid = tid >> 5;
    const int wm = wid & 3, wn = wid >> 2;
    const int gr = lane >> 2, tg = lane & 3;

    const float* Xb = X + (size_t)b * K * Nn;

    const int wrow = tid >> 3;
    const int wcol = (tid & 7) * 4;
    const int xk   = tid >> 4;
    const int xn   = (tid & 15) * 4;

    float acc[4][4];
#pragma unroll
    for (int j = 0; j < 4; ++j)
#pragma unroll
        for (int e = 0; e < 4; ++e) acc[j][e] = 0.f;

    for (int kk = 0; kk < K; kk += 32) {
#pragma unroll
        for (int h = 0; h < 2; ++h) {
            const int r = wrow + h * 32;
            float4 w4 = *(const float4*)&W[(size_t)(o0 + r) * K + kk + wcol];
            unsigned* p = &Ws[r * WS_STR + wcol];
            p[0] = f2tf(w4.x); p[1] = f2tf(w4.y); p[2] = f2tf(w4.z); p[3] = f2tf(w4.w);
        }
#pragma unroll
        for (int h = 0; h < 2; ++h) {
            const int r = xk + h * 16;
            float4 x4 = make_float4(0.f, 0.f, 0.f, 0.f);
            if (n0 + xn < Nn)
                x4 = *(const float4*)&Xb[(size_t)(kk + r) * Nn + n0 + xn];
            unsigned* p = &Xs[r * XS_STR + xn];
            p[0] = f2tf(x4.x); p[1] = f2tf(x4.y); p[2] = f2tf(x4.z); p[3] = f2tf(x4.w);
        }
        __syncthreads();

#pragma unroll
        for (int ks = 0; ks < 32; ks += 8) {
            const unsigned a0 = Ws[(wm * 16 + gr)     * WS_STR + ks + tg];
            const unsigned a1 = Ws[(wm * 16 + gr + 8) * WS_STR + ks + tg];
            const unsigned a2 = Ws[(wm * 16 + gr)     * WS_STR + ks + tg + 4];
            const unsigned a3 = Ws[(wm * 16 + gr + 8) * WS_STR + ks + tg + 4];
#pragma unroll
            for (int j = 0; j < 4; ++j) {
                const int n = wn * 32 + j * 8 + gr;
                const unsigned b0 = Xs[(ks + tg)     * XS_STR + n];
                const unsigned b1 = Xs[(ks + tg + 4) * XS_STR + n];
                mma_tf32(acc[j], a0, a1, a2, a3, b0, b1);
            }
        }
        __syncthreads();
    }

#pragma unroll
    for (int j = 0; j < 4; ++j) {
#pragma unroll
        for (int e = 0; e < 4; ++e) {
            const int row = wm * 16 + gr + ((e >> 1) ? 8 : 0);
            const int col = wn * 32 + j * 8 + tg * 2 + (e & 1);
            const int o = o0 + row, n = n0 + col;
            if (n < Nn)
                Y[((size_t)b * O + o) * Nn + n] = (acc[j][e] + bias[o]) * s[o] + t[o];
        }
    }
}

// ==========================================================================
// tf32 AV GEMM + vl + relu
// ==========================================================================
__global__ __launch_bounds__(256)
void av_mma(const float* __restrict__ Attn, const float* __restrict__ V,
            const float* __restrict__ Vl, float* __restrict__ Out)
{
    __shared__ unsigned As[64 * WS_STR];
    __shared__ unsigned Vs[64 * WS_STR];

    const int bg = blockIdx.z;
    const int b  = bg >> 3;
    const int g  = bg & 7;
    const int n0 = blockIdx.x * 64;
    const int d0 = blockIdx.y * 64;
    const int tid  = threadIdx.x;
    const int lane = tid & 31, wid = tid >> 5;
    const int wm = wid & 3, wn = wid >> 2;
    const int gr = lane >> 2, tg = lane & 3;

    const float* Ab = Attn + (size_t)bg * Nn * Nn;
    const float* Vb = V + ((size_t)b * DHd + g * Dd) * Nn;

    const int lrow = tid >> 3;
    const int lcol = (tid & 7) * 4;

    float acc[4][4];
#pragma unroll
    for (int j = 0; j < 4; ++j)
#pragma unroll
        for (int e = 0; e < 4; ++e) acc[j][e] = 0.f;

    for (int m0 = 0; m0 < Nn; m0 += 32) {
        const bool mok = (m0 + lcol) < Nn;
#pragma unroll
        for (int h = 0; h < 2; ++h) {
            const int r = lrow + h * 32;
            float4 a4 = make_float4(0.f, 0.f, 0.f, 0.f);
            if (mok && (n0 + r) < Nn)
                a4 = *(const float4*)&Ab[(size_t)(n0 + r) * Nn + m0 + lcol];
            unsigned* p = &As[r * WS_STR + lcol];
            p[0] = f2tf(a4.x); p[1] = f2tf(a4.y); p[2] = f2tf(a4.z); p[3] = f2tf(a4.w);

            float4 v4 = make_float4(0.f, 0.f, 0.f, 0.f);
            if (mok)
                v4 = *(const float4*)&Vb[(size_t)(d0 + r) * Nn + m0 + lcol];
            unsigned* q = &Vs[r * WS_STR + lcol];
            q[0] = f2tf(v4.x); q[1] = f2tf(v4.y); q[2] = f2tf(v4.z); q[3] = f2tf(v4.w);
        }
        __syncthreads();

#pragma unroll
        for (int ks = 0; ks < 32; ks += 8) {
            const unsigned a0 = As[(wm * 16 + gr)     * WS_STR + ks + tg];
            const unsigned a1 = As[(wm * 16 + gr + 8) * WS_STR + ks + tg];
            const unsigned a2 = As[(wm * 16 + gr)     * WS_STR + ks + tg + 4];
            const unsigned a3 = As[(wm * 16 + gr + 8) * WS_STR + ks + tg + 4];
#pragma unroll
            for (int j = 0; j < 4; ++j) {
                const int d = wn * 32 + j * 8 + gr;
                const unsigned b0 = Vs[d * WS_STR + ks + tg];
                const unsigned b1 = Vs[d * WS_STR + ks + tg + 4];
                mma_tf32(acc[j], a0, a1, a2, a3, b0, b1);
            }
        }
        __syncthreads();
    }

#pragma unroll
    for (int j = 0; j < 4; ++j) {
#pragma unroll
        for (int e = 0; e < 4; ++e) {
            const int n = n0 + wm * 16 + gr + ((e >> 1) ? 8 : 0);
            const int d = d0 + wn * 32 + j * 8 + tg * 2 + (e & 1);
            if (n < Nn) {
                const size_t oi = ((size_t)b * DHd + g * Dd + d) * Nn + n;
                const float v = acc[j][e] + Vl[oi];
                Out[oi] = v > 0.f ? v : 0.f;
            }
        }
    }
}

// ==========================================================================
// Depthwise 3x3 conv: one block per (b,channel); plane staged in smem
// ==========================================================================
__global__ __launch_bounds__(256)
void dwconv_kernel(const float* __restrict__ V, const float* __restrict__ Wc,
                   const float* __restrict__ bias, const float* __restrict__ s,
                   const float* __restrict__ t, float* __restrict__ Out)
{
    __shared__ float p[Nn];
    const int bc  = blockIdx.x;          // b*DHd + ch
    const int ch  = bc & (DHd - 1);
    const int tid = threadIdx.x;

    const float* vb = V + (size_t)bc * Nn;
    for (int i = tid; i < Nn; i += 256) p[i] = vb[i];

    float w[9];
#pragma unroll
    for (int j = 0; j < 9; ++j) w[j] = __ldg(&Wc[ch * 9 + j]);
    const float bi = bias[ch], si = s[ch], ti = t[ch];
    __syncthreads();

    for (int i = tid; i < Nn; i += 256) {
        const int y = i / Rr, x = i % Rr;
        float acc = 0.f;
#pragma unroll
        for (int dy = 0; dy < 3; ++dy) {
            const int yy = y + dy - 1;
            if (yy < 0 || yy >= Rr) continue;
#pragma unroll
            for (int dx = 0; dx < 3; ++dx) {
                const int xx = x + dx - 1;
                if (xx < 0 || xx >= Rr) continue;
                acc = fmaf(p[yy * Rr + xx], w[dy * 3 + dx], acc);
            }
        }
        Out[(size_t)bc * Nn + i] = (acc + bi) * si + ti;
    }
}

// ==========================================================================
// Fused attention core v3:
//   phase 1: QK^T via tf32 MMA (+ scale + arithmetic rel-pos bias from smem)
//   phase 2: register-resident mix1 -> softmax -> mix2 (per-thread all heads)
// grid: (112, B)  block 256
// ==========================================================================
__global__ __launch_bounds__(256)
void attn_kernel(const float* __restrict__ Q, const float* __restrict__ K,
                 const float* __restrict__ ab,
                 const float* __restrict__ th1w, const float* __restrict__ th1b,
                 const float* __restrict__ th2w, const float* __restrict__ th2b,
                 float* __restrict__ Attn)
{
    extern __shared__ float sm[];
    float* S    = sm;                          // TQ*8*784 floats
    float* ab_s = S + TQ * Hh * Nn;            // 8*784 floats (phase 1 only)
    float* qs   = ab_s + Hh * Nn;              // TQ*256 floats (phase 1 only)
    float* red  = qs + TQ * NHKD;              // 2*64 floats (phase 2 reductions)

    const int b   = blockIdx.y;
    const int n0  = blockIdx.x * TQ;
    const int tid = threadIdx.x;
    const int g    = tid >> 5;
    const int lane = tid & 31;
    const int gr = lane >> 2, tg = lane & 3;

    // stage ab + Q rows
    for (int e = tid; e < Hh * Nn; e += 256) ab_s[e] = ab[e];
    for (int e = tid; e < TQ * NHKD; e += 256) {
        const int nq = e >> 8, c = e & 255;
        qs[nq * NHKD + c] = Q[((size_t)b * NHKD + c) * Nn + (n0 + nq)];
    }
    __syncthreads();

    // ---------------- phase 1: MMA scores (warp g = head g) ----------------
    {
        unsigned af[4][4];
#pragma unroll
        for (int ks = 0; ks < 4; ++ks) {
            float q0 = 0.f, q2 = 0.f;
            if (gr < TQ) {
                q0 = qs[gr * NHKD + g * KDd + ks * 8 + tg];
                q2 = qs[gr * NHKD + g * KDd + ks * 8 + tg + 4];
            }
            af[ks][0] = f2tf(q0); af[ks][1] = 0u;
            af[ks][2] = f2tf(q2); af[ks][3] = 0u;
        }

        const float* Kb = K + ((size_t)b * NHKD + g * KDd) * Nn;
        const float* abg = ab_s + g * Nn;
        const int n = n0 + gr;
        const int yn = n / Rr, xn = n % Rr;
        float* Sg = S + g * Nn;

#pragma unroll 2
        for (int m0 = 0; m0 < Nn; m0 += 8) {
            unsigned bf[4][2];
#pragma unroll
            for (int ks = 0; ks < 4; ++ks) {
                bf[ks][0] = f2tf(Kb[(size_t)(ks * 8 + tg)     * Nn + m0 + gr]);
                bf[ks][1] = f2tf(Kb[(size_t)(ks * 8 + tg + 4) * Nn + m0 + gr]);
            }
            float c[4] = {0.f, 0.f, 0.f, 0.f};
#pragma unroll
            for (int ks = 0; ks < 4; ++ks)
                mma_tf32(c, af[ks][0], af[ks][1], af[ks][2], af[ks][3],
                         bf[ks][0], bf[ks][1]);
            if (gr < TQ) {
#pragma unroll
                for (int e = 0; e < 2; ++e) {
                    const int m  = m0 + tg * 2 + e;
                    const int ym = m / Rr, xm = m % Rr;
                    const int dy = yn > ym ? yn - ym : ym - yn;
                    const int dx = xn > xm ? xn - xm : xm - xn;
                    Sg[(size_t)gr * Hh * Nn + m] = c[e] * kSCALE + abg[dy * Rr + dx];
                }
            }
        }
    }
    __syncthreads();

    // ---------------- phase 2: register-resident mix/softmax/mix ----------------
    // mix weights in registers (uniform loads, L1-resident)
    float w1r[Hh][Hh], w2r[Hh][Hh], b1r[Hh], b2r[Hh];
#pragma unroll
    for (int gg = 0; gg < Hh; ++gg) {
        b1r[gg] = th1b[gg];
        b2r[gg] = th2b[gg];
#pragma unroll
        for (int h = 0; h < Hh; ++h) {
            w1r[gg][h] = th1w[gg * Hh + h];
            w2r[gg][h] = th2w[gg * Hh + h];
        }
    }

    for (int nq = 0; nq < TQ; ++nq) {
        const float* Sq = S + (size_t)nq * Hh * Nn;

        float mg[4][Hh];      // mixed scores for this thread's 4 m-columns
        float gmax[Hh];
#pragma unroll
        for (int gg = 0; gg < Hh; ++gg) gmax[gg] = -1e30f;

        // pass A: mix1, track max
#pragma unroll
        for (int mi = 0; mi < 4; ++mi) {
            const int m = tid + mi * 256;
            if (m < Nn) {
                float sv[Hh];
#pragma unroll
                for (int h = 0; h < Hh; ++h) sv[h] = Sq[h * Nn + m];
#pragma unroll
                for (int gg = 0; gg < Hh; ++gg) {
                    float a = b1r[gg];
#pragma unroll
                    for (int h = 0; h < Hh; ++h) a = fmaf(w1r[gg][h], sv[h], a);
                    mg[mi][gg] = a;
                    gmax[gg] = fmaxf(gmax[gg], a);
                }
            } else {
#pragma unroll
                for (int gg = 0; gg < Hh; ++gg) mg[mi][gg] = -1e30f;
            }
        }

        // block max reduce per g
#pragma unroll
        for (int gg = 0; gg < Hh; ++gg)
#pragma unroll
            for (int off = 16; off; off >>= 1)
                gmax[gg] = fmaxf(gmax[gg], __shfl_xor_sync(0xffffffffu, gmax[gg], off));
        if (lane == 0) {
#pragma unroll
            for (int gg = 0; gg < Hh; ++gg) red[gg * 8 + g] = gmax[gg];
        }
        __syncthreads();
        float smax[Hh];
#pragma unroll
        for (int gg = 0; gg < Hh; ++gg) {
            float v = red[gg * 8];
#pragma unroll
            for (int w = 1; w < 8; ++w) v = fmaxf(v, red[gg * 8 + w]);
            smax[gg] = v;
        }

        // pass B: exp in regs, local sums
        float gsum[Hh];
#pragma unroll
        for (int gg = 0; gg < Hh; ++gg) gsum[gg] = 0.f;
#pragma unroll
        for (int mi = 0; mi < 4; ++mi)
#pragma unroll
            for (int gg = 0; gg < Hh; ++gg) {
                const float e = __expf(mg[mi][gg] - smax[gg]);
                mg[mi][gg] = e;
                gsum[gg] += e;
            }
#pragma unroll
        for (int gg = 0; gg < Hh; ++gg)
#pragma unroll
            for (int off = 16; off; off >>= 1)
                gsum[gg] += __shfl_xor_sync(0xffffffffu, gsum[gg], off);
        if (lane == 0) {
#pragma unroll
            for (int gg = 0; gg < Hh; ++gg) red[64 + gg * 8 + g] = gsum[gg];
        }
        __syncthreads();
        float inv[Hh];
#pragma unroll
        for (int gg = 0; gg < Hh; ++gg) {
            float v = red[64 + gg * 8];
#pragma unroll
            for (int w = 1; w < 8; ++w) v += red[64 + gg * 8 + w];
            inv[gg] = 1.f / v;
        }
        __syncthreads();   // red reusable next nq

        // pass C: normalize + mix2 from registers, write global
        const size_t obase = (((size_t)b * Hh) * Nn + (n0 + nq)) * Nn;
#pragma unroll
        for (int mi = 0; mi < 4; ++mi) {
            const int m = tid + mi * 256;
            if (m < Nn) {
                float pv[Hh];
#pragma unroll
                for (int h = 0; h < Hh; ++h) pv[h] = mg[mi][h] * inv[h];
#pragma unroll
                for (int gg = 0; gg < Hh; ++gg) {
                    float a = b2r[gg];
#pragma unroll
                    for (int h = 0; h < Hh; ++h) a = fmaf(w2r[gg][h], pv[h], a);
                    Attn[obase + (size_t)gg * Nn * Nn + m] = a;
                }
            }
        }
    }
}

// ==========================================================================
// launch
// ==========================================================================
extern "C" void kernel_launch(void* const* d_in, const int* in_sizes, int n_in,
                              void* d_out, int out_size)
{
    const float* x    = (const float*)d_in[0];
    const float* Wq   = (const float*)d_in[1];
    const float* bq   = (const float*)d_in[2];
    const float* sq   = (const float*)d_in[3];
    const float* tq   = (const float*)d_in[4];
    const float* Wk   = (const float*)d_in[5];
    const float* bk   = (const float*)d_in[6];
    const float* sk   = (const float*)d_in[7];
    const float* tk   = (const float*)d_in[8];
    const float* Wv   = (const float*)d_in[9];
    const float* bv   = (const float*)d_in[10];
    const float* sv   = (const float*)d_in[11];
    const float* tv   = (const float*)d_in[12];
    const float* Wvl  = (const float*)d_in[13];
    const float* bvl  = (const float*)d_in[14];
    const float* svl  = (const float*)d_in[15];
    const float* tvl  = (const float*)d_in[16];
    const float* th1w = (const float*)d_in[17];
    const float* th1b = (const float*)d_in[18];
    const float* th2w = (const float*)d_in[19];
    const float* th2b = (const float*)d_in[20];
    const float* ab   = (const float*)d_in[21];
    const float* Wp   = (const float*)d_in[22];
    const float* bp   = (const float*)d_in[23];
    const float* sp   = (const float*)d_in[24];
    const float* tp   = (const float*)d_in[25];
    float* out = (float*)d_out;

    void *pq, *pk, *pv, *pvl, *pattn, *po;
    cudaGetSymbolAddress(&pq, g_q);
    cudaGetSymbolAddress(&pk, g_k);
    cudaGetSymbolAddress(&pv, g_vmap);
    cudaGetSymbolAddress(&pvl, g_vl);
    cudaGetSymbolAddress(&pattn, g_attn);
    cudaGetSymbolAddress(&po, g_o);
    float* q    = (float*)pq;
    float* k    = (float*)pk;
    float* vmap = (float*)pv;
    float* vl   = (float*)pvl;
    float* attn = (float*)pattn;
    float* o    = (float*)po;

    const dim3 blk(256);

    // projections (tf32 tensor cores)
    proj_mma<<<dim3(13, NHKD / 64, Bn), blk>>>(x, Wq, bq, sq, tq, q, NHKD, DIMc);
    proj_mma<<<dim3(13, NHKD / 64, Bn), blk>>>(x, Wk, bk, sk, tk, k, NHKD, DIMc);
    proj_mma<<<dim3(13, DHd  / 64, Bn), blk>>>(x, Wv, bv, sv, tv, vmap, DHd, DIMc);

    // depthwise conv branch
    dwconv_kernel<<<Bn * DHd, blk>>>(vmap, Wvl, bvl, svl, tvl, vl);

    // fused attention (MMA QK + register-resident mix/softmax)
    {
        const int smem = (TQ * Hh * Nn + Hh * Nn + TQ * NHKD + 128) * (int)sizeof(float);
        cudaFuncSetAttribute(attn_kernel, cudaFuncAttributeMaxDynamicSharedMemorySize, smem);
        attn_kernel<<<dim3(Nn / TQ, Bn), blk, smem>>>(q, k, ab, th1w, th1b,
                                                      th2w, th2b, attn);
    }

    // AV + vl + relu (tf32 tensor cores)
    av_mma<<<dim3(13, 2, Bn * Hh), blk>>>(attn, vmap, vl, o);

    // final projection (tf32 tensor cores)
    proj_mma<<<dim3(13, DIMc / 64, Bn), blk>>>(o, Wp, bp, sp, tp, out, DIMc, DHd);
}

// round 10
// speedup vs baseline: 1.8341x; 1.0469x over previous
#include <cuda_runtime.h>
#include <cuda_fp16.h>
#include <math.h>

// ---------------- problem constants ----------------
#define Bn    32
#define DIMc  384
#define Rr    28
#define Nn    784          // R*R
#define Hh    8
#define KDd   32
#define Dd    128
#define NHKD  256          // H*KD
#define DHd   1024         // H*D
#define TQ    7            // queries per attention block

__device__ __constant__ float kSCALE = 0.17677669529663687f; // 1/sqrt(32)

// ---------------- scratch ----------------
__device__ float  g_q   [(size_t)Bn * NHKD * Nn];
__device__ float  g_k   [(size_t)Bn * NHKD * Nn];
__device__ float  g_vmap[(size_t)Bn * DHd  * Nn];
__device__ __half g_vl  [(size_t)Bn * DHd  * Nn];          // fp16
__device__ __half g_attn[(size_t)Bn * Hh * Nn * Nn];       // fp16 (315 MB)
__device__ float  g_o   [(size_t)Bn * DHd  * Nn];

// ---------------- MMA helpers ----------------
__device__ __forceinline__ unsigned f2tf(float x) {
    unsigned r;
    asm("cvt.rna.tf32.f32 %0, %1;" : "=r"(r) : "f"(x));
    return r;
}

__device__ __forceinline__ void mma_tf32(float c[4],
                                         unsigned a0, unsigned a1, unsigned a2, unsigned a3,
                                         unsigned b0, unsigned b1)
{
    asm volatile("mma.sync.aligned.m16n8k8.row.col.f32.tf32.tf32.f32 "
                 "{%0,%1,%2,%3}, {%4,%5,%6,%7}, {%8,%9}, {%0,%1,%2,%3};"
                 : "+f"(c[0]), "+f"(c[1]), "+f"(c[2]), "+f"(c[3])
                 : "r"(a0), "r"(a1), "r"(a2), "r"(a3), "r"(b0), "r"(b1));
}

__device__ __forceinline__ void mma_f16(float c[4],
                                        unsigned a0, unsigned a1, unsigned a2, unsigned a3,
                                        unsigned b0, unsigned b1)
{
    asm volatile("mma.sync.aligned.m16n8k16.row.col.f32.f16.f16.f32 "
                 "{%0,%1,%2,%3}, {%4,%5,%6,%7}, {%8,%9}, {%0,%1,%2,%3};"
                 : "+f"(c[0]), "+f"(c[1]), "+f"(c[2]), "+f"(c[3])
                 : "r"(a0), "r"(a1), "r"(a2), "r"(a3), "r"(b0), "r"(b1));
}

#define WS_STR 36
#define XS_STR 72
#define AV_STR 72   // fp16 elements per smem row (64 + 8 pad)

// ==========================================================================
// tf32 pointwise-conv GEMM
// ==========================================================================
__global__ __launch_bounds__(256)
void proj_mma(const float* __restrict__ X, const float* __restrict__ W,
              const float* __restrict__ bias, const float* __restrict__ s,
              const float* __restrict__ t, float* __restrict__ Y,
              int O, int K)
{
    __shared__ unsigned Ws[64 * WS_STR];   // [o][k]
    __shared__ unsigned Xs[32 * XS_STR];   // [k][n]

    const int b  = blockIdx.z;
    const int o0 = blockIdx.y * 64;
    const int n0 = blockIdx.x * 64;
    const int tid  = threadIdx.x;
    const int lane = tid & 31, wid = tid >> 5;
    const int wm = wid & 3, wn = wid >> 2;
    const int gr = lane >> 2, tg = lane & 3;

    const float* Xb = X + (size_t)b * K * Nn;

    const int wrow = tid >> 3;
    const int wcol = (tid & 7) * 4;
    const int xk   = tid >> 4;
    const int xn   = (tid & 15) * 4;

    float acc[4][4];
#pragma unroll
    for (int j = 0; j < 4; ++j)
#pragma unroll
        for (int e = 0; e < 4; ++e) acc[j][e] = 0.f;

    for (int kk = 0; kk < K; kk += 32) {
#pragma unroll
        for (int h = 0; h < 2; ++h) {
            const int r = wrow + h * 32;
            float4 w4 = *(const float4*)&W[(size_t)(o0 + r) * K + kk + wcol];
            unsigned* p = &Ws[r * WS_STR + wcol];
            p[0] = f2tf(w4.x); p[1] = f2tf(w4.y); p[2] = f2tf(w4.z); p[3] = f2tf(w4.w);
        }
#pragma unroll
        for (int h = 0; h < 2; ++h) {
            const int r = xk + h * 16;
            float4 x4 = make_float4(0.f, 0.f, 0.f, 0.f);
            if (n0 + xn < Nn)
                x4 = *(const float4*)&Xb[(size_t)(kk + r) * Nn + n0 + xn];
            unsigned* p = &Xs[r * XS_STR + xn];
            p[0] = f2tf(x4.x); p[1] = f2tf(x4.y); p[2] = f2tf(x4.z); p[3] = f2tf(x4.w);
        }
        __syncthreads();

#pragma unroll
        for (int ks = 0; ks < 32; ks += 8) {
            const unsigned a0 = Ws[(wm * 16 + gr)     * WS_STR + ks + tg];
            const unsigned a1 = Ws[(wm * 16 + gr + 8) * WS_STR + ks + tg];
            const unsigned a2 = Ws[(wm * 16 + gr)     * WS_STR + ks + tg + 4];
            const unsigned a3 = Ws[(wm * 16 + gr + 8) * WS_STR + ks + tg + 4];
#pragma unroll
            for (int j = 0; j < 4; ++j) {
                const int n = wn * 32 + j * 8 + gr;
                const unsigned b0 = Xs[(ks + tg)     * XS_STR + n];
                const unsigned b1 = Xs[(ks + tg + 4) * XS_STR + n];
                mma_tf32(acc[j], a0, a1, a2, a3, b0, b1);
            }
        }
        __syncthreads();
    }

#pragma unroll
    for (int j = 0; j < 4; ++j) {
#pragma unroll
        for (int e = 0; e < 4; ++e) {
            const int row = wm * 16 + gr + ((e >> 1) ? 8 : 0);
            const int col = wn * 32 + j * 8 + tg * 2 + (e & 1);
            const int o = o0 + row, n = n0 + col;
            if (n < Nn)
                Y[((size_t)b * O + o) * Nn + n] = (acc[j][e] + bias[o]) * s[o] + t[o];
        }
    }
}

// ==========================================================================
// fp16 AV GEMM: O[n,d] = sum_m P[n][m] * V[d][m]; epilogue +vl(fp16), relu
// A = P (fp16) row-major; B = V (fp32 -> fp16 on stage).
// k-tile 64 (4 x m16n8k16). grid: (13, 2, B*H)  block 256
// ==========================================================================
__global__ __launch_bounds__(256)
void av_mma(const __half* __restrict__ P, const float* __restrict__ V,
            const __half* __restrict__ Vl, float* __restrict__ Out)
{
    __shared__ __half As[64 * AV_STR];   // [n][m]
    __shared__ __half Vs[64 * AV_STR];   // [d][m]

    const int bg = blockIdx.z;
    const int b  = bg >> 3;
    const int g  = bg & 7;
    const int n0 = blockIdx.x * 64;
    const int d0 = blockIdx.y * 64;
    const int tid  = threadIdx.x;
    const int lane = tid & 31, wid = tid >> 5;
    const int wm = wid & 3, wn = wid >> 2;     // wm: n group (4), wn: d group (2)
    const int gr = lane >> 2, tg = lane & 3;

    const __half* Pb = P + (size_t)bg * Nn * Nn;                 // [n][m]
    const float*  Vb = V + ((size_t)b * DHd + g * Dd) * Nn;      // [d][m]

    const int lrow = tid >> 2;          // 0..63
    const int lc16 = (tid & 3) * 16;    // 0,16,32,48

    float acc[4][4];
#pragma unroll
    for (int j = 0; j < 4; ++j)
#pragma unroll
        for (int e = 0; e < 4; ++e) acc[j][e] = 0.f;

    for (int m0 = 0; m0 < Nn; m0 += 64) {   // 13 iters, last partial (16 valid)
        // stage P tile (fp16, uint4 = 8 elems)
#pragma unroll
        for (int ch = 0; ch < 2; ++ch) {
            const int c = lc16 + ch * 8;
            uint4 v = make_uint4(0u, 0u, 0u, 0u);
            if ((n0 + lrow) < Nn && (m0 + c) < Nn)
                v = *(const uint4*)&Pb[(size_t)(n0 + lrow) * Nn + m0 + c];
            *(uint4*)&As[lrow * AV_STR + c] = v;
        }
        // stage V tile (fp32 -> fp16)
#pragma unroll
        for (int ch = 0; ch < 4; ++ch) {
            const int c = lc16 + ch * 4;
            float4 v = make_float4(0.f, 0.f, 0.f, 0.f);
            if ((m0 + c) < Nn)
                v = *(const float4*)&Vb[(size_t)(d0 + lrow) * Nn + m0 + c];
            __half2* q = (__half2*)&Vs[lrow * AV_STR + c];
            q[0] = __float22half2_rn(make_float2(v.x, v.y));
            q[1] = __float22half2_rn(make_float2(v.z, v.w));
        }
        __syncthreads();

#pragma unroll
        for (int ks = 0; ks < 4; ++ks) {
            const int ko = ks * 16;
            const unsigned a0 = *(const unsigned*)&As[(wm * 16 + gr)     * AV_STR + ko + tg * 2];
            const unsigned a1 = *(const unsigned*)&As[(wm * 16 + gr + 8) * AV_STR + ko + tg * 2];
            const unsigned a2 = *(const unsigned*)&As[(wm * 16 + gr)     * AV_STR + ko + tg * 2 + 8];
            const unsigned a3 = *(const unsigned*)&As[(wm * 16 + gr + 8) * AV_STR + ko + tg * 2 + 8];
#pragma unroll
            for (int j = 0; j < 4; ++j) {
                const int d = wn * 32 + j * 8 + gr;
                const unsigned b0 = *(const unsigned*)&Vs[d * AV_STR + ko + tg * 2];
                const unsigned b1 = *(const unsigned*)&Vs[d * AV_STR + ko + tg * 2 + 8];
                mma_f16(acc[j], a0, a1, a2, a3, b0, b1);
            }
        }
        __syncthreads();
    }

#pragma unroll
    for (int j = 0; j < 4; ++j) {
#pragma unroll
        for (int e = 0; e < 4; ++e) {
            const int n = n0 + wm * 16 + gr + ((e >> 1) ? 8 : 0);
            const int d = d0 + wn * 32 + j * 8 + tg * 2 + (e & 1);
            if (n < Nn) {
                const size_t oi = ((size_t)b * DHd + g * Dd + d) * Nn + n;
                const float v = acc[j][e] + __half2float(Vl[oi]);
                Out[oi] = v > 0.f ? v : 0.f;
            }
        }
    }
}

// ==========================================================================
// Depthwise 3x3 conv: one block per (b,channel); plane staged in smem; fp16 out
// ==========================================================================
__global__ __launch_bounds__(256)
void dwconv_kernel(const float* __restrict__ V, const float* __restrict__ Wc,
                   const float* __restrict__ bias, const float* __restrict__ s,
                   const float* __restrict__ t, __half* __restrict__ Out)
{
    __shared__ float p[Nn];
    const int bc  = blockIdx.x;          // b*DHd + ch
    const int ch  = bc & (DHd - 1);
    const int tid = threadIdx.x;

    const float* vb = V + (size_t)bc * Nn;
    for (int i = tid; i < Nn; i += 256) p[i] = vb[i];

    float w[9];
#pragma unroll
    for (int j = 0; j < 9; ++j) w[j] = __ldg(&Wc[ch * 9 + j]);
    const float bi = bias[ch], si = s[ch], ti = t[ch];
    __syncthreads();

    for (int i = tid; i < Nn; i += 256) {
        const int y = i / Rr, x = i % Rr;
        float acc = 0.f;
#pragma unroll
        for (int dy = 0; dy < 3; ++dy) {
            const int yy = y + dy - 1;
            if (yy < 0 || yy >= Rr) continue;
#pragma unroll
            for (int dx = 0; dx < 3; ++dx) {
                const int xx = x + dx - 1;
                if (xx < 0 || xx >= Rr) continue;
                acc = fmaf(p[yy * Rr + xx], w[dy * 3 + dx], acc);
            }
        }
        Out[(size_t)bc * Nn + i] = __float2half_rn((acc + bi) * si + ti);
    }
}

// ==========================================================================
// Fused attention core:
//   phase 1: QK^T via tf32 MMA (+ scale + arithmetic rel-pos bias from smem)
//   phase 2: register-resident mix1 -> softmax -> mix2 -> fp16 write
// grid: (112, B)  block 256
// ==========================================================================
__global__ __launch_bounds__(256)
void attn_kernel(const float* __restrict__ Q, const float* __restrict__ K,
                 const float* __restrict__ ab,
                 const float* __restrict__ th1w, const float* __restrict__ th1b,
                 const float* __restrict__ th2w, const float* __restrict__ th2b,
                 __half* __restrict__ Attn)
{
    extern __shared__ float sm[];
    float* S    = sm;                          // TQ*8*784 floats
    float* ab_s = S + TQ * Hh * Nn;            // 8*784 floats (phase 1 only)
    float* qs   = ab_s + Hh * Nn;              // TQ*256 floats (phase 1 only)
    float* red  = qs + TQ * NHKD;              // 128 floats (phase 2 reductions)

    const int b   = blockIdx.y;
    const int n0  = blockIdx.x * TQ;
    const int tid = threadIdx.x;
    const int g    = tid >> 5;
    const int lane = tid & 31;
    const int gr = lane >> 2, tg = lane & 3;

    // stage ab + Q rows
    for (int e = tid; e < Hh * Nn; e += 256) ab_s[e] = ab[e];
    for (int e = tid; e < TQ * NHKD; e += 256) {
        const int nq = e >> 8, c = e & 255;
        qs[nq * NHKD + c] = Q[((size_t)b * NHKD + c) * Nn + (n0 + nq)];
    }
    __syncthreads();

    // ---------------- phase 1: MMA scores (warp g = head g) ----------------
    {
        unsigned af[4][4];
#pragma unroll
        for (int ks = 0; ks < 4; ++ks) {
            float q0 = 0.f, q2 = 0.f;
            if (gr < TQ) {
                q0 = qs[gr * NHKD + g * KDd + ks * 8 + tg];
                q2 = qs[gr * NHKD + g * KDd + ks * 8 + tg + 4];
            }
            af[ks][0] = f2tf(q0); af[ks][1] = 0u;
            af[ks][2] = f2tf(q2); af[ks][3] = 0u;
        }

        const float* Kb = K + ((size_t)b * NHKD + g * KDd) * Nn;
        const float* abg = ab_s + g * Nn;
        const int n = n0 + gr;
        const int yn = n / Rr, xn = n % Rr;
        float* Sg = S + g * Nn;

#pragma unroll 2
        for (int m0 = 0; m0 < Nn; m0 += 8) {
            unsigned bf[4][2];
#pragma unroll
            for (int ks = 0; ks < 4; ++ks) {
                bf[ks][0] = f2tf(Kb[(size_t)(ks * 8 + tg)     * Nn + m0 + gr]);
                bf[ks][1] = f2tf(Kb[(size_t)(ks * 8 + tg + 4) * Nn + m0 + gr]);
            }
            float c[4] = {0.f, 0.f, 0.f, 0.f};
#pragma unroll
            for (int ks = 0; ks < 4; ++ks)
                mma_tf32(c, af[ks][0], af[ks][1], af[ks][2], af[ks][3],
                         bf[ks][0], bf[ks][1]);
            if (gr < TQ) {
#pragma unroll
                for (int e = 0; e < 2; ++e) {
                    const int m  = m0 + tg * 2 + e;
                    const int ym = m / Rr, xm = m % Rr;
                    const int dy = yn > ym ? yn - ym : ym - yn;
                    const int dx = xn > xm ? xn - xm : xm - xn;
                    Sg[(size_t)gr * Hh * Nn + m] = c[e] * kSCALE + abg[dy * Rr + dx];
                }
            }
        }
    }
    __syncthreads();

    // ---------------- phase 2: register-resident mix/softmax/mix ----------------
    float w1r[Hh][Hh], w2r[Hh][Hh], b1r[Hh], b2r[Hh];
#pragma unroll
    for (int gg = 0; gg < Hh; ++gg) {
        b1r[gg] = th1b[gg];
        b2r[gg] = th2b[gg];
#pragma unroll
        for (int h = 0; h < Hh; ++h) {
            w1r[gg][h] = th1w[gg * Hh + h];
            w2r[gg][h] = th2w[gg * Hh + h];
        }
    }

    for (int nq = 0; nq < TQ; ++nq) {
        const float* Sq = S + (size_t)nq * Hh * Nn;

        float mg[4][Hh];
        float gmax[Hh];
#pragma unroll
        for (int gg = 0; gg < Hh; ++gg) gmax[gg] = -1e30f;

        // pass A: mix1, track max
#pragma unroll
        for (int mi = 0; mi < 4; ++mi) {
            const int m = tid + mi * 256;
            if (m < Nn) {
                float sv[Hh];
#pragma unroll
                for (int h = 0; h < Hh; ++h) sv[h] = Sq[h * Nn + m];
#pragma unroll
                for (int gg = 0; gg < Hh; ++gg) {
                    float a = b1r[gg];
#pragma unroll
                    for (int h = 0; h < Hh; ++h) a = fmaf(w1r[gg][h], sv[h], a);
                    mg[mi][gg] = a;
                    gmax[gg] = fmaxf(gmax[gg], a);
                }
            } else {
#pragma unroll
                for (int gg = 0; gg < Hh; ++gg) mg[mi][gg] = -1e30f;
            }
        }

#pragma unroll
        for (int gg = 0; gg < Hh; ++gg)
#pragma unroll
            for (int off = 16; off; off >>= 1)
                gmax[gg] = fmaxf(gmax[gg], __shfl_xor_sync(0xffffffffu, gmax[gg], off));
        if (lane == 0) {
#pragma unroll
            for (int gg = 0; gg < Hh; ++gg) red[gg * 8 + g] = gmax[gg];
        }
        __syncthreads();
        float smax[Hh];
#pragma unroll
        for (int gg = 0; gg < Hh; ++gg) {
            float v = red[gg * 8];
#pragma unroll
            for (int w = 1; w < 8; ++w) v = fmaxf(v, red[gg * 8 + w]);
            smax[gg] = v;
        }

        float gsum[Hh];
#pragma unroll
        for (int gg = 0; gg < Hh; ++gg) gsum[gg] = 0.f;
#pragma unroll
        for (int mi = 0; mi < 4; ++mi)
#pragma unroll
            for (int gg = 0; gg < Hh; ++gg) {
                const float e = __expf(mg[mi][gg] - smax[gg]);
                mg[mi][gg] = e;
                gsum[gg] += e;
            }
#pragma unroll
        for (int gg = 0; gg < Hh; ++gg)
#pragma unroll
            for (int off = 16; off; off >>= 1)
                gsum[gg] += __shfl_xor_sync(0xffffffffu, gsum[gg], off);
        if (lane == 0) {
#pragma unroll
            for (int gg = 0; gg < Hh; ++gg) red[64 + gg * 8 + g] = gsum[gg];
        }
        __syncthreads();
        float inv[Hh];
#pragma unroll
        for (int gg = 0; gg < Hh; ++gg) {
            float v = red[64 + gg * 8];
#pragma unroll
            for (int w = 1; w < 8; ++w) v += red[64 + gg * 8 + w];
            inv[gg] = 1.f / v;
        }
        __syncthreads();

        // pass C: normalize + mix2, fp16 write
        const size_t obase = (((size_t)b * Hh) * Nn + (n0 + nq)) * Nn;
#pragma unroll
        for (int mi = 0; mi < 4; ++mi) {
            const int m = tid + mi * 256;
            if (m < Nn) {
                float pv[Hh];
#pragma unroll
                for (int h = 0; h < Hh; ++h) pv[h] = mg[mi][h] * inv[h];
#pragma unroll
                for (int gg = 0; gg < Hh; ++gg) {
                    float a = b2r[gg];
#pragma unroll
                    for (int h = 0; h < Hh; ++h) a = fmaf(w2r[gg][h], pv[h], a);
                    Attn[obase + (size_t)gg * Nn * Nn + m] = __float2half_rn(a);
                }
            }
        }
    }
}

// ==========================================================================
// launch
// ==========================================================================
extern "C" void kernel_launch(void* const* d_in, const int* in_sizes, int n_in,
                              void* d_out, int out_size)
{
    const float* x    = (const float*)d_in[0];
    const float* Wq   = (const float*)d_in[1];
    const float* bq   = (const float*)d_in[2];
    const float* sq   = (const float*)d_in[3];
    const float* tq   = (const float*)d_in[4];
    const float* Wk   = (const float*)d_in[5];
    const float* bk   = (const float*)d_in[6];
    const float* sk   = (const float*)d_in[7];
    const float* tk   = (const float*)d_in[8];
    const float* Wv   = (const float*)d_in[9];
    const float* bv   = (const float*)d_in[10];
    const float* sv   = (const float*)d_in[11];
    const float* tv   = (const float*)d_in[12];
    const float* Wvl  = (const float*)d_in[13];
    const float* bvl  = (const float*)d_in[14];
    const float* svl  = (const float*)d_in[15];
    const float* tvl  = (const float*)d_in[16];
    const float* th1w = (const float*)d_in[17];
    const float* th1b = (const float*)d_in[18];
    const float* th2w = (const float*)d_in[19];
    const float* th2b = (const float*)d_in[20];
    const float* ab   = (const float*)d_in[21];
    const float* Wp   = (const float*)d_in[22];
    const float* bp   = (const float*)d_in[23];
    const float* sp   = (const float*)d_in[24];
    const float* tp   = (const float*)d_in[25];
    float* out = (float*)d_out;

    void *pq, *pk, *pv, *pvl, *pattn, *po;
    cudaGetSymbolAddress(&pq, g_q);
    cudaGetSymbolAddress(&pk, g_k);
    cudaGetSymbolAddress(&pv, g_vmap);
    cudaGetSymbolAddress(&pvl, g_vl);
    cudaGetSymbolAddress(&pattn, g_attn);
    cudaGetSymbolAddress(&po, g_o);
    float*  q    = (float*)pq;
    float*  k    = (float*)pk;
    float*  vmap = (float*)pv;
    __half* vl   = (__half*)pvl;
    __half* attn = (__half*)pattn;
    float*  o    = (float*)po;

    const dim3 blk(256);

    // projections (tf32 tensor cores)
    proj_mma<<<dim3(13, NHKD / 64, Bn), blk>>>(x, Wq, bq, sq, tq, q, NHKD, DIMc);
    proj_mma<<<dim3(13, NHKD / 64, Bn), blk>>>(x, Wk, bk, sk, tk, k, NHKD, DIMc);
    proj_mma<<<dim3(13, DHd  / 64, Bn), blk>>>(x, Wv, bv, sv, tv, vmap, DHd, DIMc);

    // depthwise conv branch (fp16 out)
    dwconv_kernel<<<Bn * DHd, blk>>>(vmap, Wvl, bvl, svl, tvl, vl);

    // fused attention (MMA QK + register-resident mix/softmax, fp16 out)
    {
        const int smem = (TQ * Hh * Nn + Hh * Nn + TQ * NHKD + 128) * (int)sizeof(float);
        cudaFuncSetAttribute(attn_kernel, cudaFuncAttributeMaxDynamicSharedMemorySize, smem);
        attn_kernel<<<dim3(Nn / TQ, Bn), blk, smem>>>(q, k, ab, th1w, th1b,
                                                      th2w, th2b, attn);
    }

    // AV (fp16 tensor cores) + vl + relu
    av_mma<<<dim3(13, 2, Bn * Hh), blk>>>(attn, vmap, vl, o);

    // final projection (tf32 tensor cores)
    proj_mma<<<dim3(13, DIMc / 64, Bn), blk>>>(o, Wp, bp, sp, tp, out, DIMc, DHd);
}

// round 11
// speedup vs baseline: 1.8757x; 1.0227x over previous
#include <cuda_runtime.h>
#include <cuda_fp16.h>
#include <math.h>

// ---------------- problem constants ----------------
#define Bn    32
#define DIMc  384
#define Rr    28
#define Nn    784          // R*R
#define Hh    8
#define KDd   32
#define Dd    128
#define NHKD  256          // H*KD
#define DHd   1024         // H*D
#define TQ    7            // queries per attention block

__device__ __constant__ float kSCALE = 0.17677669529663687f; // 1/sqrt(32)

// ---------------- scratch ----------------
__device__ float  g_q   [(size_t)Bn * NHKD * Nn];
__device__ float  g_k   [(size_t)Bn * NHKD * Nn];
__device__ __half g_vmap[(size_t)Bn * DHd  * Nn];          // fp16
__device__ __half g_vl  [(size_t)Bn * DHd  * Nn];          // fp16
__device__ __half g_attn[(size_t)Bn * Hh * Nn * Nn];       // fp16 (315 MB)
__device__ __half g_o   [(size_t)Bn * DHd  * Nn];          // fp16

// ---------------- MMA helpers ----------------
__device__ __forceinline__ unsigned f2tf(float x) {
    unsigned r;
    asm("cvt.rna.tf32.f32 %0, %1;" : "=r"(r) : "f"(x));
    return r;
}

__device__ __forceinline__ void mma_tf32(float c[4],
                                         unsigned a0, unsigned a1, unsigned a2, unsigned a3,
                                         unsigned b0, unsigned b1)
{
    asm volatile("mma.sync.aligned.m16n8k8.row.col.f32.tf32.tf32.f32 "
                 "{%0,%1,%2,%3}, {%4,%5,%6,%7}, {%8,%9}, {%0,%1,%2,%3};"
                 : "+f"(c[0]), "+f"(c[1]), "+f"(c[2]), "+f"(c[3])
                 : "r"(a0), "r"(a1), "r"(a2), "r"(a3), "r"(b0), "r"(b1));
}

__device__ __forceinline__ void mma_f16(float c[4],
                                        unsigned a0, unsigned a1, unsigned a2, unsigned a3,
                                        unsigned b0, unsigned b1)
{
    asm volatile("mma.sync.aligned.m16n8k16.row.col.f32.f16.f16.f32 "
                 "{%0,%1,%2,%3}, {%4,%5,%6,%7}, {%8,%9}, {%0,%1,%2,%3};"
                 : "+f"(c[0]), "+f"(c[1]), "+f"(c[2]), "+f"(c[3])
                 : "r"(a0), "r"(a1), "r"(a2), "r"(a3), "r"(b0), "r"(b1));
}

#define WS_STR 36
#define XS_STR 72
#define AV_STR 72   // fp16 elems per smem row (64 + 8 pad); 144B row = 9x16B (uint4 ok)

// ==========================================================================
// tf32 pointwise-conv GEMM (kept for Q/K projections — pre-softmax precision)
// ==========================================================================
__global__ __launch_bounds__(256)
void proj_mma(const float* __restrict__ X, const float* __restrict__ W,
              const float* __restrict__ bias, const float* __restrict__ s,
              const float* __restrict__ t, float* __restrict__ Y,
              int O, int K)
{
    __shared__ unsigned Ws[64 * WS_STR];   // [o][k]
    __shared__ unsigned Xs[32 * XS_STR];   // [k][n]

    const int b  = blockIdx.z;
    const int o0 = blockIdx.y * 64;
    const int n0 = blockIdx.x * 64;
    const int tid  = threadIdx.x;
    const int lane = tid & 31, wid = tid >> 5;
    const int wm = wid & 3, wn = wid >> 2;
    const int gr = lane >> 2, tg = lane & 3;

    const float* Xb = X + (size_t)b * K * Nn;

    const int wrow = tid >> 3;
    const int wcol = (tid & 7) * 4;
    const int xk   = tid >> 4;
    const int xn   = (tid & 15) * 4;

    float acc[4][4];
#pragma unroll
    for (int j = 0; j < 4; ++j)
#pragma unroll
        for (int e = 0; e < 4; ++e) acc[j][e] = 0.f;

    for (int kk = 0; kk < K; kk += 32) {
#pragma unroll
        for (int h = 0; h < 2; ++h) {
            const int r = wrow + h * 32;
            float4 w4 = *(const float4*)&W[(size_t)(o0 + r) * K + kk + wcol];
            unsigned* p = &Ws[r * WS_STR + wcol];
            p[0] = f2tf(w4.x); p[1] = f2tf(w4.y); p[2] = f2tf(w4.z); p[3] = f2tf(w4.w);
        }
#pragma unroll
        for (int h = 0; h < 2; ++h) {
            const int r = xk + h * 16;
            float4 x4 = make_float4(0.f, 0.f, 0.f, 0.f);
            if (n0 + xn < Nn)
                x4 = *(const float4*)&Xb[(size_t)(kk + r) * Nn + n0 + xn];
            unsigned* p = &Xs[r * XS_STR + xn];
            p[0] = f2tf(x4.x); p[1] = f2tf(x4.y); p[2] = f2tf(x4.z); p[3] = f2tf(x4.w);
        }
        __syncthreads();

#pragma unroll
        for (int ks = 0; ks < 32; ks += 8) {
            const unsigned a0 = Ws[(wm * 16 + gr)     * WS_STR + ks + tg];
            const unsigned a1 = Ws[(wm * 16 + gr + 8) * WS_STR + ks + tg];
            const unsigned a2 = Ws[(wm * 16 + gr)     * WS_STR + ks + tg + 4];
            const unsigned a3 = Ws[(wm * 16 + gr + 8) * WS_STR + ks + tg + 4];
#pragma unroll
            for (int j = 0; j < 4; ++j) {
                const int n = wn * 32 + j * 8 + gr;
                const unsigned b0 = Xs[(ks + tg)     * XS_STR + n];
                const unsigned b1 = Xs[(ks + tg + 4) * XS_STR + n];
                mma_tf32(acc[j], a0, a1, a2, a3, b0, b1);
            }
        }
        __syncthreads();
    }

#pragma unroll
    for (int j = 0; j < 4; ++j) {
#pragma unroll
        for (int e = 0; e < 4; ++e) {
            const int row = wm * 16 + gr + ((e >> 1) ? 8 : 0);
            const int col = wn * 32 + j * 8 + tg * 2 + (e & 1);
            const int o = o0 + row, n = n0 + col;
            if (n < Nn)
                Y[((size_t)b * O + o) * Nn + n] = (acc[j][e] + bias[o]) * s[o] + t[o];
        }
    }
}

// ==========================================================================
// fp16 pointwise-conv GEMM (V proj: fp32 in/fp16 out; out proj: fp16 in/fp32 out)
// block tile 64o x 64n, k-tile 64. Ws[o][k] fp16; Xs[k][n] fp16.
// ==========================================================================
template<typename TIn, typename TOut>
__global__ __launch_bounds__(256)
void proj_f16(const TIn* __restrict__ X, const float* __restrict__ W,
              const float* __restrict__ bias, const float* __restrict__ s,
              const float* __restrict__ t, TOut* __restrict__ Y,
              int O, int K)
{
    __shared__ __half Ws[64 * AV_STR];   // [o][k]  (72-stride)
    __shared__ __half Xs[64 * AV_STR];   // [k][n]

    const int b  = blockIdx.z;
    const int o0 = blockIdx.y * 64;
    const int n0 = blockIdx.x * 64;
    const int tid  = threadIdx.x;
    const int lane = tid & 31, wid = tid >> 5;
    const int wm = wid & 3, wn = wid >> 2;
    const int gr = lane >> 2, tg = lane & 3;

    const TIn* Xb = X + (size_t)b * K * Nn;

    const int lrow = tid >> 2;          // 0..63
    const int lc16 = (tid & 3) * 16;    // 0,16,32,48

    float acc[4][4];
#pragma unroll
    for (int j = 0; j < 4; ++j)
#pragma unroll
        for (int e = 0; e < 4; ++e) acc[j][e] = 0.f;

    for (int kk = 0; kk < K; kk += 64) {
        // stage W tile (fp32 -> fp16): row lrow, k chunk lc16..+15
#pragma unroll
        for (int ch = 0; ch < 4; ++ch) {
            const int c = lc16 + ch * 4;
            float4 w4 = *(const float4*)&W[(size_t)(o0 + lrow) * K + kk + c];
            __half2* p = (__half2*)&Ws[lrow * AV_STR + c];
            p[0] = __float22half2_rn(make_float2(w4.x, w4.y));
            p[1] = __float22half2_rn(make_float2(w4.z, w4.w));
        }
        // stage X tile: k row lrow, n chunk lc16..+15
        if (sizeof(TIn) == 4) {
#pragma unroll
            for (int ch = 0; ch < 4; ++ch) {
                const int c = lc16 + ch * 4;
                float4 v = make_float4(0.f, 0.f, 0.f, 0.f);
                if (n0 + c < Nn)
                    v = *(const float4*)&((const float*)Xb)[(size_t)(kk + lrow) * Nn + n0 + c];
                __half2* p = (__half2*)&Xs[lrow * AV_STR + c];
                p[0] = __float22half2_rn(make_float2(v.x, v.y));
                p[1] = __float22half2_rn(make_float2(v.z, v.w));
            }
        } else {
#pragma unroll
            for (int ch = 0; ch < 2; ++ch) {
                const int c = lc16 + ch * 8;
                uint4 v = make_uint4(0u, 0u, 0u, 0u);
                if (n0 + c < Nn)
                    v = *(const uint4*)&((const __half*)Xb)[(size_t)(kk + lrow) * Nn + n0 + c];
                *(uint4*)&Xs[lrow * AV_STR + c] = v;
            }
        }
        __syncthreads();

#pragma unroll
        for (int ks = 0; ks < 4; ++ks) {
            const int ko = ks * 16;
            const unsigned a0 = *(const unsigned*)&Ws[(wm * 16 + gr)     * AV_STR + ko + tg * 2];
            const unsigned a1 = *(const unsigned*)&Ws[(wm * 16 + gr + 8) * AV_STR + ko + tg * 2];
            const unsigned a2 = *(const unsigned*)&Ws[(wm * 16 + gr)     * AV_STR + ko + tg * 2 + 8];
            const unsigned a3 = *(const unsigned*)&Ws[(wm * 16 + gr + 8) * AV_STR + ko + tg * 2 + 8];
#pragma unroll
            for (int j = 0; j < 4; ++j) {
                const int n = wn * 32 + j * 8 + gr;
                // B col-major fragment: consecutive k from Xs[k][n]
                __half2 p0 = __halves2half2(Xs[(ko + tg * 2    ) * AV_STR + n],
                                            Xs[(ko + tg * 2 + 1) * AV_STR + n]);
                __half2 p1 = __halves2half2(Xs[(ko + tg * 2 + 8) * AV_STR + n],
                                            Xs[(ko + tg * 2 + 9) * AV_STR + n]);
                mma_f16(acc[j], a0, a1, a2, a3,
                        *(unsigned*)&p0, *(unsigned*)&p1);
            }
        }
        __syncthreads();
    }

#pragma unroll
    for (int j = 0; j < 4; ++j) {
#pragma unroll
        for (int e = 0; e < 4; ++e) {
            const int row = wm * 16 + gr + ((e >> 1) ? 8 : 0);
            const int col = wn * 32 + j * 8 + tg * 2 + (e & 1);
            const int o = o0 + row, n = n0 + col;
            if (n < Nn) {
                const float v = (acc[j][e] + bias[o]) * s[o] + t[o];
                if (sizeof(TOut) == 2)
                    ((__half*)Y)[((size_t)b * O + o) * Nn + n] = __float2half_rn(v);
                else
                    ((float*)Y)[((size_t)b * O + o) * Nn + n] = v;
            }
        }
    }
}

// ==========================================================================
// fp16 AV GEMM: O[n,d] = sum_m P[n][m] * V[d][m]; epilogue +vl(fp16), relu, fp16 out
// ==========================================================================
__global__ __launch_bounds__(256)
void av_mma(const __half* __restrict__ P, const __half* __restrict__ V,
            const __half* __restrict__ Vl, __half* __restrict__ Out)
{
    __shared__ __half As[64 * AV_STR];   // [n][m]
    __shared__ __half Vs[64 * AV_STR];   // [d][m]

    const int bg = blockIdx.z;
    const int b  = bg >> 3;
    const int g  = bg & 7;
    const int n0 = blockIdx.x * 64;
    const int d0 = blockIdx.y * 64;
    const int tid  = threadIdx.x;
    const int lane = tid & 31, wid = tid >> 5;
    const int wm = wid & 3, wn = wid >> 2;
    const int gr = lane >> 2, tg = lane & 3;

    const __half* Pb = P + (size_t)bg * Nn * Nn;                 // [n][m]
    const __half* Vb = V + ((size_t)b * DHd + g * Dd) * Nn;      // [d][m]

    const int lrow = tid >> 2;          // 0..63
    const int lc16 = (tid & 3) * 16;    // 0,16,32,48

    float acc[4][4];
#pragma unroll
    for (int j = 0; j < 4; ++j)
#pragma unroll
        for (int e = 0; e < 4; ++e) acc[j][e] = 0.f;

    for (int m0 = 0; m0 < Nn; m0 += 64) {
#pragma unroll
        for (int ch = 0; ch < 2; ++ch) {
            const int c = lc16 + ch * 8;
            uint4 v = make_uint4(0u, 0u, 0u, 0u);
            if ((n0 + lrow) < Nn && (m0 + c) < Nn)
                v = *(const uint4*)&Pb[(size_t)(n0 + lrow) * Nn + m0 + c];
            *(uint4*)&As[lrow * AV_STR + c] = v;

            uint4 w = make_uint4(0u, 0u, 0u, 0u);
            if ((m0 + c) < Nn)
                w = *(const uint4*)&Vb[(size_t)(d0 + lrow) * Nn + m0 + c];
            *(uint4*)&Vs[lrow * AV_STR + c] = w;
        }
        __syncthreads();

#pragma unroll
        for (int ks = 0; ks < 4; ++ks) {
            const int ko = ks * 16;
            const unsigned a0 = *(const unsigned*)&As[(wm * 16 + gr)     * AV_STR + ko + tg * 2];
            const unsigned a1 = *(const unsigned*)&As[(wm * 16 + gr + 8) * AV_STR + ko + tg * 2];
            const unsigned a2 = *(const unsigned*)&As[(wm * 16 + gr)     * AV_STR + ko + tg * 2 + 8];
            const unsigned a3 = *(const unsigned*)&As[(wm * 16 + gr + 8) * AV_STR + ko + tg * 2 + 8];
#pragma unroll
            for (int j = 0; j < 4; ++j) {
                const int d = wn * 32 + j * 8 + gr;
                const unsigned b0 = *(const unsigned*)&Vs[d * AV_STR + ko + tg * 2];
                const unsigned b1 = *(const unsigned*)&Vs[d * AV_STR + ko + tg * 2 + 8];
                mma_f16(acc[j], a0, a1, a2, a3, b0, b1);
            }
        }
        __syncthreads();
    }

#pragma unroll
    for (int j = 0; j < 4; ++j) {
#pragma unroll
        for (int e = 0; e < 4; ++e) {
            const int n = n0 + wm * 16 + gr + ((e >> 1) ? 8 : 0);
            const int d = d0 + wn * 32 + j * 8 + tg * 2 + (e & 1);
            if (n < Nn) {
                const size_t oi = ((size_t)b * DHd + g * Dd + d) * Nn + n;
                const float v = acc[j][e] + __half2float(Vl[oi]);
                Out[oi] = __float2half_rn(v > 0.f ? v : 0.f);
            }
        }
    }
}

// ==========================================================================
// Depthwise 3x3 conv: fp16 in, fp32 math, fp16 out
// ==========================================================================
__global__ __launch_bounds__(256)
void dwconv_kernel(const __half* __restrict__ V, const float* __restrict__ Wc,
                   const float* __restrict__ bias, const float* __restrict__ s,
                   const float* __restrict__ t, __half* __restrict__ Out)
{
    __shared__ float p[Nn];
    const int bc  = blockIdx.x;          // b*DHd + ch
    const int ch  = bc & (DHd - 1);
    const int tid = threadIdx.x;

    const __half* vb = V + (size_t)bc * Nn;
    for (int i = tid; i < Nn; i += 256) p[i] = __half2float(vb[i]);

    float w[9];
#pragma unroll
    for (int j = 0; j < 9; ++j) w[j] = __ldg(&Wc[ch * 9 + j]);
    const float bi = bias[ch], si = s[ch], ti = t[ch];
    __syncthreads();

    for (int i = tid; i < Nn; i += 256) {
        const int y = i / Rr, x = i % Rr;
        float acc = 0.f;
#pragma unroll
        for (int dy = 0; dy < 3; ++dy) {
            const int yy = y + dy - 1;
            if (yy < 0 || yy >= Rr) continue;
#pragma unroll
            for (int dx = 0; dx < 3; ++dx) {
                const int xx = x + dx - 1;
                if (xx < 0 || xx >= Rr) continue;
                acc = fmaf(p[yy * Rr + xx], w[dy * 3 + dx], acc);
            }
        }
        Out[(size_t)bc * Nn + i] = __float2half_rn((acc + bi) * si + ti);
    }
}

// ==========================================================================
// Fused attention core:
//   phase 1: QK^T via tf32 MMA (+ scale + arithmetic rel-pos bias from smem)
//   phase 2: register-resident mix1 -> softmax -> mix2 -> fp16 write
// ==========================================================================
__global__ __launch_bounds__(256)
void attn_kernel(const float* __restrict__ Q, const float* __restrict__ K,
                 const float* __restrict__ ab,
                 const float* __restrict__ th1w, const float* __restrict__ th1b,
                 const float* __restrict__ th2w, const float* __restrict__ th2b,
                 __half* __restrict__ Attn)
{
    extern __shared__ float sm[];
    float* S    = sm;                          // TQ*8*784 floats
    float* ab_s = S + TQ * Hh * Nn;            // 8*784 floats (phase 1 only)
    float* qs   = ab_s + Hh * Nn;              // TQ*256 floats (phase 1 only)
    float* red  = qs + TQ * NHKD;              // 128 floats (phase 2 reductions)

    const int b   = blockIdx.y;
    const int n0  = blockIdx.x * TQ;
    const int tid = threadIdx.x;
    const int g    = tid >> 5;
    const int lane = tid & 31;
    const int gr = lane >> 2, tg = lane & 3;

    for (int e = tid; e < Hh * Nn; e += 256) ab_s[e] = ab[e];
    for (int e = tid; e < TQ * NHKD; e += 256) {
        const int nq = e >> 8, c = e & 255;
        qs[nq * NHKD + c] = Q[((size_t)b * NHKD + c) * Nn + (n0 + nq)];
    }
    __syncthreads();

    // ---------------- phase 1: MMA scores (warp g = head g) ----------------
    {
        unsigned af[4][4];
#pragma unroll
        for (int ks = 0; ks < 4; ++ks) {
            float q0 = 0.f, q2 = 0.f;
            if (gr < TQ) {
                q0 = qs[gr * NHKD + g * KDd + ks * 8 + tg];
                q2 = qs[gr * NHKD + g * KDd + ks * 8 + tg + 4];
            }
            af[ks][0] = f2tf(q0); af[ks][1] = 0u;
            af[ks][2] = f2tf(q2); af[ks][3] = 0u;
        }

        const float* Kb = K + ((size_t)b * NHKD + g * KDd) * Nn;
        const float* abg = ab_s + g * Nn;
        const int n = n0 + gr;
        const int yn = n / Rr, xn = n % Rr;
        float* Sg = S + g * Nn;

#pragma unroll 2
        for (int m0 = 0; m0 < Nn; m0 += 8) {
            unsigned bf[4][2];
#pragma unroll
            for (int ks = 0; ks < 4; ++ks) {
                bf[ks][0] = f2tf(Kb[(size_t)(ks * 8 + tg)     * Nn + m0 + gr]);
                bf[ks][1] = f2tf(Kb[(size_t)(ks * 8 + tg + 4) * Nn + m0 + gr]);
            }
            float c[4] = {0.f, 0.f, 0.f, 0.f};
#pragma unroll
            for (int ks = 0; ks < 4; ++ks)
                mma_tf32(c, af[ks][0], af[ks][1], af[ks][2], af[ks][3],
                         bf[ks][0], bf[ks][1]);
            if (gr < TQ) {
#pragma unroll
                for (int e = 0; e < 2; ++e) {
                    const int m  = m0 + tg * 2 + e;
                    const int ym = m / Rr, xm = m % Rr;
                    const int dy = yn > ym ? yn - ym : ym - yn;
                    const int dx = xn > xm ? xn - xm : xm - xn;
                    Sg[(size_t)gr * Hh * Nn + m] = c[e] * kSCALE + abg[dy * Rr + dx];
                }
            }
        }
    }
    __syncthreads();

    // ---------------- phase 2: register-resident mix/softmax/mix ----------------
    float w1r[Hh][Hh], w2r[Hh][Hh], b1r[Hh], b2r[Hh];
#pragma unroll
    for (int gg = 0; gg < Hh; ++gg) {
        b1r[gg] = th1b[gg];
        b2r[gg] = th2b[gg];
#pragma unroll
        for (int h = 0; h < Hh; ++h) {
            w1r[gg][h] = th1w[gg * Hh + h];
            w2r[gg][h] = th2w[gg * Hh + h];
        }
    }

    for (int nq = 0; nq < TQ; ++nq) {
        const float* Sq = S + (size_t)nq * Hh * Nn;

        float mg[4][Hh];
        float gmax[Hh];
#pragma unroll
        for (int gg = 0; gg < Hh; ++gg) gmax[gg] = -1e30f;

#pragma unroll
        for (int mi = 0; mi < 4; ++mi) {
            const int m = tid + mi * 256;
            if (m < Nn) {
                float sv[Hh];
#pragma unroll
                for (int h = 0; h < Hh; ++h) sv[h] = Sq[h * Nn + m];
#pragma unroll
                for (int gg = 0; gg < Hh; ++gg) {
                    float a = b1r[gg];
#pragma unroll
                    for (int h = 0; h < Hh; ++h) a = fmaf(w1r[gg][h], sv[h], a);
                    mg[mi][gg] = a;
                    gmax[gg] = fmaxf(gmax[gg], a);
                }
            } else {
#pragma unroll
                for (int gg = 0; gg < Hh; ++gg) mg[mi][gg] = -1e30f;
            }
        }

#pragma unroll
        for (int gg = 0; gg < Hh; ++gg)
#pragma unroll
            for (int off = 16; off; off >>= 1)
                gmax[gg] = fmaxf(gmax[gg], __shfl_xor_sync(0xffffffffu, gmax[gg], off));
        if (lane == 0) {
#pragma unroll
            for (int gg = 0; gg < Hh; ++gg) red[gg * 8 + g] = gmax[gg];
        }
        __syncthreads();
        float smax[Hh];
#pragma unroll
        for (int gg = 0; gg < Hh; ++gg) {
            float v = red[gg * 8];
#pragma unroll
            for (int w = 1; w < 8; ++w) v = fmaxf(v, red[gg * 8 + w]);
            smax[gg] = v;
        }

        float gsum[Hh];
#pragma unroll
        for (int gg = 0; gg < Hh; ++gg) gsum[gg] = 0.f;
#pragma unroll
        for (int mi = 0; mi < 4; ++mi)
#pragma unroll
            for (int gg = 0; gg < Hh; ++gg) {
                const float e = __expf(mg[mi][gg] - smax[gg]);
                mg[mi][gg] = e;
                gsum[gg] += e;
            }
#pragma unroll
        for (int gg = 0; gg < Hh; ++gg)
#pragma unroll
            for (int off = 16; off; off >>= 1)
                gsum[gg] += __shfl_xor_sync(0xffffffffu, gsum[gg], off);
        if (lane == 0) {
#pragma unroll
            for (int gg = 0; gg < Hh; ++gg) red[64 + gg * 8 + g] = gsum[gg];
        }
        __syncthreads();
        float inv[Hh];
#pragma unroll
        for (int gg = 0; gg < Hh; ++gg) {
            float v = red[64 + gg * 8];
#pragma unroll
            for (int w = 1; w < 8; ++w) v += red[64 + gg * 8 + w];
            inv[gg] = 1.f / v;
        }
        __syncthreads();

        const size_t obase = (((size_t)b * Hh) * Nn + (n0 + nq)) * Nn;
#pragma unroll
        for (int mi = 0; mi < 4; ++mi) {
            const int m = tid + mi * 256;
            if (m < Nn) {
                float pv[Hh];
#pragma unroll
                for (int h = 0; h < Hh; ++h) pv[h] = mg[mi][h] * inv[h];
#pragma unroll
                for (int gg = 0; gg < Hh; ++gg) {
                    float a = b2r[gg];
#pragma unroll
                    for (int h = 0; h < Hh; ++h) a = fmaf(w2r[gg][h], pv[h], a);
                    Attn[obase + (size_t)gg * Nn * Nn + m] = __float2half_rn(a);
                }
            }
        }
    }
}

// ==========================================================================
// launch
// ==========================================================================
extern "C" void kernel_launch(void* const* d_in, const int* in_sizes, int n_in,
                              void* d_out, int out_size)
{
    const float* x    = (const float*)d_in[0];
    const float* Wq   = (const float*)d_in[1];
    const float* bq   = (const float*)d_in[2];
    const float* sq   = (const float*)d_in[3];
    const float* tq   = (const float*)d_in[4];
    const float* Wk   = (const float*)d_in[5];
    const float* bk   = (const float*)d_in[6];
    const float* sk   = (const float*)d_in[7];
    const float* tk   = (const float*)d_in[8];
    const float* Wv   = (const float*)d_in[9];
    const float* bv   = (const float*)d_in[10];
    const float* sv   = (const float*)d_in[11];
    const float* tv   = (const float*)d_in[12];
    const float* Wvl  = (const float*)d_in[13];
    const float* bvl  = (const float*)d_in[14];
    const float* svl  = (const float*)d_in[15];
    const float* tvl  = (const float*)d_in[16];
    const float* th1w = (const float*)d_in[17];
    const float* th1b = (const float*)d_in[18];
    const float* th2w = (const float*)d_in[19];
    const float* th2b = (const float*)d_in[20];
    const float* ab   = (const float*)d_in[21];
    const float* Wp   = (const float*)d_in[22];
    const float* bp   = (const float*)d_in[23];
    const float* sp   = (const float*)d_in[24];
    const float* tp   = (const float*)d_in[25];
    float* out = (float*)d_out;

    void *pq, *pk, *pv, *pvl, *pattn, *po;
    cudaGetSymbolAddress(&pq, g_q);
    cudaGetSymbolAddress(&pk, g_k);
    cudaGetSymbolAddress(&pv, g_vmap);
    cudaGetSymbolAddress(&pvl, g_vl);
    cudaGetSymbolAddress(&pattn, g_attn);
    cudaGetSymbolAddress(&po, g_o);
    float*  q    = (float*)pq;
    float*  k    = (float*)pk;
    __half* vmap = (__half*)pv;
    __half* vl   = (__half*)pvl;
    __half* attn = (__half*)pattn;
    __half* o    = (__half*)po;

    const dim3 blk(256);

    // Q/K projections (tf32 — pre-softmax precision)
    proj_mma<<<dim3(13, NHKD / 64, Bn), blk>>>(x, Wq, bq, sq, tq, q, NHKD, DIMc);
    proj_mma<<<dim3(13, NHKD / 64, Bn), blk>>>(x, Wk, bk, sk, tk, k, NHKD, DIMc);

    // V projection (fp16 tensor cores, fp16 out)
    proj_f16<float, __half><<<dim3(13, DHd / 64, Bn), blk>>>(x, Wv, bv, sv, tv,
                                                             vmap, DHd, DIMc);

    // depthwise conv branch (fp16 in/out)
    dwconv_kernel<<<Bn * DHd, blk>>>(vmap, Wvl, bvl, svl, tvl, vl);

    // fused attention (MMA QK + register-resident mix/softmax, fp16 out)
    {
        const int smem = (TQ * Hh * Nn + Hh * Nn + TQ * NHKD + 128) * (int)sizeof(float);
        cudaFuncSetAttribute(attn_kernel, cudaFuncAttributeMaxDynamicSharedMemorySize, smem);
        attn_kernel<<<dim3(Nn / TQ, Bn), blk, smem>>>(q, k, ab, th1w, th1b,
                                                      th2w, th2b, attn);
    }

    // AV (fp16 tensor cores) + vl + relu, fp16 out
    av_mma<<<dim3(13, 2, Bn * Hh), blk>>>(attn, vmap, vl, o);

    // final projection (fp16 tensor cores, fp32 out)
    proj_f16<__half, float><<<dim3(13, DIMc / 64, Bn), blk>>>(o, Wp, bp, sp, tp,
                                                              out, DIMc, DHd);
}

// round 13
// speedup vs baseline: 1.9908x; 1.0613x over previous
#include <cuda_runtime.h>
#include <cuda_fp16.h>
#include <math.h>

// ---------------- problem constants ----------------
#define Bn    32
#define DIMc  384
#define Rr    28
#define Nn    784          // R*R
#define Hh    8
#define KDd   32
#define Dd    128
#define NHKD  256          // H*KD
#define DHd   1024         // H*D
#define TQ    7            // queries per attention block

__device__ __constant__ float kSCALE = 0.17677669529663687f; // 1/sqrt(32)

// ---------------- scratch ----------------
__device__ __half g_xh  [(size_t)Bn * DIMc * Nn];          // x in fp16
__device__ __half g_q   [(size_t)Bn * NHKD * Nn];          // fp16
__device__ __half g_k   [(size_t)Bn * NHKD * Nn];          // fp16
__device__ __half g_vmap[(size_t)Bn * DHd  * Nn];          // fp16
__device__ __half g_vl  [(size_t)Bn * DHd  * Nn];          // fp16
__device__ __half g_attn[(size_t)Bn * Hh * Nn * Nn];       // fp16 (315 MB)
__device__ __half g_o   [(size_t)Bn * DHd  * Nn];          // fp16

// ---------------- MMA helper ----------------
__device__ __forceinline__ void mma_f16(float c[4],
                                        unsigned a0, unsigned a1, unsigned a2, unsigned a3,
                                        unsigned b0, unsigned b1)
{
    asm volatile("mma.sync.aligned.m16n8k16.row.col.f32.f16.f16.f32 "
                 "{%0,%1,%2,%3}, {%4,%5,%6,%7}, {%8,%9}, {%0,%1,%2,%3};"
                 : "+f"(c[0]), "+f"(c[1]), "+f"(c[2]), "+f"(c[3])
                 : "r"(a0), "r"(a1), "r"(a2), "r"(a3), "r"(b0), "r"(b1));
}

#define GS 72   // smem row stride in halves (64 + 8 pad)

// ==========================================================================
// x -> fp16 conversion
// ==========================================================================
__global__ __launch_bounds__(256)
void x2h(const float4* __restrict__ X, __half2* __restrict__ Y, int n4)
{
    const int i = blockIdx.x * 256 + threadIdx.x;
    if (i < n4) {
        const float4 v = X[i];
        Y[2 * i]     = __float22half2_rn(make_float2(v.x, v.y));
        Y[2 * i + 1] = __float22half2_rn(make_float2(v.z, v.w));
    }
}

// ==========================================================================
// fp16 pointwise-conv GEMM, block tile 128o x 64n, k-tile 64.
// X fp16 [b][K][784]; W fp32 [O][K] (staged fp16). Y fp16 or fp32.
// grid (13, O/128, B), block 256 (8 warps: 4 o-groups x 2 n-groups)
// ==========================================================================
template<typename TOut>
__global__ __launch_bounds__(256)
void gemm_f16(const __half* __restrict__ X, const float* __restrict__ W,
              const float* __restrict__ bias, const float* __restrict__ s,
              const float* __restrict__ t, TOut* __restrict__ Y,
              int O, int K)
{
    __shared__ __half Ws[128 * GS];   // [o][k]
    __shared__ __half Xs[64 * GS];    // [k][n]

    const int b  = blockIdx.z;
    const int o0 = blockIdx.y * 128;
    const int n0 = blockIdx.x * 64;
    const int tid  = threadIdx.x;
    const int lane = tid & 31, wid = tid >> 5;
    const int wo = wid & 3, wn = wid >> 2;
    const int gr = lane >> 2, tg = lane & 3;

    const __half* Xb = X + (size_t)b * K * Nn;

    const int wr  = tid >> 1;          // 0..127 (W row)
    const int wkc = (tid & 1) * 32;    // k chunk base
    const int xr  = tid >> 2;          // 0..63  (X k-row)
    const int xc  = (tid & 3) * 16;    // n chunk base

    float acc[2][4][4];
#pragma unroll
    for (int mi = 0; mi < 2; ++mi)
#pragma unroll
        for (int j = 0; j < 4; ++j)
#pragma unroll
            for (int e = 0; e < 4; ++e) acc[mi][j][e] = 0.f;

    for (int kk = 0; kk < K; kk += 64) {
        // stage W tile 128x64 (fp32 -> fp16)
#pragma unroll
        for (int u = 0; u < 8; ++u) {
            const int c = wkc + u * 4;
            const float4 w4 = *(const float4*)&W[(size_t)(o0 + wr) * K + kk + c];
            __half2* p = (__half2*)&Ws[wr * GS + c];
            p[0] = __float22half2_rn(make_float2(w4.x, w4.y));
            p[1] = __float22half2_rn(make_float2(w4.z, w4.w));
        }
        // stage X tile 64x64 (fp16 copy, guarded per 8-half chunk)
#pragma unroll
        for (int u = 0; u < 2; ++u) {
            const int c = xc + u * 8;
            uint4 v = make_uint4(0u, 0u, 0u, 0u);
            if (n0 + c < Nn)
                v = *(const uint4*)&Xb[(size_t)(kk + xr) * Nn + n0 + c];
            *(uint4*)&Xs[xr * GS + c] = v;
        }
        __syncthreads();

#pragma unroll
        for (int ks = 0; ks < 4; ++ks) {
            const int ko = ks * 16;
            unsigned a[2][4];
#pragma unroll
            for (int mi = 0; mi < 2; ++mi) {
                const int row = wo * 32 + mi * 16 + gr;
                a[mi][0] = *(const unsigned*)&Ws[(row)     * GS + ko + tg * 2];
                a[mi][1] = *(const unsigned*)&Ws[(row + 8) * GS + ko + tg * 2];
                a[mi][2] = *(const unsigned*)&Ws[(row)     * GS + ko + tg * 2 + 8];
                a[mi][3] = *(const unsigned*)&Ws[(row + 8) * GS + ko + tg * 2 + 8];
            }
#pragma unroll
            for (int j = 0; j < 4; ++j) {
                const int n = wn * 32 + j * 8 + gr;
                const __half2 b0 = __halves2half2(Xs[(ko + tg * 2)     * GS + n],
                                                  Xs[(ko + tg * 2 + 1) * GS + n]);
                const __half2 b1 = __halves2half2(Xs[(ko + tg * 2 + 8) * GS + n],
                                                  Xs[(ko + tg * 2 + 9) * GS + n]);
#pragma unroll
                for (int mi = 0; mi < 2; ++mi)
                    mma_f16(acc[mi][j], a[mi][0], a[mi][1], a[mi][2], a[mi][3],
                            *(const unsigned*)&b0, *(const unsigned*)&b1);
            }
        }
        __syncthreads();
    }

#pragma unroll
    for (int mi = 0; mi < 2; ++mi)
#pragma unroll
        for (int j = 0; j < 4; ++j)
#pragma unroll
            for (int e = 0; e < 4; ++e) {
                const int o = o0 + wo * 32 + mi * 16 + gr + ((e >> 1) ? 8 : 0);
                const int n = n0 + wn * 32 + j * 8 + tg * 2 + (e & 1);
                if (n < Nn) {
                    const float v = (acc[mi][j][e] + bias[o]) * s[o] + t[o];
                    if (sizeof(TOut) == 2)
                        ((__half*)Y)[((size_t)b * O + o) * Nn + n] = __float2half_rn(v);
                    else
                        ((float*)Y)[((size_t)b * O + o) * Nn + n] = v;
                }
            }
}

// ==========================================================================
// fp16 AV GEMM: O[d,n] = sum_m V[d][m] * P[n][m]; epilogue +vl, relu, fp16 out
// block tile 128d x 64n, m-tile 64. grid (13, B*H), block 256.
// A = V rows (d), B = P rows (n); both m-contiguous -> direct half2 LDS frags.
// ==========================================================================
__global__ __launch_bounds__(256)
void av_mma(const __half* __restrict__ P, const __half* __restrict__ V,
            const __half* __restrict__ Vl, __half* __restrict__ Out)
{
    __shared__ __half Vs[128 * GS];   // [d][m]
    __shared__ __half Ps[64 * GS];    // [n][m]

    const int bg = blockIdx.y;
    const int b  = bg >> 3;
    const int g  = bg & 7;
    const int n0 = blockIdx.x * 64;
    const int tid  = threadIdx.x;
    const int lane = tid & 31, wid = tid >> 5;
    const int wo = wid & 3, wn = wid >> 2;     // wo: d group, wn: n group
    const int gr = lane >> 2, tg = lane & 3;

    const __half* Pb = P + (size_t)bg * Nn * Nn;                 // [n][m]
    const __half* Vb = V + ((size_t)b * DHd + g * Dd) * Nn;      // [d][m]

    const int vr = tid >> 1;           // 0..127 (V d-row)
    const int vc = (tid & 1) * 32;     // m chunk
    const int pr = tid >> 2;           // 0..63  (P n-row)
    const int pc = (tid & 3) * 16;     // m chunk

    float acc[2][4][4];
#pragma unroll
    for (int mi = 0; mi < 2; ++mi)
#pragma unroll
        for (int j = 0; j < 4; ++j)
#pragma unroll
            for (int e = 0; e < 4; ++e) acc[mi][j][e] = 0.f;

    for (int m0 = 0; m0 < Nn; m0 += 64) {   // 13 iters, last partial
#pragma unroll
        for (int u = 0; u < 4; ++u) {
            const int c = vc + u * 8;
            uint4 v = make_uint4(0u, 0u, 0u, 0u);
            if (m0 + c < Nn)
                v = *(const uint4*)&Vb[(size_t)vr * Nn + m0 + c];
            *(uint4*)&Vs[vr * GS + c] = v;
        }
#pragma unroll
        for (int u = 0; u < 2; ++u) {
            const int c = pc + u * 8;
            uint4 v = make_uint4(0u, 0u, 0u, 0u);
            if ((n0 + pr) < Nn && (m0 + c) < Nn)
                v = *(const uint4*)&Pb[(size_t)(n0 + pr) * Nn + m0 + c];
            *(uint4*)&Ps[pr * GS + c] = v;
        }
        __syncthreads();

#pragma unroll
        for (int ks = 0; ks < 4; ++ks) {
            const int ko = ks * 16;
            unsigned a[2][4];
#pragma unroll
            for (int mi = 0; mi < 2; ++mi) {
                const int row = wo * 32 + mi * 16 + gr;
                a[mi][0] = *(const unsigned*)&Vs[(row)     * GS + ko + tg * 2];
                a[mi][1] = *(const unsigned*)&Vs[(row + 8) * GS + ko + tg * 2];
                a[mi][2] = *(const unsigned*)&Vs[(row)     * GS + ko + tg * 2 + 8];
                a[mi][3] = *(const unsigned*)&Vs[(row + 8) * GS + ko + tg * 2 + 8];
            }
#pragma unroll
            for (int j = 0; j < 4; ++j) {
                const int n = wn * 32 + j * 8 + gr;
                const unsigned b0 = *(const unsigned*)&Ps[n * GS + ko + tg * 2];
                const unsigned b1 = *(const unsigned*)&Ps[n * GS + ko + tg * 2 + 8];
#pragma unroll
                for (int mi = 0; mi < 2; ++mi)
                    mma_f16(acc[mi][j], a[mi][0], a[mi][1], a[mi][2], a[mi][3], b0, b1);
            }
        }
        __syncthreads();
    }

#pragma unroll
    for (int mi = 0; mi < 2; ++mi)
#pragma unroll
        for (int j = 0; j < 4; ++j)
#pragma unroll
            for (int e = 0; e < 4; ++e) {
                const int d = wo * 32 + mi * 16 + gr + ((e >> 1) ? 8 : 0);
                const int n = n0 + wn * 32 + j * 8 + tg * 2 + (e & 1);
                if (n < Nn) {
                    const size_t oi = ((size_t)b * DHd + g * Dd + d) * Nn + n;
                    const float v = acc[mi][j][e] + __half2float(Vl[oi]);
                    Out[oi] = __float2half_rn(v > 0.f ? v : 0.f);
                }
            }
}

// ==========================================================================
// Depthwise 3x3 conv: fp16 in, fp32 math, fp16 out
// ==========================================================================
__global__ __launch_bounds__(256)
void dwconv_kernel(const __half* __restrict__ V, const float* __restrict__ Wc,
                   const float* __restrict__ bias, const float* __restrict__ s,
                   const float* __restrict__ t, __half* __restrict__ Out)
{
    __shared__ float p[Nn];
    const int bc  = blockIdx.x;          // b*DHd + ch
    const int ch  = bc & (DHd - 1);
    const int tid = threadIdx.x;

    const __half* vb = V + (size_t)bc * Nn;
    for (int i = tid; i < Nn; i += 256) p[i] = __half2float(vb[i]);

    float w[9];
#pragma unroll
    for (int j = 0; j < 9; ++j) w[j] = __ldg(&Wc[ch * 9 + j]);
    const float bi = bias[ch], si = s[ch], ti = t[ch];
    __syncthreads();

    for (int i = tid; i < Nn; i += 256) {
        const int y = i / Rr, x = i % Rr;
        float acc = 0.f;
#pragma unroll
        for (int dy = 0; dy < 3; ++dy) {
            const int yy = y + dy - 1;
            if (yy < 0 || yy >= Rr) continue;
#pragma unroll
            for (int dx = 0; dx < 3; ++dx) {
                const int xx = x + dx - 1;
                if (xx < 0 || xx >= Rr) continue;
                acc = fmaf(p[yy * Rr + xx], w[dy * 3 + dx], acc);
            }
        }
        Out[(size_t)bc * Nn + i] = __float2half_rn((acc + bi) * si + ti);
    }
}

// ==========================================================================
// Fused attention core:
//   phase 1: QK^T via fp16 MMA (+ scale + arithmetic rel-pos bias from smem)
//   phase 2: register-resident mix1 -> softmax -> mix2 -> fp16 write
// grid (112, B), block 256
// ==========================================================================
__global__ __launch_bounds__(256)
void attn_kernel(const __half* __restrict__ Q, const __half* __restrict__ K,
                 const float* __restrict__ ab,
                 const float* __restrict__ th1w, const float* __restrict__ th1b,
                 const float* __restrict__ th2w, const float* __restrict__ th2b,
                 __half* __restrict__ Attn)
{
    extern __shared__ char smraw[];
    float*  S    = (float*)smraw;              // TQ*8*784 floats
    float*  ab_s = S + TQ * Hh * Nn;           // 8*784 floats
    float*  red  = ab_s + Hh * Nn;             // 128 floats
    __half* qs   = (__half*)(red + 128);       // TQ*256 halves

    const int b   = blockIdx.y;
    const int n0  = blockIdx.x * TQ;
    const int tid = threadIdx.x;
    const int g    = tid >> 5;
    const int lane = tid & 31;
    const int gr = lane >> 2, tg = lane & 3;

    for (int e = tid; e < Hh * Nn; e += 256) ab_s[e] = ab[e];
    for (int e = tid; e < TQ * NHKD; e += 256) {
        const int nq = e >> 8, c = e & 255;
        qs[nq * NHKD + c] = Q[((size_t)b * NHKD + c) * Nn + (n0 + nq)];
    }
    __syncthreads();

    // ---------------- phase 1: fp16 MMA scores (warp g = head g) ----------------
    {
        const unsigned zu = 0u;
        unsigned af0[2], af2[2];   // rows gr (rows gr+8 are zero padding)
#pragma unroll
        for (int ks = 0; ks < 2; ++ks) {
            if (gr < TQ) {
                af0[ks] = *(const unsigned*)&qs[gr * NHKD + g * KDd + ks * 16 + tg * 2];
                af2[ks] = *(const unsigned*)&qs[gr * NHKD + g * KDd + ks * 16 + tg * 2 + 8];
            } else { af0[ks] = 0u; af2[ks] = 0u; }
        }

        const __half* Kb = K + ((size_t)b * NHKD + g * KDd) * Nn;
        const float* abg = ab_s + g * Nn;
        const int n = n0 + gr;
        const int yn = n / Rr, xn = n % Rr;
        float* Sg = S + g * Nn;

#pragma unroll 2
        for (int m0 = 0; m0 < Nn; m0 += 8) {
            const int m = m0 + gr;
            unsigned bf[2][2];
#pragma unroll
            for (int ks = 0; ks < 2; ++ks) {
                const int kb = ks * 16 + tg * 2;
                const __half2 t0 = __halves2half2(Kb[(size_t)(kb)     * Nn + m],
                                                  Kb[(size_t)(kb + 1) * Nn + m]);
                const __half2 t1 = __halves2half2(Kb[(size_t)(kb + 8) * Nn + m],
                                                  Kb[(size_t)(kb + 9) * Nn + m]);
                bf[ks][0] = *(const unsigned*)&t0;
                bf[ks][1] = *(const unsigned*)&t1;
            }
            float c[4] = {0.f, 0.f, 0.f, 0.f};
            mma_f16(c, af0[0], zu, af2[0], zu, bf[0][0], bf[0][1]);
            mma_f16(c, af0[1], zu, af2[1], zu, bf[1][0], bf[1][1]);
            if (gr < TQ) {
#pragma unroll
                for (int e = 0; e < 2; ++e) {
                    const int mm = m0 + tg * 2 + e;
                    const int ym = mm / Rr, xm = mm % Rr;
                    const int dy = yn > ym ? yn - ym : ym - yn;
                    const int dx = xn > xm ? xn - xm : xm - xn;
                    Sg[(size_t)gr * Hh * Nn + mm] = c[e] * kSCALE + abg[dy * Rr + dx];
                }
            }
        }
    }
    __syncthreads();

    // ---------------- phase 2: register-resident mix/softmax/mix ----------------
    float w1r[Hh][Hh], w2r[Hh][Hh], b1r[Hh], b2r[Hh];
#pragma unroll
    for (int gg = 0; gg < Hh; ++gg) {
        b1r[gg] = th1b[gg];
        b2r[gg] = th2b[gg];
#pragma unroll
        for (int h = 0; h < Hh; ++h) {
            w1r[gg][h] = th1w[gg * Hh + h];
            w2r[gg][h] = th2w[gg * Hh + h];
        }
    }

    for (int nq = 0; nq < TQ; ++nq) {
        const float* Sq = S + (size_t)nq * Hh * Nn;

        float mg[4][Hh];
        float gmax[Hh];
#pragma unroll
        for (int gg = 0; gg < Hh; ++gg) gmax[gg] = -1e30f;

#pragma unroll
        for (int mi = 0; mi < 4; ++mi) {
            const int m = tid + mi * 256;
            if (m < Nn) {
                float sv[Hh];
#pragma unroll
                for (int h = 0; h < Hh; ++h) sv[h] = Sq[h * Nn + m];
#pragma unroll
                for (int gg = 0; gg < Hh; ++gg) {
                    float a = b1r[gg];
#pragma unroll
                    for (int h = 0; h < Hh; ++h) a = fmaf(w1r[gg][h], sv[h], a);
                    mg[mi][gg] = a;
                    gmax[gg] = fmaxf(gmax[gg], a);
                }
            } else {
#pragma unroll
                for (int gg = 0; gg < Hh; ++gg) mg[mi][gg] = -1e30f;
            }
        }

#pragma unroll
        for (int gg = 0; gg < Hh; ++gg)
#pragma unroll
            for (int off = 16; off; off >>= 1)
                gmax[gg] = fmaxf(gmax[gg], __shfl_xor_sync(0xffffffffu, gmax[gg], off));
        if (lane == 0) {
#pragma unroll
            for (int gg = 0; gg < Hh; ++gg) red[gg * 8 + g] = gmax[gg];
        }
        __syncthreads();
        float smax[Hh];
#pragma unroll
        for (int gg = 0; gg < Hh; ++gg) {
            float v = red[gg * 8];
#pragma unroll
            for (int w = 1; w < 8; ++w) v = fmaxf(v, red[gg * 8 + w]);
            smax[gg] = v;
        }

        float gsum[Hh];
#pragma unroll
        for (int gg = 0; gg < Hh; ++gg) gsum[gg] = 0.f;
#pragma unroll
        for (int mi = 0; mi < 4; ++mi)
#pragma unroll
            for (int gg = 0; gg < Hh; ++gg) {
                const float e = __expf(mg[mi][gg] - smax[gg]);
                mg[mi][gg] = e;
                gsum[gg] += e;
            }
#pragma unroll
        for (int gg = 0; gg < Hh; ++gg)
#pragma unroll
            for (int off = 16; off; off >>= 1)
                gsum[gg] += __shfl_xor_sync(0xffffffffu, gsum[gg], off);
        if (lane == 0) {
#pragma unroll
            for (int gg = 0; gg < Hh; ++gg) red[64 + gg * 8 + g] = gsum[gg];
        }
        __syncthreads();
        float inv[Hh];
#pragma unroll
        for (int gg = 0; gg < Hh; ++gg) {
            float v = red[64 + gg * 8];
#pragma unroll
            for (int w = 1; w < 8; ++w) v += red[64 + gg * 8 + w];
            inv[gg] = 1.f / v;
        }
        __syncthreads();

        const size_t obase = (((size_t)b * Hh) * Nn + (n0 + nq)) * Nn;
#pragma unroll
        for (int mi = 0; mi < 4; ++mi) {
            const int m = tid + mi * 256;
            if (m < Nn) {
                float pv[Hh];
#pragma unroll
                for (int h = 0; h < Hh; ++h) pv[h] = mg[mi][h] * inv[h];
#pragma unroll
                for (int gg = 0; gg < Hh; ++gg) {
                    float a = b2r[gg];
#pragma unroll
                    for (int h = 0; h < Hh; ++h) a = fmaf(w2r[gg][h], pv[h], a);
                    Attn[obase + (size_t)gg * Nn * Nn + m] = __float2half_rn(a);
                }
            }
        }
    }
}

// ==========================================================================
// launch
// ==========================================================================
extern "C" void kernel_launch(void* const* d_in, const int* in_sizes, int n_in,
                              void* d_out, int out_size)
{
    const float* x    = (const float*)d_in[0];
    const float* Wq   = (const float*)d_in[1];
    const float* bq   = (const float*)d_in[2];
    const float* sq   = (const float*)d_in[3];
    const float* tq   = (const float*)d_in[4];
    const float* Wk   = (const float*)d_in[5];
    const float* bk   = (const float*)d_in[6];
    const float* sk   = (const float*)d_in[7];
    const float* tk   = (const float*)d_in[8];
    const float* Wv   = (const float*)d_in[9];
    const float* bv   = (const float*)d_in[10];
    const float* sv   = (const float*)d_in[11];
    const float* tv   = (const float*)d_in[12];
    const float* Wvl  = (const float*)d_in[13];
    const float* bvl  = (const float*)d_in[14];
    const float* svl  = (const float*)d_in[15];
    const float* tvl  = (const float*)d_in[16];
    const float* th1w = (const float*)d_in[17];
    const float* th1b = (const float*)d_in[18];
    const float* th2w = (const float*)d_in[19];
    const float* th2b = (const float*)d_in[20];
    const float* ab   = (const float*)d_in[21];
    const float* Wp   = (const float*)d_in[22];
    const float* bp   = (const float*)d_in[23];
    const float* sp   = (const float*)d_in[24];
    const float* tp   = (const float*)d_in[25];
    float* out = (float*)d_out;

    void *pxh, *pq, *pk, *pv, *pvl, *pattn, *po;
    cudaGetSymbolAddress(&pxh, g_xh);
    cudaGetSymbolAddress(&pq, g_q);
    cudaGetSymbolAddress(&pk, g_k);
    cudaGetSymbolAddress(&pv, g_vmap);
    cudaGetSymbolAddress(&pvl, g_vl);
    cudaGetSymbolAddress(&pattn, g_attn);
    cudaGetSymbolAddress(&po, g_o);
    __half* xh   = (__half*)pxh;
    __half* q    = (__half*)pq;
    __half* k    = (__half*)pk;
    __half* vmap = (__half*)pv;
    __half* vl   = (__half*)pvl;
    __half* attn = (__half*)pattn;
    __half* o    = (__half*)po;

    const dim3 blk(256);

    // x -> fp16 (once; feeds Q/K/V projections)
    {
        const int n4 = Bn * DIMc * Nn / 4;
        x2h<<<(n4 + 255) / 256, blk>>>((const float4*)x, (__half2*)xh, n4);
    }

    // projections (fp16 tensor cores, 128-wide o-tiles)
    gemm_f16<__half><<<dim3(13, NHKD / 128, Bn), blk>>>(xh, Wq, bq, sq, tq, q, NHKD, DIMc);
    gemm_f16<__half><<<dim3(13, NHKD / 128, Bn), blk>>>(xh, Wk, bk, sk, tk, k, NHKD, DIMc);
    gemm_f16<__half><<<dim3(13, DHd  / 128, Bn), blk>>>(xh, Wv, bv, sv, tv, vmap, DHd, DIMc);

    // depthwise conv branch (fp16 in/out)
    dwconv_kernel<<<Bn * DHd, blk>>>(vmap, Wvl, bvl, svl, tvl, vl);

    // fused attention (fp16 QK MMA + register-resident mix/softmax, fp16 out)
    {
        const int smem = (TQ * Hh * Nn + Hh * Nn + 128) * (int)sizeof(float)
                       + TQ * NHKD * (int)sizeof(__half);
        cudaFuncSetAttribute(attn_kernel, cudaFuncAttributeMaxDynamicSharedMemorySize, smem);
        attn_kernel<<<dim3(Nn / TQ, Bn), blk, smem>>>(q, k, ab, th1w, th1b,
                                                      th2w, th2b, attn);
    }

    // AV (fp16 tensor cores, full-D tiles) + vl + relu, fp16 out
    av_mma<<<dim3(13, Bn * Hh), blk>>>(attn, vmap, vl, o);

    // final projection (fp16 tensor cores, fp32 out)
    gemm_f16<float><<<dim3(13, DIMc / 128, Bn), blk>>>(o, Wp, bp, sp, tp, out, DIMc, DHd);
}

// round 14
// speedup vs baseline: 2.0463x; 1.0279x over previous
#include <cuda_runtime.h>
#include <cuda_fp16.h>
#include <math.h>

// ---------------- problem constants ----------------
#define Bn    32
#define DIMc  384
#define Rr    28
#define Nn    784          // R*R
#define Hh    8
#define KDd   32
#define Dd    128
#define NHKD  256          // H*KD
#define DHd   1024         // H*D
#define TQ    7            // queries per attention block

__device__ __constant__ float kSCALE = 0.17677669529663687f; // 1/sqrt(32)

// ---------------- scratch ----------------
__device__ __half g_xt  [(size_t)Bn * Nn * DIMc];          // x transposed [b][n][c] fp16
__device__ __half g_q   [(size_t)Bn * Nn * NHKD];          // Q transposed [b][n][c]
__device__ __half g_k   [(size_t)Bn * Nn * NHKD];          // K transposed [b][n][c]
__device__ __half g_vmap[(size_t)Bn * DHd * Nn];           // V [b][dh][n]
__device__ __half g_vl  [(size_t)Bn * DHd * Nn];           // vl [b][dh][n]
__device__ __half g_attn[(size_t)Bn * Hh * Nn * Nn];       // P [bg][n][m] fp16
__device__ __half g_o   [(size_t)Bn * Nn * DHd];           // o transposed [b][n][dh]

// ---------------- MMA helper ----------------
__device__ __forceinline__ void mma_f16(float c[4],
                                        unsigned a0, unsigned a1, unsigned a2, unsigned a3,
                                        unsigned b0, unsigned b1)
{
    asm volatile("mma.sync.aligned.m16n8k16.row.col.f32.f16.f16.f32 "
                 "{%0,%1,%2,%3}, {%4,%5,%6,%7}, {%8,%9}, {%0,%1,%2,%3};"
                 : "+f"(c[0]), "+f"(c[1]), "+f"(c[2]), "+f"(c[3])
                 : "r"(a0), "r"(a1), "r"(a2), "r"(a3), "r"(b0), "r"(b1));
}

#define GS 72   // smem row stride in halves (64 + 8 pad)

// ==========================================================================
// x [b][384][784] fp32  ->  x_t [b][784][384] fp16  (tile transpose)
// grid (13, 12, B)  block 256.  tile: 32 c-rows x 64 n-cols
// ==========================================================================
__global__ __launch_bounds__(256)
void xT_kernel(const float* __restrict__ X, __half* __restrict__ Y)
{
    __shared__ float tile[32][68];
    const int b  = blockIdx.z;
    const int c0 = blockIdx.y * 32;
    const int n0 = blockIdx.x * 64;
    const int tid = threadIdx.x;

    // load 32c x 64n (coalesced float4 along n)
    {
        const int row = tid >> 4;          // 0..15 (+16)
        const int col = (tid & 15) * 4;    // 0..60
#pragma unroll
        for (int h = 0; h < 2; ++h) {
            const int c = row + h * 16;
            if (n0 + col < Nn) {
                const float4 v = *(const float4*)&X[((size_t)b * DIMc + c0 + c) * Nn + n0 + col];
                tile[c][col] = v.x; tile[c][col + 1] = v.y;
                tile[c][col + 2] = v.z; tile[c][col + 3] = v.w;
            }
        }
    }
    __syncthreads();

    // store 64n x 32c (coalesced half2 along c)
    {
        const int r  = tid >> 2;           // 0..63 (n row)
        const int cc = (tid & 3) * 8;      // 0..24 (c base)
        if (n0 + r < Nn) {
            __half2* dst = (__half2*)&Y[((size_t)b * Nn + n0 + r) * DIMc + c0 + cc];
#pragma unroll
            for (int u = 0; u < 4; ++u)
                dst[u] = __float22half2_rn(make_float2(tile[cc + 2 * u][r],
                                                       tile[cc + 2 * u + 1][r]));
        }
    }
}

// ==========================================================================
// fp16 GEMM: Y[b,o,n] = ((sum_k W[o,k]*Xt[b,n,k]) + bias)*s + t
// Xt fp16 [b][784][K] (k-contiguous!), W fp32 [O][K].
// TRANS_OUT=false: Y [b][O][784];  TRANS_OUT=true: Y [b][784][O] fp16.
// block tile 128o x 64n, k-tile 64. grid (13, O/128, B), block 256.
// ==========================================================================
template<typename TOut, bool TRANS_OUT>
__global__ __launch_bounds__(256)
void gemm_f16(const __half* __restrict__ Xt, const float* __restrict__ W,
              const float* __restrict__ bias, const float* __restrict__ s,
              const float* __restrict__ t, TOut* __restrict__ Y,
              int O, int K)
{
    __shared__ __half Ws[128 * GS];   // [o][k]
    __shared__ __half Xs[64 * GS];    // [n][k]

    const int b  = blockIdx.z;
    const int o0 = blockIdx.y * 128;
    const int n0 = blockIdx.x * 64;
    const int tid  = threadIdx.x;
    const int lane = tid & 31, wid = tid >> 5;
    const int wo = wid & 3, wn = wid >> 2;
    const int gr = lane >> 2, tg = lane & 3;

    const __half* Xb = Xt + (size_t)b * Nn * K;

    const int wr  = tid >> 1;          // 0..127 (W o-row)
    const int wkc = (tid & 1) * 32;    // k chunk base
    const int xr  = tid >> 2;          // 0..63  (X n-row)
    const int xc  = (tid & 3) * 16;    // k chunk base

    float acc[2][4][4];
#pragma unroll
    for (int mi = 0; mi < 2; ++mi)
#pragma unroll
        for (int j = 0; j < 4; ++j)
#pragma unroll
            for (int e = 0; e < 4; ++e) acc[mi][j][e] = 0.f;

    const bool xrow_ok = (n0 + xr) < Nn;

    for (int kk = 0; kk < K; kk += 64) {
        // stage W tile 128x64 (fp32 -> fp16)
#pragma unroll
        for (int u = 0; u < 8; ++u) {
            const int c = wkc + u * 4;
            const float4 w4 = *(const float4*)&W[(size_t)(o0 + wr) * K + kk + c];
            __half2* p = (__half2*)&Ws[wr * GS + c];
            p[0] = __float22half2_rn(make_float2(w4.x, w4.y));
            p[1] = __float22half2_rn(make_float2(w4.z, w4.w));
        }
        // stage X tile 64n x 64k (fp16, k-contiguous, coalesced)
#pragma unroll
        for (int u = 0; u < 2; ++u) {
            const int c = xc + u * 8;
            uint4 v = make_uint4(0u, 0u, 0u, 0u);
            if (xrow_ok)
                v = *(const uint4*)&Xb[(size_t)(n0 + xr) * K + kk + c];
            *(uint4*)&Xs[xr * GS + c] = v;
        }
        __syncthreads();

#pragma unroll
        for (int ks = 0; ks < 4; ++ks) {
            const int ko = ks * 16;
            unsigned a[2][4];
#pragma unroll
            for (int mi = 0; mi < 2; ++mi) {
                const int row = wo * 32 + mi * 16 + gr;
                a[mi][0] = *(const unsigned*)&Ws[(row)     * GS + ko + tg * 2];
                a[mi][1] = *(const unsigned*)&Ws[(row + 8) * GS + ko + tg * 2];
                a[mi][2] = *(const unsigned*)&Ws[(row)     * GS + ko + tg * 2 + 8];
                a[mi][3] = *(const unsigned*)&Ws[(row + 8) * GS + ko + tg * 2 + 8];
            }
#pragma unroll
            for (int j = 0; j < 4; ++j) {
                const int n = wn * 32 + j * 8 + gr;
                const unsigned b0 = *(const unsigned*)&Xs[n * GS + ko + tg * 2];
                const unsigned b1 = *(const unsigned*)&Xs[n * GS + ko + tg * 2 + 8];
#pragma unroll
                for (int mi = 0; mi < 2; ++mi)
                    mma_f16(acc[mi][j], a[mi][0], a[mi][1], a[mi][2], a[mi][3], b0, b1);
            }
        }
        __syncthreads();
    }

#pragma unroll
    for (int mi = 0; mi < 2; ++mi)
#pragma unroll
        for (int j = 0; j < 4; ++j)
#pragma unroll
            for (int e = 0; e < 4; ++e) {
                const int o = o0 + wo * 32 + mi * 16 + gr + ((e >> 1) ? 8 : 0);
                const int n = n0 + wn * 32 + j * 8 + tg * 2 + (e & 1);
                if (n < Nn) {
                    const float v = (acc[mi][j][e] + bias[o]) * s[o] + t[o];
                    if (TRANS_OUT)
                        ((__half*)Y)[((size_t)b * Nn + n) * O + o] = __float2half_rn(v);
                    else if (sizeof(TOut) == 2)
                        ((__half*)Y)[((size_t)b * O + o) * Nn + n] = __float2half_rn(v);
                    else
                        ((float*)Y)[((size_t)b * O + o) * Nn + n] = v;
                }
            }
}

// ==========================================================================
// fp16 AV GEMM: o[d,n] = sum_m V[d][m] * P[n][m]; epilogue +vl, relu.
// writes o TRANSPOSED: o_t [b][n][dh] fp16 (feeds out-projection).
// block tile 128d x 64n, m-tile 64. grid (13, B*H), block 256.
// ==========================================================================
__global__ __launch_bounds__(256)
void av_mma(const __half* __restrict__ P, const __half* __restrict__ V,
            const __half* __restrict__ Vl, __half* __restrict__ Ot)
{
    __shared__ __half Vs[128 * GS];   // [d][m]
    __shared__ __half Ps[64 * GS];    // [n][m]

    const int bg = blockIdx.y;
    const int b  = bg >> 3;
    const int g  = bg & 7;
    const int n0 = blockIdx.x * 64;
    const int tid  = threadIdx.x;
    const int lane = tid & 31, wid = tid >> 5;
    const int wo = wid & 3, wn = wid >> 2;
    const int gr = lane >> 2, tg = lane & 3;

    const __half* Pb = P + (size_t)bg * Nn * Nn;                 // [n][m]
    const __half* Vb = V + ((size_t)b * DHd + g * Dd) * Nn;      // [d][m]

    const int vr = tid >> 1;           // 0..127
    const int vc = (tid & 1) * 32;
    const int pr = tid >> 2;           // 0..63
    const int pc = (tid & 3) * 16;

    float acc[2][4][4];
#pragma unroll
    for (int mi = 0; mi < 2; ++mi)
#pragma unroll
        for (int j = 0; j < 4; ++j)
#pragma unroll
            for (int e = 0; e < 4; ++e) acc[mi][j][e] = 0.f;

    const bool prow_ok = (n0 + pr) < Nn;

    for (int m0 = 0; m0 < Nn; m0 += 64) {
#pragma unroll
        for (int u = 0; u < 4; ++u) {
            const int c = vc + u * 8;
            uint4 v = make_uint4(0u, 0u, 0u, 0u);
            if (m0 + c < Nn)
                v = *(const uint4*)&Vb[(size_t)vr * Nn + m0 + c];
            *(uint4*)&Vs[vr * GS + c] = v;
        }
#pragma unroll
        for (int u = 0; u < 2; ++u) {
            const int c = pc + u * 8;
            uint4 v = make_uint4(0u, 0u, 0u, 0u);
            if (prow_ok && (m0 + c) < Nn)
                v = *(const uint4*)&Pb[(size_t)(n0 + pr) * Nn + m0 + c];
            *(uint4*)&Ps[pr * GS + c] = v;
        }
        __syncthreads();

#pragma unroll
        for (int ks = 0; ks < 4; ++ks) {
            const int ko = ks * 16;
            unsigned a[2][4];
#pragma unroll
            for (int mi = 0; mi < 2; ++mi) {
                const int row = wo * 32 + mi * 16 + gr;
                a[mi][0] = *(const unsigned*)&Vs[(row)     * GS + ko + tg * 2];
                a[mi][1] = *(const unsigned*)&Vs[(row + 8) * GS + ko + tg * 2];
                a[mi][2] = *(const unsigned*)&Vs[(row)     * GS + ko + tg * 2 + 8];
                a[mi][3] = *(const unsigned*)&Vs[(row + 8) * GS + ko + tg * 2 + 8];
            }
#pragma unroll
            for (int j = 0; j < 4; ++j) {
                const int n = wn * 32 + j * 8 + gr;
                const unsigned b0 = *(const unsigned*)&Ps[n * GS + ko + tg * 2];
                const unsigned b1 = *(const unsigned*)&Ps[n * GS + ko + tg * 2 + 8];
#pragma unroll
                for (int mi = 0; mi < 2; ++mi)
                    mma_f16(acc[mi][j], a[mi][0], a[mi][1], a[mi][2], a[mi][3], b0, b1);
            }
        }
        __syncthreads();
    }

#pragma unroll
    for (int mi = 0; mi < 2; ++mi)
#pragma unroll
        for (int j = 0; j < 4; ++j)
#pragma unroll
            for (int e = 0; e < 4; ++e) {
                const int d = wo * 32 + mi * 16 + gr + ((e >> 1) ? 8 : 0);
                const int n = n0 + wn * 32 + j * 8 + tg * 2 + (e & 1);
                if (n < Nn) {
                    const int ch = g * Dd + d;
                    const float v = acc[mi][j][e]
                        + __half2float(Vl[((size_t)b * DHd + ch) * Nn + n]);
                    Ot[((size_t)b * Nn + n) * DHd + ch] =
                        __float2half_rn(v > 0.f ? v : 0.f);
                }
            }
}

// ==========================================================================
// Depthwise 3x3 conv: fp16 in, fp32 math, fp16 out
// ==========================================================================
__global__ __launch_bounds__(256)
void dwconv_kernel(const __half* __restrict__ V, const float* __restrict__ Wc,
                   const float* __restrict__ bias, const float* __restrict__ s,
                   const float* __restrict__ t, __half* __restrict__ Out)
{
    __shared__ float p[Nn];
    const int bc  = blockIdx.x;          // b*DHd + ch
    const int ch  = bc & (DHd - 1);
    const int tid = threadIdx.x;

    const __half* vb = V + (size_t)bc * Nn;
    for (int i = tid; i < Nn; i += 256) p[i] = __half2float(vb[i]);

    float w[9];
#pragma unroll
    for (int j = 0; j < 9; ++j) w[j] = __ldg(&Wc[ch * 9 + j]);
    const float bi = bias[ch], si = s[ch], ti = t[ch];
    __syncthreads();

    for (int i = tid; i < Nn; i += 256) {
        const int y = i / Rr, x = i % Rr;
        float acc = 0.f;
#pragma unroll
        for (int dy = 0; dy < 3; ++dy) {
            const int yy = y + dy - 1;
            if (yy < 0 || yy >= Rr) continue;
#pragma unroll
            for (int dx = 0; dx < 3; ++dx) {
                const int xx = x + dx - 1;
                if (xx < 0 || xx >= Rr) continue;
                acc = fmaf(p[yy * Rr + xx], w[dy * 3 + dx], acc);
            }
        }
        Out[(size_t)bc * Nn + i] = __float2half_rn((acc + bi) * si + ti);
    }
}

// ==========================================================================
// Fused attention core (Q_t, K_t transposed [b][n][256]):
//   phase 1: QK^T via fp16 MMA (+ scale + arithmetic rel-pos bias)
//   phase 2: register-resident mix1 -> softmax -> mix2 -> fp16 write
// grid (112, B), block 256
// ==========================================================================
__global__ __launch_bounds__(256)
void attn_kernel(const __half* __restrict__ Qt, const __half* __restrict__ Kt,
                 const float* __restrict__ ab,
                 const float* __restrict__ th1w, const float* __restrict__ th1b,
                 const float* __restrict__ th2w, const float* __restrict__ th2b,
                 __half* __restrict__ Attn)
{
    extern __shared__ char smraw[];
    float*  S    = (float*)smraw;              // TQ*8*784 floats
    float*  ab_s = S + TQ * Hh * Nn;           // 8*784 floats
    float*  red  = ab_s + Hh * Nn;             // 128 floats
    __half* qs   = (__half*)(red + 128);       // TQ*256 halves

    const int b   = blockIdx.y;
    const int n0  = blockIdx.x * TQ;
    const int tid = threadIdx.x;
    const int g    = tid >> 5;
    const int lane = tid & 31;
    const int gr = lane >> 2, tg = lane & 3;

    for (int e = tid; e < Hh * Nn; e += 256) ab_s[e] = ab[e];
    // coalesced Q staging: rows of Q_t
    for (int e = tid; e < TQ * NHKD; e += 256) {
        const int nq = e >> 8, c = e & 255;
        qs[nq * NHKD + c] = Qt[((size_t)b * Nn + n0 + nq) * NHKD + c];
    }
    __syncthreads();

    // ---------------- phase 1: fp16 MMA scores (warp g = head g) ----------------
    {
        const unsigned zu = 0u;
        unsigned af0[2], af2[2];
#pragma unroll
        for (int ks = 0; ks < 2; ++ks) {
            if (gr < TQ) {
                af0[ks] = *(const unsigned*)&qs[gr * NHKD + g * KDd + ks * 16 + tg * 2];
                af2[ks] = *(const unsigned*)&qs[gr * NHKD + g * KDd + ks * 16 + tg * 2 + 8];
            } else { af0[ks] = 0u; af2[ks] = 0u; }
        }

        const __half* Kb = Kt + (size_t)b * Nn * NHKD + g * KDd;
        const float* abg = ab_s + g * Nn;
        const int n = n0 + gr;
        const int yn = n / Rr, xn = n % Rr;
        float* Sg = S + g * Nn;

#pragma unroll 2
        for (int m0 = 0; m0 < Nn; m0 += 8) {
            const size_t mrow = (size_t)(m0 + gr) * NHKD;
            unsigned bf[2][2];
#pragma unroll
            for (int ks = 0; ks < 2; ++ks) {
                bf[ks][0] = *(const unsigned*)&Kb[mrow + ks * 16 + tg * 2];
                bf[ks][1] = *(const unsigned*)&Kb[mrow + ks * 16 + tg * 2 + 8];
            }
            float c[4] = {0.f, 0.f, 0.f, 0.f};
            mma_f16(c, af0[0], zu, af2[0], zu, bf[0][0], bf[0][1]);
            mma_f16(c, af0[1], zu, af2[1], zu, bf[1][0], bf[1][1]);
            if (gr < TQ) {
#pragma unroll
                for (int e = 0; e < 2; ++e) {
                    const int mm = m0 + tg * 2 + e;
                    const int ym = mm / Rr, xm = mm % Rr;
                    const int dy = yn > ym ? yn - ym : ym - yn;
                    const int dx = xn > xm ? xn - xm : xm - xn;
                    Sg[(size_t)gr * Hh * Nn + mm] = c[e] * kSCALE + abg[dy * Rr + dx];
                }
            }
        }
    }
    __syncthreads();

    // ---------------- phase 2: register-resident mix/softmax/mix ----------------
    float w1r[Hh][Hh], w2r[Hh][Hh], b1r[Hh], b2r[Hh];
#pragma unroll
    for (int gg = 0; gg < Hh; ++gg) {
        b1r[gg] = th1b[gg];
        b2r[gg] = th2b[gg];
#pragma unroll
        for (int h = 0; h < Hh; ++h) {
            w1r[gg][h] = th1w[gg * Hh + h];
            w2r[gg][h] = th2w[gg * Hh + h];
        }
    }

    for (int nq = 0; nq < TQ; ++nq) {
        const float* Sq = S + (size_t)nq * Hh * Nn;

        float mg[4][Hh];
        float gmax[Hh];
#pragma unroll
        for (int gg = 0; gg < Hh; ++gg) gmax[gg] = -1e30f;

#pragma unroll
        for (int mi = 0; mi < 4; ++mi) {
            const int m = tid + mi * 256;
            if (m < Nn) {
                float sv[Hh];
#pragma unroll
                for (int h = 0; h < Hh; ++h) sv[h] = Sq[h * Nn + m];
#pragma unroll
                for (int gg = 0; gg < Hh; ++gg) {
                    float a = b1r[gg];
#pragma unroll
                    for (int h = 0; h < Hh; ++h) a = fmaf(w1r[gg][h], sv[h], a);
                    mg[mi][gg] = a;
                    gmax[gg] = fmaxf(gmax[gg], a);
                }
            } else {
#pragma unroll
                for (int gg = 0; gg < Hh; ++gg) mg[mi][gg] = -1e30f;
            }
        }

#pragma unroll
        for (int gg = 0; gg < Hh; ++gg)
#pragma unroll
            for (int off = 16; off; off >>= 1)
                gmax[gg] = fmaxf(gmax[gg], __shfl_xor_sync(0xffffffffu, gmax[gg], off));
        if (lane == 0) {
#pragma unroll
            for (int gg = 0; gg < Hh; ++gg) red[gg * 8 + g] = gmax[gg];
        }
        __syncthreads();
        float smax[Hh];
#pragma unroll
        for (int gg = 0; gg < Hh; ++gg) {
            float v = red[gg * 8];
#pragma unroll
            for (int w = 1; w < 8; ++w) v = fmaxf(v, red[gg * 8 + w]);
            smax[gg] = v;
        }

        float gsum[Hh];
#pragma unroll
        for (int gg = 0; gg < Hh; ++gg) gsum[gg] = 0.f;
#pragma unroll
        for (int mi = 0; mi < 4; ++mi)
#pragma unroll
            for (int gg = 0; gg < Hh; ++gg) {
                const float e = __expf(mg[mi][gg] - smax[gg]);
                mg[mi][gg] = e;
                gsum[gg] += e;
            }
#pragma unroll
        for (int gg = 0; gg < Hh; ++gg)
#pragma unroll
            for (int off = 16; off; off >>= 1)
                gsum[gg] += __shfl_xor_sync(0xffffffffu, gsum[gg], off);
        if (lane == 0) {
#pragma unroll
            for (int gg = 0; gg < Hh; ++gg) red[64 + gg * 8 + g] = gsum[gg];
        }
        __syncthreads();
        float inv[Hh];
#pragma unroll
        for (int gg = 0; gg < Hh; ++gg) {
            float v = red[64 + gg * 8];
#pragma unroll
            for (int w = 1; w < 8; ++w) v += red[64 + gg * 8 + w];
            inv[gg] = 1.f / v;
        }
        __syncthreads();

        const size_t obase = (((size_t)b * Hh) * Nn + (n0 + nq)) * Nn;
#pragma unroll
        for (int mi = 0; mi < 4; ++mi) {
            const int m = tid + mi * 256;
            if (m < Nn) {
                float pv[Hh];
#pragma unroll
                for (int h = 0; h < Hh; ++h) pv[h] = mg[mi][h] * inv[h];
#pragma unroll
                for (int gg = 0; gg < Hh; ++gg) {
                    float a = b2r[gg];
#pragma unroll
                    for (int h = 0; h < Hh; ++h) a = fmaf(w2r[gg][h], pv[h], a);
                    Attn[obase + (size_t)gg * Nn * Nn + m] = __float2half_rn(a);
                }
            }
        }
    }
}

// ==========================================================================
// launch
// ==========================================================================
extern "C" void kernel_launch(void* const* d_in, const int* in_sizes, int n_in,
                              void* d_out, int out_size)
{
    const float* x    = (const float*)d_in[0];
    const float* Wq   = (const float*)d_in[1];
    const float* bq   = (const float*)d_in[2];
    const float* sq   = (const float*)d_in[3];
    const float* tq   = (const float*)d_in[4];
    const float* Wk   = (const float*)d_in[5];
    const float* bk   = (const float*)d_in[6];
    const float* sk   = (const float*)d_in[7];
    const float* tk   = (const float*)d_in[8];
    const float* Wv   = (const float*)d_in[9];
    const float* bv   = (const float*)d_in[10];
    const float* sv   = (const float*)d_in[11];
    const float* tv   = (const float*)d_in[12];
    const float* Wvl  = (const float*)d_in[13];
    const float* bvl  = (const float*)d_in[14];
    const float* svl  = (const float*)d_in[15];
    const float* tvl  = (const float*)d_in[16];
    const float* th1w = (const float*)d_in[17];
    const float* th1b = (const float*)d_in[18];
    const float* th2w = (const float*)d_in[19];
    const float* th2b = (const float*)d_in[20];
    const float* ab   = (const float*)d_in[21];
    const float* Wp   = (const float*)d_in[22];
    const float* bp   = (const float*)d_in[23];
    const float* sp   = (const float*)d_in[24];
    const float* tp   = (const float*)d_in[25];
    float* out = (float*)d_out;

    void *pxt, *pq, *pk, *pv, *pvl, *pattn, *po;
    cudaGetSymbolAddress(&pxt, g_xt);
    cudaGetSymbolAddress(&pq, g_q);
    cudaGetSymbolAddress(&pk, g_k);
    cudaGetSymbolAddress(&pv, g_vmap);
    cudaGetSymbolAddress(&pvl, g_vl);
    cudaGetSymbolAddress(&pattn, g_attn);
    cudaGetSymbolAddress(&po, g_o);
    __half* xt   = (__half*)pxt;
    __half* q    = (__half*)pq;
    __half* k    = (__half*)pk;
    __half* vmap = (__half*)pv;
    __half* vl   = (__half*)pvl;
    __half* attn = (__half*)pattn;
    __half* o    = (__half*)po;

    const dim3 blk(256);

    // x -> transposed fp16 [b][n][c]
    xT_kernel<<<dim3(13, DIMc / 32, Bn), blk>>>(x, xt);

    // projections: Q,K transposed out [b][n][256]; V normal [b][dh][n]
    gemm_f16<__half, true ><<<dim3(13, NHKD / 128, Bn), blk>>>(xt, Wq, bq, sq, tq, q, NHKD, DIMc);
    gemm_f16<__half, true ><<<dim3(13, NHKD / 128, Bn), blk>>>(xt, Wk, bk, sk, tk, k, NHKD, DIMc);
    gemm_f16<__half, false><<<dim3(13, DHd  / 128, Bn), blk>>>(xt, Wv, bv, sv, tv, vmap, DHd, DIMc);

    // depthwise conv branch
    dwconv_kernel<<<Bn * DHd, blk>>>(vmap, Wvl, bvl, svl, tvl, vl);

    // fused attention
    {
        const int smem = (TQ * Hh * Nn + Hh * Nn + 128) * (int)sizeof(float)
                       + TQ * NHKD * (int)sizeof(__half);
        cudaFuncSetAttribute(attn_kernel, cudaFuncAttributeMaxDynamicSharedMemorySize, smem);
        attn_kernel<<<dim3(Nn / TQ, Bn), blk, smem>>>(q, k, ab, th1w, th1b,
                                                      th2w, th2b, attn);
    }

    // AV + vl + relu, writes o_t [b][n][dh]
    av_mma<<<dim3(13, Bn * Hh), blk>>>(attn, vmap, vl, o);

    // final projection from o_t
    gemm_f16<float, false><<<dim3(13, DIMc / 128, Bn), blk>>>(o, Wp, bp, sp, tp, out, DIMc, DHd);
}

// round 15
// speedup vs baseline: 2.3405x; 1.1438x over previous
#include <cuda_runtime.h>
#include <cuda_fp16.h>
#include <math.h>

// ---------------- problem constants ----------------
#define Bn    32
#define DIMc  384
#define Rr    28
#define Nn    784          // R*R
#define Hh    8
#define KDd   32
#define Dd    128
#define NHKD  256          // H*KD
#define DHd   1024         // H*D
#define TQ    7            // queries per attention block

__device__ __constant__ float kSCALE = 0.17677669529663687f; // 1/sqrt(32)

// ---------------- scratch ----------------
__device__ __half g_xt  [(size_t)Bn * Nn * DIMc];          // x transposed [b][n][c] fp16
__device__ __half g_q   [(size_t)Bn * Nn * NHKD];          // Q transposed [b][n][c]
__device__ __half g_k   [(size_t)Bn * Nn * NHKD];          // K transposed [b][n][c]
__device__ __half g_vmap[(size_t)Bn * DHd * Nn];           // V [b][dh][n]
__device__ __half g_vl  [(size_t)Bn * DHd * Nn];           // vl [b][dh][n]
__device__ __half g_attn[(size_t)Bn * Hh * Nn * Nn];       // P [bg][n][m] fp16
__device__ __half g_o   [(size_t)Bn * Nn * DHd];           // o transposed [b][n][dh]
// fp16 weights (converted once per launch)
__device__ __half g_wq  [NHKD * DIMc];
__device__ __half g_wk  [NHKD * DIMc];
__device__ __half g_wv  [DHd  * DIMc];
__device__ __half g_wp  [DIMc * DHd];

// ---------------- MMA helper ----------------
__device__ __forceinline__ void mma_f16(float c[4],
                                        unsigned a0, unsigned a1, unsigned a2, unsigned a3,
                                        unsigned b0, unsigned b1)
{
    asm volatile("mma.sync.aligned.m16n8k16.row.col.f32.f16.f16.f32 "
                 "{%0,%1,%2,%3}, {%4,%5,%6,%7}, {%8,%9}, {%0,%1,%2,%3};"
                 : "+f"(c[0]), "+f"(c[1]), "+f"(c[2]), "+f"(c[3])
                 : "r"(a0), "r"(a1), "r"(a2), "r"(a3), "r"(b0), "r"(b1));
}

#define GS 72   // smem row stride in halves (64 + 8 pad)

// ==========================================================================
// weights fp32 -> fp16 (once per launch)
// ==========================================================================
__global__ __launch_bounds__(256)
void w2h(const float4* __restrict__ W, __half2* __restrict__ Y, int n4)
{
    const int i = blockIdx.x * 256 + threadIdx.x;
    if (i < n4) {
        const float4 v = W[i];
        Y[2 * i]     = __float22half2_rn(make_float2(v.x, v.y));
        Y[2 * i + 1] = __float22half2_rn(make_float2(v.z, v.w));
    }
}

// ==========================================================================
// x [b][384][784] fp32  ->  x_t [b][784][384] fp16  (tile transpose)
// ==========================================================================
__global__ __launch_bounds__(256)
void xT_kernel(const float* __restrict__ X, __half* __restrict__ Y)
{
    __shared__ float tile[32][68];
    const int b  = blockIdx.z;
    const int c0 = blockIdx.y * 32;
    const int n0 = blockIdx.x * 64;
    const int tid = threadIdx.x;

    {
        const int row = tid >> 4;
        const int col = (tid & 15) * 4;
#pragma unroll
        for (int h = 0; h < 2; ++h) {
            const int c = row + h * 16;
            if (n0 + col < Nn) {
                const float4 v = *(const float4*)&X[((size_t)b * DIMc + c0 + c) * Nn + n0 + col];
                tile[c][col] = v.x; tile[c][col + 1] = v.y;
                tile[c][col + 2] = v.z; tile[c][col + 3] = v.w;
            }
        }
    }
    __syncthreads();

    {
        const int r  = tid >> 2;
        const int cc = (tid & 3) * 8;
        if (n0 + r < Nn) {
            __half2* dst = (__half2*)&Y[((size_t)b * Nn + n0 + r) * DIMc + c0 + cc];
#pragma unroll
            for (int u = 0; u < 4; ++u)
                dst[u] = __float22half2_rn(make_float2(tile[cc + 2 * u][r],
                                                       tile[cc + 2 * u + 1][r]));
        }
    }
}

// ==========================================================================
// fp16 GEMM v2: block tile 128o x 128n, k-tile 64. warp tile 64o x 32n.
// Xt fp16 [b][784][K] (k-contiguous), Wh fp16 [O][K].
// grid (7, O/128, B), block 256 (8 warps: 2 o-halves x 4 n-quarters)
// ==========================================================================
template<typename TOut, bool TRANS_OUT>
__global__ __launch_bounds__(256)
void gemm_f16(const __half* __restrict__ Xt, const __half* __restrict__ Wh,
              const float* __restrict__ bias, const float* __restrict__ s,
              const float* __restrict__ t, TOut* __restrict__ Y,
              int O, int K)
{
    __shared__ __half Ws[128 * GS];   // [o][k]
    __shared__ __half Xs[128 * GS];   // [n][k]

    const int b  = blockIdx.z;
    const int o0 = blockIdx.y * 128;
    const int n0 = blockIdx.x * 128;
    const int tid  = threadIdx.x;
    const int lane = tid & 31, wid = tid >> 5;
    const int wo = wid & 1, wn = wid >> 1;     // wo: o half (64), wn: n quarter (32)
    const int gr = lane >> 2, tg = lane & 3;

    const __half* Xb = Xt + (size_t)b * Nn * K;

    const int sr = tid >> 1;           // 0..127 (staging row)
    const int sc = (tid & 1) * 32;     // k chunk base (32 halves = 4 uint4)

    float acc[4][4][4];
#pragma unroll
    for (int mi = 0; mi < 4; ++mi)
#pragma unroll
        for (int j = 0; j < 4; ++j)
#pragma unroll
            for (int e = 0; e < 4; ++e) acc[mi][j][e] = 0.f;

    const bool xrow_ok = (n0 + sr) < Nn;

    for (int kk = 0; kk < K; kk += 64) {
        // stage W tile 128x64 (fp16 uint4 copies)
        {
            const __half* src = &Wh[(size_t)(o0 + sr) * K + kk + sc];
            __half* dst = &Ws[sr * GS + sc];
#pragma unroll
            for (int u = 0; u < 4; ++u)
                *(uint4*)(dst + u * 8) = *(const uint4*)(src + u * 8);
        }
        // stage X tile 128n x 64k
        {
            const __half* src = &Xb[(size_t)(n0 + sr) * K + kk + sc];
            __half* dst = &Xs[sr * GS + sc];
#pragma unroll
            for (int u = 0; u < 4; ++u) {
                uint4 v = make_uint4(0u, 0u, 0u, 0u);
                if (xrow_ok) v = *(const uint4*)(src + u * 8);
                *(uint4*)(dst + u * 8) = v;
            }
        }
        __syncthreads();

#pragma unroll
        for (int ks = 0; ks < 4; ++ks) {
            const int ko = ks * 16;
            unsigned a[4][4];
#pragma unroll
            for (int mi = 0; mi < 4; ++mi) {
                const int row = wo * 64 + mi * 16 + gr;
                a[mi][0] = *(const unsigned*)&Ws[(row)     * GS + ko + tg * 2];
                a[mi][1] = *(const unsigned*)&Ws[(row + 8) * GS + ko + tg * 2];
                a[mi][2] = *(const unsigned*)&Ws[(row)     * GS + ko + tg * 2 + 8];
                a[mi][3] = *(const unsigned*)&Ws[(row + 8) * GS + ko + tg * 2 + 8];
            }
            unsigned bb[4][2];
#pragma unroll
            for (int j = 0; j < 4; ++j) {
                const int n = wn * 32 + j * 8 + gr;
                bb[j][0] = *(const unsigned*)&Xs[n * GS + ko + tg * 2];
                bb[j][1] = *(const unsigned*)&Xs[n * GS + ko + tg * 2 + 8];
            }
#pragma unroll
            for (int mi = 0; mi < 4; ++mi)
#pragma unroll
                for (int j = 0; j < 4; ++j)
                    mma_f16(acc[mi][j], a[mi][0], a[mi][1], a[mi][2], a[mi][3],
                            bb[j][0], bb[j][1]);
        }
        __syncthreads();
    }

#pragma unroll
    for (int mi = 0; mi < 4; ++mi)
#pragma unroll
        for (int j = 0; j < 4; ++j)
#pragma unroll
            for (int e = 0; e < 4; ++e) {
                const int o = o0 + wo * 64 + mi * 16 + gr + ((e >> 1) ? 8 : 0);
                const int n = n0 + wn * 32 + j * 8 + tg * 2 + (e & 1);
                if (n < Nn) {
                    const float v = (acc[mi][j][e] + bias[o]) * s[o] + t[o];
                    if (TRANS_OUT)
                        ((__half*)Y)[((size_t)b * Nn + n) * O + o] = __float2half_rn(v);
                    else if (sizeof(TOut) == 2)
                        ((__half*)Y)[((size_t)b * O + o) * Nn + n] = __float2half_rn(v);
                    else
                        ((float*)Y)[((size_t)b * O + o) * Nn + n] = v;
                }
            }
}

// ==========================================================================
// fp16 AV GEMM: o[d,n] = sum_m V[d][m] * P[n][m]; epilogue +vl, relu.
// writes o TRANSPOSED: o_t [b][n][dh]. block 128d x 64n, m-tile 64.
// ==========================================================================
__global__ __launch_bounds__(256)
void av_mma(const __half* __restrict__ P, const __half* __restrict__ V,
            const __half* __restrict__ Vl, __half* __restrict__ Ot)
{
    __shared__ __half Vs[128 * GS];   // [d][m]
    __shared__ __half Ps[64 * GS];    // [n][m]

    const int bg = blockIdx.y;
    const int b  = bg >> 3;
    const int g  = bg & 7;
    const int n0 = blockIdx.x * 64;
    const int tid  = threadIdx.x;
    const int lane = tid & 31, wid = tid >> 5;
    const int wo = wid & 3, wn = wid >> 2;
    const int gr = lane >> 2, tg = lane & 3;

    const __half* Pb = P + (size_t)bg * Nn * Nn;
    const __half* Vb = V + ((size_t)b * DHd + g * Dd) * Nn;

    const int vr = tid >> 1;
    const int vc = (tid & 1) * 32;
    const int pr = tid >> 2;
    const int pc = (tid & 3) * 16;

    float acc[2][4][4];
#pragma unroll
    for (int mi = 0; mi < 2; ++mi)
#pragma unroll
        for (int j = 0; j < 4; ++j)
#pragma unroll
            for (int e = 0; e < 4; ++e) acc[mi][j][e] = 0.f;

    const bool prow_ok = (n0 + pr) < Nn;

    for (int m0 = 0; m0 < Nn; m0 += 64) {
#pragma unroll
        for (int u = 0; u < 4; ++u) {
            const int c = vc + u * 8;
            uint4 v = make_uint4(0u, 0u, 0u, 0u);
            if (m0 + c < Nn)
                v = *(const uint4*)&Vb[(size_t)vr * Nn + m0 + c];
            *(uint4*)&Vs[vr * GS + c] = v;
        }
#pragma unroll
        for (int u = 0; u < 2; ++u) {
            const int c = pc + u * 8;
            uint4 v = make_uint4(0u, 0u, 0u, 0u);
            if (prow_ok && (m0 + c) < Nn)
                v = *(const uint4*)&Pb[(size_t)(n0 + pr) * Nn + m0 + c];
            *(uint4*)&Ps[pr * GS + c] = v;
        }
        __syncthreads();

#pragma unroll
        for (int ks = 0; ks < 4; ++ks) {
            const int ko = ks * 16;
            unsigned a[2][4];
#pragma unroll
            for (int mi = 0; mi < 2; ++mi) {
                const int row = wo * 32 + mi * 16 + gr;
                a[mi][0] = *(const unsigned*)&Vs[(row)     * GS + ko + tg * 2];
                a[mi][1] = *(const unsigned*)&Vs[(row + 8) * GS + ko + tg * 2];
                a[mi][2] = *(const unsigned*)&Vs[(row)     * GS + ko + tg * 2 + 8];
                a[mi][3] = *(const unsigned*)&Vs[(row + 8) * GS + ko + tg * 2 + 8];
            }
#pragma unroll
            for (int j = 0; j < 4; ++j) {
                const int n = wn * 32 + j * 8 + gr;
                const unsigned b0 = *(const unsigned*)&Ps[n * GS + ko + tg * 2];
                const unsigned b1 = *(const unsigned*)&Ps[n * GS + ko + tg * 2 + 8];
#pragma unroll
                for (int mi = 0; mi < 2; ++mi)
                    mma_f16(acc[mi][j], a[mi][0], a[mi][1], a[mi][2], a[mi][3], b0, b1);
            }
        }
        __syncthreads();
    }

#pragma unroll
    for (int mi = 0; mi < 2; ++mi)
#pragma unroll
        for (int j = 0; j < 4; ++j)
#pragma unroll
            for (int e = 0; e < 4; ++e) {
                const int d = wo * 32 + mi * 16 + gr + ((e >> 1) ? 8 : 0);
                const int n = n0 + wn * 32 + j * 8 + tg * 2 + (e & 1);
                if (n < Nn) {
                    const int ch = g * Dd + d;
                    const float v = acc[mi][j][e]
                        + __half2float(Vl[((size_t)b * DHd + ch) * Nn + n]);
                    Ot[((size_t)b * Nn + n) * DHd + ch] =
                        __float2half_rn(v > 0.f ? v : 0.f);
                }
            }
}

// ==========================================================================
// Depthwise 3x3 conv: fp16 in, fp32 math, fp16 out
// ==========================================================================
__global__ __launch_bounds__(256)
void dwconv_kernel(const __half* __restrict__ V, const float* __restrict__ Wc,
                   const float* __restrict__ bias, const float* __restrict__ s,
                   const float* __restrict__ t, __half* __restrict__ Out)
{
    __shared__ float p[Nn];
    const int bc  = blockIdx.x;
    const int ch  = bc & (DHd - 1);
    const int tid = threadIdx.x;

    const __half* vb = V + (size_t)bc * Nn;
    for (int i = tid; i < Nn; i += 256) p[i] = __half2float(vb[i]);

    float w[9];
#pragma unroll
    for (int j = 0; j < 9; ++j) w[j] = __ldg(&Wc[ch * 9 + j]);
    const float bi = bias[ch], si = s[ch], ti = t[ch];
    __syncthreads();

    for (int i = tid; i < Nn; i += 256) {
        const int y = i / Rr, x = i % Rr;
        float acc = 0.f;
#pragma unroll
        for (int dy = 0; dy < 3; ++dy) {
            const int yy = y + dy - 1;
            if (yy < 0 || yy >= Rr) continue;
#pragma unroll
            for (int dx = 0; dx < 3; ++dx) {
                const int xx = x + dx - 1;
                if (xx < 0 || xx >= Rr) continue;
                acc = fmaf(p[yy * Rr + xx], w[dy * 3 + dx], acc);
            }
        }
        Out[(size_t)bc * Nn + i] = __float2half_rn((acc + bi) * si + ti);
    }
}

// ==========================================================================
// Fused attention core (Q_t, K_t transposed [b][n][256])
// ==========================================================================
__global__ __launch_bounds__(256)
void attn_kernel(const __half* __restrict__ Qt, const __half* __restrict__ Kt,
                 const float* __restrict__ ab,
                 const float* __restrict__ th1w, const float* __restrict__ th1b,
                 const float* __restrict__ th2w, const float* __restrict__ th2b,
                 __half* __restrict__ Attn)
{
    extern __shared__ char smraw[];
    float*  S    = (float*)smraw;              // TQ*8*784 floats
    float*  ab_s = S + TQ * Hh * Nn;           // 8*784 floats
    float*  red  = ab_s + Hh * Nn;             // 128 floats
    __half* qs   = (__half*)(red + 128);       // TQ*256 halves

    const int b   = blockIdx.y;
    const int n0  = blockIdx.x * TQ;
    const int tid = threadIdx.x;
    const int g    = tid >> 5;
    const int lane = tid & 31;
    const int gr = lane >> 2, tg = lane & 3;

    for (int e = tid; e < Hh * Nn; e += 256) ab_s[e] = ab[e];
    for (int e = tid; e < TQ * NHKD; e += 256) {
        const int nq = e >> 8, c = e & 255;
        qs[nq * NHKD + c] = Qt[((size_t)b * Nn + n0 + nq) * NHKD + c];
    }
    __syncthreads();

    // ---------------- phase 1: fp16 MMA scores (warp g = head g) ----------------
    {
        const unsigned zu = 0u;
        unsigned af0[2], af2[2];
#pragma unroll
        for (int ks = 0; ks < 2; ++ks) {
            if (gr < TQ) {
                af0[ks] = *(const unsigned*)&qs[gr * NHKD + g * KDd + ks * 16 + tg * 2];
                af2[ks] = *(const unsigned*)&qs[gr * NHKD + g * KDd + ks * 16 + tg * 2 + 8];
            } else { af0[ks] = 0u; af2[ks] = 0u; }
        }

        const __half* Kb = Kt + (size_t)b * Nn * NHKD + g * KDd;
        const float* abg = ab_s + g * Nn;
        const int n = n0 + gr;
        const int yn = n / Rr, xn = n % Rr;
        float* Sg = S + g * Nn;

#pragma unroll 2
        for (int m0 = 0; m0 < Nn; m0 += 8) {
            const size_t mrow = (size_t)(m0 + gr) * NHKD;
            unsigned bf[2][2];
#pragma unroll
            for (int ks = 0; ks < 2; ++ks) {
                bf[ks][0] = *(const unsigned*)&Kb[mrow + ks * 16 + tg * 2];
                bf[ks][1] = *(const unsigned*)&Kb[mrow + ks * 16 + tg * 2 + 8];
            }
            float c[4] = {0.f, 0.f, 0.f, 0.f};
            mma_f16(c, af0[0], zu, af2[0], zu, bf[0][0], bf[0][1]);
            mma_f16(c, af0[1], zu, af2[1], zu, bf[1][0], bf[1][1]);
            if (gr < TQ) {
#pragma unroll
                for (int e = 0; e < 2; ++e) {
                    const int mm = m0 + tg * 2 + e;
                    const int ym = mm / Rr, xm = mm % Rr;
                    const int dy = yn > ym ? yn - ym : ym - yn;
                    const int dx = xn > xm ? xn - xm : xm - xn;
                    Sg[(size_t)gr * Hh * Nn + mm] = c[e] * kSCALE + abg[dy * Rr + dx];
                }
            }
        }
    }
    __syncthreads();

    // ---------------- phase 2: register-resident mix/softmax/mix ----------------
    float w1r[Hh][Hh], w2r[Hh][Hh], b1r[Hh], b2r[Hh];
#pragma unroll
    for (int gg = 0; gg < Hh; ++gg) {
        b1r[gg] = th1b[gg];
        b2r[gg] = th2b[gg];
#pragma unroll
        for (int h = 0; h < Hh; ++h) {
            w1r[gg][h] = th1w[gg * Hh + h];
            w2r[gg][h] = th2w[gg * Hh + h];
        }
    }

    for (int nq = 0; nq < TQ; ++nq) {
        const float* Sq = S + (size_t)nq * Hh * Nn;

        float mg[4][Hh];
        float gmax[Hh];
#pragma unroll
        for (int gg = 0; gg < Hh; ++gg) gmax[gg] = -1e30f;

#pragma unroll
        for (int mi = 0; mi < 4; ++mi) {
            const int m = tid + mi * 256;
            if (m < Nn) {
                float sv[Hh];
#pragma unroll
                for (int h = 0; h < Hh; ++h) sv[h] = Sq[h * Nn + m];
#pragma unroll
                for (int gg = 0; gg < Hh; ++gg) {
                    float a = b1r[gg];
#pragma unroll
                    for (int h = 0; h < Hh; ++h) a = fmaf(w1r[gg][h], sv[h], a);
                    mg[mi][gg] = a;
                    gmax[gg] = fmaxf(gmax[gg], a);
                }
            } else {
#pragma unroll
                for (int gg = 0; gg < Hh; ++gg) mg[mi][gg] = -1e30f;
            }
        }

#pragma unroll
        for (int gg = 0; gg < Hh; ++gg)
#pragma unroll
            for (int off = 16; off; off >>= 1)
                gmax[gg] = fmaxf(gmax[gg], __shfl_xor_sync(0xffffffffu, gmax[gg], off));
        if (lane == 0) {
#pragma unroll
            for (int gg = 0; gg < Hh; ++gg) red[gg * 8 + g] = gmax[gg];
        }
        __syncthreads();
        float smax[Hh];
#pragma unroll
        for (int gg = 0; gg < Hh; ++gg) {
            float v = red[gg * 8];
#pragma unroll
            for (int w = 1; w < 8; ++w) v = fmaxf(v, red[gg * 8 + w]);
            smax[gg] = v;
        }

        float gsum[Hh];
#pragma unroll
        for (int gg = 0; gg < Hh; ++gg) gsum[gg] = 0.f;
#pragma unroll
        for (int mi = 0; mi < 4; ++mi)
#pragma unroll
            for (int gg = 0; gg < Hh; ++gg) {
                const float e = __expf(mg[mi][gg] - smax[gg]);
                mg[mi][gg] = e;
                gsum[gg] += e;
            }
#pragma unroll
        for (int gg = 0; gg < Hh; ++gg)
#pragma unroll
            for (int off = 16; off; off >>= 1)
                gsum[gg] += __shfl_xor_sync(0xffffffffu, gsum[gg], off);
        if (lane == 0) {
#pragma unroll
            for (int gg = 0; gg < Hh; ++gg) red[64 + gg * 8 + g] = gsum[gg];
        }
        __syncthreads();
        float inv[Hh];
#pragma unroll
        for (int gg = 0; gg < Hh; ++gg) {
            float v = red[64 + gg * 8];
#pragma unroll
            for (int w = 1; w < 8; ++w) v += red[64 + gg * 8 + w];
            inv[gg] = 1.f / v;
        }
        __syncthreads();

        const size_t obase = (((size_t)b * Hh) * Nn + (n0 + nq)) * Nn;
#pragma unroll
        for (int mi = 0; mi < 4; ++mi) {
            const int m = tid + mi * 256;
            if (m < Nn) {
                float pv[Hh];
#pragma unroll
                for (int h = 0; h < Hh; ++h) pv[h] = mg[mi][h] * inv[h];
#pragma unroll
                for (int gg = 0; gg < Hh; ++gg) {
                    float a = b2r[gg];
#pragma unroll
                    for (int h = 0; h < Hh; ++h) a = fmaf(w2r[gg][h], pv[h], a);
                    Attn[obase + (size_t)gg * Nn * Nn + m] = __float2half_rn(a);
                }
            }
        }
    }
}

// ==========================================================================
// launch
// ==========================================================================
extern "C" void kernel_launch(void* const* d_in, const int* in_sizes, int n_in,
                              void* d_out, int out_size)
{
    const float* x    = (const float*)d_in[0];
    const float* Wq   = (const float*)d_in[1];
    const float* bq   = (const float*)d_in[2];
    const float* sq   = (const float*)d_in[3];
    const float* tq   = (const float*)d_in[4];
    const float* Wk   = (const float*)d_in[5];
    const float* bk   = (const float*)d_in[6];
    const float* sk   = (const float*)d_in[7];
    const float* tk   = (const float*)d_in[8];
    const float* Wv   = (const float*)d_in[9];
    const float* bv   = (const float*)d_in[10];
    const float* sv   = (const float*)d_in[11];
    const float* tv   = (const float*)d_in[12];
    const float* Wvl  = (const float*)d_in[13];
    const float* bvl  = (const float*)d_in[14];
    const float* svl  = (const float*)d_in[15];
    const float* tvl  = (const float*)d_in[16];
    const float* th1w = (const float*)d_in[17];
    const float* th1b = (const float*)d_in[18];
    const float* th2w = (const float*)d_in[19];
    const float* th2b = (const float*)d_in[20];
    const float* ab   = (const float*)d_in[21];
    const float* Wp   = (const float*)d_in[22];
    const float* bp   = (const float*)d_in[23];
    const float* sp   = (const float*)d_in[24];
    const float* tp   = (const float*)d_in[25];
    float* out = (float*)d_out;

    void *pxt, *pq, *pk, *pv, *pvl, *pattn, *po, *pwq, *pwk, *pwv, *pwp;
    cudaGetSymbolAddress(&pxt, g_xt);
    cudaGetSymbolAddress(&pq, g_q);
    cudaGetSymbolAddress(&pk, g_k);
    cudaGetSymbolAddress(&pv, g_vmap);
    cudaGetSymbolAddress(&pvl, g_vl);
    cudaGetSymbolAddress(&pattn, g_attn);
    cudaGetSymbolAddress(&po, g_o);
    cudaGetSymbolAddress(&pwq, g_wq);
    cudaGetSymbolAddress(&pwk, g_wk);
    cudaGetSymbolAddress(&pwv, g_wv);
    cudaGetSymbolAddress(&pwp, g_wp);
    __half* xt   = (__half*)pxt;
    __half* q    = (__half*)pq;
    __half* k    = (__half*)pk;
    __half* vmap = (__half*)pv;
    __half* vl   = (__half*)pvl;
    __half* attn = (__half*)pattn;
    __half* o    = (__half*)po;
    __half* wq   = (__half*)pwq;
    __half* wk   = (__half*)pwk;
    __half* wv   = (__half*)pwv;
    __half* wp   = (__half*)pwp;

    const dim3 blk(256);

    // weights -> fp16 (once per launch; cheap)
    w2h<<<(NHKD * DIMc / 4 + 255) / 256, blk>>>((const float4*)Wq, (__half2*)wq, NHKD * DIMc / 4);
    w2h<<<(NHKD * DIMc / 4 + 255) / 256, blk>>>((const float4*)Wk, (__half2*)wk, NHKD * DIMc / 4);
    w2h<<<(DHd  * DIMc / 4 + 255) / 256, blk>>>((const float4*)Wv, (__half2*)wv, DHd * DIMc / 4);
    w2h<<<(DIMc * DHd  / 4 + 255) / 256, blk>>>((const float4*)Wp, (__half2*)wp, DIMc * DHd / 4);

    // x -> transposed fp16 [b][n][c]
    xT_kernel<<<dim3(13, DIMc / 32, Bn), blk>>>(x, xt);

    // projections: Q,K transposed out [b][n][256]; V normal [b][dh][n]
    gemm_f16<__half, true ><<<dim3(7, NHKD / 128, Bn), blk>>>(xt, wq, bq, sq, tq, q, NHKD, DIMc);
    gemm_f16<__half, true ><<<dim3(7, NHKD / 128, Bn), blk>>>(xt, wk, bk, sk, tk, k, NHKD, DIMc);
    gemm_f16<__half, false><<<dim3(7, DHd  / 128, Bn), blk>>>(xt, wv, bv, sv, tv, vmap, DHd, DIMc);

    // depthwise conv branch
    dwconv_kernel<<<Bn * DHd, blk>>>(vmap, Wvl, bvl, svl, tvl, vl);

    // fused attention
    {
        const int smem = (TQ * Hh * Nn + Hh * Nn + 128) * (int)sizeof(float)
                       + TQ * NHKD * (int)sizeof(__half);
        cudaFuncSetAttribute(attn_kernel, cudaFuncAttributeMaxDynamicSharedMemorySize, smem);
        attn_kernel<<<dim3(Nn / TQ, Bn), blk, smem>>>(q, k, ab, th1w, th1b,
                                                      th2w, th2b, attn);
    }

    // AV + vl + relu, writes o_t [b][n][dh]
    av_mma<<<dim3(13, Bn * Hh), blk>>>(attn, vmap, vl, o);

    // final projection from o_t
    gemm_f16<float, false><<<dim3(7, DIMc / 128, Bn), blk>>>(o, wp, bp, sp, tp, out, DIMc, DHd);
}